// round 1
// baseline (speedup 1.0000x reference)
#include <cuda_runtime.h>

#define NN     20000
#define FIN    50
#define HID    128
#define HEADS  4
#define FOUT   512            // HEADS*HID
#define E0     320000
#define ET     (E0 + NN)      // edges incl. self-loops = 340000

// ---------------- scratch (device globals; no allocation allowed) ----------
__device__ float g_hA[(size_t)NN * FOUT];   // GEMM output of current layer
__device__ float g_hB[(size_t)NN * FOUT];   // aggregated layer output
__device__ float g_asrc[NN * HEADS];
__device__ float g_adst[NN * HEADS];
__device__ float g_h3[NN], g_as3[NN], g_ad3[NN];
__device__ int   g_src[ET], g_dstv[ET], g_csrc[ET];
__device__ int   g_deg[NN], g_cursor[NN], g_rowoff[NN + 1];
__device__ int   g_is64;

// ---------------- helpers --------------------------------------------------
__device__ __forceinline__ float warp_red_sum(float v) {
    #pragma unroll
    for (int o = 16; o; o >>= 1) v += __shfl_xor_sync(0xffffffffu, v, o);
    return v;
}
__device__ __forceinline__ float warp_red_max(float v) {
    #pragma unroll
    for (int o = 16; o; o >>= 1) v = fmaxf(v, __shfl_xor_sync(0xffffffffu, v, o));
    return v;
}
__device__ __forceinline__ float leaky(float x) { return x > 0.f ? x : 0.2f * x; }

// ---------------- edge dtype detection + decode ----------------------------
// int64 (values < 2^31, non-negative) => every odd 32-bit word is 0.
__global__ void detect_kernel(const unsigned* __restrict__ w) {
    if (threadIdx.x == 0) {
        int is64 = 1;
        for (int i = 1; i < 64; i += 2)
            if (w[i] != 0u) { is64 = 0; break; }
        g_is64 = is64;
    }
}

__global__ void decode_kernel(const void* __restrict__ ei) {
    int e = blockIdx.x * blockDim.x + threadIdx.x;
    if (e >= ET) return;
    int s, d;
    if (e < E0) {
        if (g_is64) {
            const long long* p = (const long long*)ei;
            s = (int)p[e]; d = (int)p[E0 + e];
        } else {
            const int* p = (const int*)ei;
            s = p[e]; d = p[E0 + e];
        }
    } else {
        s = d = e - E0;   // self-loop
    }
    g_src[e] = s; g_dstv[e] = d;
}

// ---------------- CSR build (by dst) ---------------------------------------
__global__ void zero_deg_kernel() {
    int i = blockIdx.x * blockDim.x + threadIdx.x;
    if (i < NN) g_deg[i] = 0;
}

__global__ void count_kernel() {
    int e = blockIdx.x * blockDim.x + threadIdx.x;
    if (e < ET) atomicAdd(&g_deg[g_dstv[e]], 1);
}

__global__ __launch_bounds__(1024) void scan_kernel() {
    __shared__ int sm[1024];
    __shared__ int carry;
    int t = threadIdx.x;
    if (t == 0) { carry = 0; g_rowoff[0] = 0; }
    __syncthreads();
    for (int base = 0; base < NN; base += 1024) {
        int i = base + t;
        int v = (i < NN) ? g_deg[i] : 0;
        sm[t] = v;
        __syncthreads();
        // inclusive Hillis-Steele scan
        for (int s = 1; s < 1024; s <<= 1) {
            int add = (t >= s) ? sm[t - s] : 0;
            __syncthreads();
            sm[t] += add;
            __syncthreads();
        }
        if (i < NN) {
            int inc = sm[t] + carry;
            g_rowoff[i + 1] = inc;
            g_cursor[i]     = inc - v;   // exclusive start
        }
        __syncthreads();
        if (t == 0) carry += sm[1023];
        __syncthreads();
    }
}

__global__ void scatter_kernel() {
    int e = blockIdx.x * blockDim.x + threadIdx.x;
    if (e >= ET) return;
    int d = g_dstv[e];
    int pos = atomicAdd(&g_cursor[d], 1);
    g_csrc[pos] = g_src[e];
}

// ---------------- SGEMM: C[M,512] = A[M,K] @ B[K,512] ----------------------
// 128x128 tile, BK=8, 256 threads, 8x8 per-thread microtile.
// useInternalA != 0 -> A = g_hB (layer-2 input); output always g_hA.
__global__ __launch_bounds__(256) void sgemm_kernel(
    const float* __restrict__ Aext, const float* __restrict__ B,
    int M, int K, int useInternalA)
{
    const float* __restrict__ A = useInternalA ? (const float*)g_hB : Aext;
    float* __restrict__ C = g_hA;

    __shared__ float As[8][128];
    __shared__ float Bs[8][128];
    int tid = threadIdx.x;
    int rowBase = blockIdx.y * 128;
    int colBase = blockIdx.x * 128;
    int tr = tid >> 4, tc = tid & 15;

    float acc[8][8];
    #pragma unroll
    for (int i = 0; i < 8; i++)
        #pragma unroll
        for (int j = 0; j < 8; j++) acc[i][j] = 0.f;

    for (int k0 = 0; k0 < K; k0 += 8) {
        #pragma unroll
        for (int i = 0; i < 4; i++) {
            int idx = tid * 4 + i;
            int r = idx >> 3, kk = idx & 7;
            int gr = rowBase + r, gk = k0 + kk;
            As[kk][r] = (gr < M && gk < K) ? A[(size_t)gr * K + gk] : 0.f;
        }
        #pragma unroll
        for (int i = 0; i < 4; i++) {
            int idx = tid + i * 256;
            int kk = idx >> 7, c = idx & 127;
            int gk = k0 + kk;
            Bs[kk][c] = (gk < K) ? B[(size_t)gk * 512 + colBase + c] : 0.f;
        }
        __syncthreads();
        #pragma unroll
        for (int kk = 0; kk < 8; kk++) {
            float a[8], b[8];
            const float4* A4 = (const float4*)&As[kk][0];
            const float4* B4 = (const float4*)&Bs[kk][0];
            float4 a0 = A4[tr * 2], a1 = A4[tr * 2 + 1];
            float4 b0 = B4[tc * 2], b1 = B4[tc * 2 + 1];
            a[0]=a0.x; a[1]=a0.y; a[2]=a0.z; a[3]=a0.w;
            a[4]=a1.x; a[5]=a1.y; a[6]=a1.z; a[7]=a1.w;
            b[0]=b0.x; b[1]=b0.y; b[2]=b0.z; b[3]=b0.w;
            b[4]=b1.x; b[5]=b1.y; b[6]=b1.z; b[7]=b1.w;
            #pragma unroll
            for (int i = 0; i < 8; i++)
                #pragma unroll
                for (int j = 0; j < 8; j++)
                    acc[i][j] = fmaf(a[i], b[j], acc[i][j]);
        }
        __syncthreads();
    }
    #pragma unroll
    for (int i = 0; i < 8; i++) {
        int gr = rowBase + tr * 8 + i;
        if (gr < M) {
            #pragma unroll
            for (int j = 0; j < 8; j++)
                C[(size_t)gr * 512 + colBase + tc * 8 + j] = acc[i][j];
        }
    }
}

// ---------------- per-node attention dots ----------------------------------
// a_src[n][h] = <h[n,h,:], att_src[h,:]> ; same for dst. One node per block.
__global__ __launch_bounds__(128) void dots_kernel(
    const float* __restrict__ atts, const float* __restrict__ attd)
{
    int n = blockIdx.x;
    int w = threadIdx.x >> 5, lane = threadIdx.x & 31;
    const float* hr = g_hA + (size_t)n * 512 + w * 128;
    float s1 = 0.f, s2 = 0.f;
    #pragma unroll
    for (int i = 0; i < 4; i++) {
        float v = hr[lane + 32 * i];
        s1 += v * atts[w * 128 + lane + 32 * i];
        s2 += v * attd[w * 128 + lane + 32 * i];
    }
    s1 = warp_red_sum(s1);
    s2 = warp_red_sum(s2);
    if (!lane) { g_asrc[n * 4 + w] = s1; g_adst[n * 4 + w] = s2; }
}

// ---------------- per-node softmax + aggregate (layers 1,2) ----------------
// Block of 512 threads per dst node: phase1 per-head max, then fused
// exp/sum + weighted accumulate over in-edges (CSR). Reads g_hA, writes g_hB.
__global__ __launch_bounds__(512) void agg_kernel(const float* __restrict__ bias)
{
    __shared__ float red[512];
    __shared__ float wch[512];     // 128 edges x 4 heads (exp weights)
    __shared__ int   sc[128];      // src ids of current chunk
    __shared__ float m4[4], inv4[4];

    int n = blockIdx.x, t = threadIdx.x;
    int start = g_rowoff[n];
    int deg   = g_rowoff[n + 1] - start;
    int head = t & 3, el = t >> 2;
    float ad = g_adst[n * 4 + head];

    // phase 1: per-head max of leaky-relu logits
    float lmax = -1e30f;
    for (int c = 0; c < deg; c += 128) {
        int e = c + el;
        if (e < deg) {
            int s = g_csrc[start + e];
            lmax = fmaxf(lmax, leaky(g_asrc[s * 4 + head] + ad));
        }
    }
    red[t] = lmax;
    __syncthreads();
    for (int s = 256; s >= 4; s >>= 1) {
        if (t < s) red[t] = fmaxf(red[t], red[t + s]);
        __syncthreads();
    }
    if (t < 4) m4[t] = red[t];
    __syncthreads();
    float m = m4[head];

    // phase 2: exp weights + sum, fused with weighted feature accumulation
    int j = t, hh = j >> 7;            // output channel, its head
    float lsum = 0.f, acc = 0.f;
    for (int c = 0; c < deg; c += 128) {
        int e = c + el;
        if (e < deg) {
            int s = g_csrc[start + e];
            if (head == 0) sc[el] = s;
            float w = __expf(leaky(g_asrc[s * 4 + head] + ad) - m);
            wch[el * 4 + head] = w;
            lsum += w;
        }
        __syncthreads();
        int cend = min(128, deg - c);
        const float* __restrict__ hp = g_hA + j;
        for (int e2 = 0; e2 < cend; e2++)
            acc = fmaf(wch[e2 * 4 + hh], hp[(size_t)sc[e2] * 512], acc);
        __syncthreads();
    }
    red[t] = lsum;
    __syncthreads();
    for (int s = 256; s >= 4; s >>= 1) {
        if (t < s) red[t] += red[t + s];
        __syncthreads();
    }
    if (t < 4) inv4[t] = 1.f / (red[t] + 1e-16f);
    __syncthreads();

    float o = acc * inv4[hh] + bias[j];
    o = o > 0.f ? o : (__expf(o) - 1.f);          // ELU
    g_hB[(size_t)n * 512 + j] = o;
}

// ---------------- layer 3: GEMV + scalar attention -------------------------
__global__ __launch_bounds__(256) void gemv3_kernel(
    const float* __restrict__ W3, const float* __restrict__ as3p,
    const float* __restrict__ ad3p)
{
    int n = blockIdx.x * 8 + (threadIdx.x >> 5);
    if (n >= NN) return;
    int lane = threadIdx.x & 31;
    const float* hr = g_hB + (size_t)n * 512;
    float s = 0.f;
    #pragma unroll
    for (int i = 0; i < 16; i++) s = fmaf(hr[lane + 32 * i], W3[lane + 32 * i], s);
    s = warp_red_sum(s);
    if (!lane) { g_h3[n] = s; g_as3[n] = s * as3p[0]; g_ad3[n] = s * ad3p[0]; }
}

__global__ __launch_bounds__(256) void agg3_kernel(
    const float* __restrict__ b3, float* __restrict__ out)
{
    int n = blockIdx.x * 8 + (threadIdx.x >> 5);
    if (n >= NN) return;
    int lane = threadIdx.x & 31;
    int start = g_rowoff[n], deg = g_rowoff[n + 1] - start;
    float ad = g_ad3[n];
    float m = -1e30f;
    for (int e = lane; e < deg; e += 32) {
        int s = g_csrc[start + e];
        m = fmaxf(m, leaky(g_as3[s] + ad));
    }
    m = warp_red_max(m);
    float sum = 0.f, acc = 0.f;
    for (int e = lane; e < deg; e += 32) {
        int s = g_csrc[start + e];
        float w = __expf(leaky(g_as3[s] + ad) - m);
        sum += w;
        acc = fmaf(w, g_h3[s], acc);
    }
    sum = warp_red_sum(sum);
    acc = warp_red_sum(acc);
    if (!lane) out[n] = acc / (sum + 1e-16f) + b3[0];
}

// ---------------- launch ----------------------------------------------------
extern "C" void kernel_launch(void* const* d_in, const int* in_sizes, int n_in,
                              void* d_out, int out_size)
{
    const float* x   = (const float*)d_in[0];
    const void*  ei  = d_in[1];
    const float* W1  = (const float*)d_in[2];
    const float* as1 = (const float*)d_in[3];
    const float* ad1 = (const float*)d_in[4];
    const float* b1  = (const float*)d_in[5];
    const float* W2  = (const float*)d_in[6];
    const float* as2 = (const float*)d_in[7];
    const float* ad2 = (const float*)d_in[8];
    const float* b2  = (const float*)d_in[9];
    const float* W3  = (const float*)d_in[10];
    const float* as3 = (const float*)d_in[11];
    const float* ad3 = (const float*)d_in[12];
    const float* b3  = (const float*)d_in[13];
    float* out = (float*)d_out;

    // CSR build (per-launch, capture-safe)
    detect_kernel<<<1, 32>>>((const unsigned*)ei);
    decode_kernel<<<(ET + 255) / 256, 256>>>(ei);
    zero_deg_kernel<<<(NN + 255) / 256, 256>>>();
    count_kernel<<<(ET + 255) / 256, 256>>>();
    scan_kernel<<<1, 1024>>>();
    scatter_kernel<<<(ET + 255) / 256, 256>>>();

    dim3 gg(4, (NN + 127) / 128);

    // layer 1
    sgemm_kernel<<<gg, 256>>>(x, W1, NN, FIN, 0);
    dots_kernel<<<NN, 128>>>(as1, ad1);
    agg_kernel<<<NN, 512>>>(b1);
    // layer 2
    sgemm_kernel<<<gg, 256>>>(nullptr, W2, NN, FOUT, 1);
    dots_kernel<<<NN, 128>>>(as2, ad2);
    agg_kernel<<<NN, 512>>>(b2);
    // layer 3
    gemv3_kernel<<<(NN + 7) / 8, 256>>>(W3, as3, ad3);
    agg3_kernel<<<(NN + 7) / 8, 256>>>(b3, out);
}

// round 3
// speedup vs baseline: 1.5352x; 1.5352x over previous
#include <cuda_runtime.h>
#include <cuda_bf16.h>
#include <cstdint>

#define NN     20000
#define FIN    50
#define HID    128
#define HEADS  4
#define FOUT   512            // HEADS*HID
#define E0     320000
#define ET     (E0 + NN)      // edges incl. self-loops = 340000

// ---------------- scratch (device globals; no allocation allowed) ----------
__device__ float g_hA[(size_t)NN * FOUT];   // GEMM output of current layer
__device__ float g_hB[(size_t)NN * FOUT];   // aggregated layer output
__device__ __nv_bfloat16 g_W2Th[(size_t)FOUT * FOUT]; // W2^T hi (bf16), [n][k]
__device__ __nv_bfloat16 g_W2Tl[(size_t)FOUT * FOUT]; // W2^T lo (bf16)
__device__ float g_asrc[NN * HEADS];
__device__ float g_adst[NN * HEADS];
__device__ float g_h3[NN], g_as3[NN], g_ad3[NN];
__device__ int   g_src[ET], g_dstv[ET], g_csrc[ET];
__device__ int   g_deg[NN], g_cursor[NN], g_rowoff[NN + 1];
__device__ int   g_is64;

// ---------------- helpers --------------------------------------------------
__device__ __forceinline__ float warp_red_sum(float v) {
    #pragma unroll
    for (int o = 16; o; o >>= 1) v += __shfl_xor_sync(0xffffffffu, v, o);
    return v;
}
__device__ __forceinline__ float warp_red_max(float v) {
    #pragma unroll
    for (int o = 16; o; o >>= 1) v = fmaxf(v, __shfl_xor_sync(0xffffffffu, v, o));
    return v;
}
__device__ __forceinline__ float leaky(float x) { return x > 0.f ? x : 0.2f * x; }

__device__ __forceinline__ uint32_t smem_u32(const void* p) {
    uint32_t a;
    asm("{ .reg .u64 t; cvta.to.shared.u64 t, %1; cvt.u32.u64 %0, t; }" : "=r"(a) : "l"(p));
    return a;
}

// pack two floats' bf16-hi parts into one uint, return residuals
__device__ __forceinline__ unsigned pk_hi(float a, float b, float& ra, float& rb) {
    __nv_bfloat16 ha = __float2bfloat16(a), hb = __float2bfloat16(b);
    ra = a - __bfloat162float(ha);
    rb = b - __bfloat162float(hb);
    return ((unsigned)__bfloat16_as_ushort(hb) << 16) | (unsigned)__bfloat16_as_ushort(ha);
}
__device__ __forceinline__ unsigned pk(float a, float b) {
    __nv_bfloat16 ha = __float2bfloat16(a), hb = __float2bfloat16(b);
    return ((unsigned)__bfloat16_as_ushort(hb) << 16) | (unsigned)__bfloat16_as_ushort(ha);
}

__device__ __forceinline__ void ldm_x4(unsigned r[4], uint32_t addr) {
    asm volatile("ldmatrix.sync.aligned.m8n8.x4.shared.b16 {%0,%1,%2,%3}, [%4];"
                 : "=r"(r[0]), "=r"(r[1]), "=r"(r[2]), "=r"(r[3]) : "r"(addr));
}
__device__ __forceinline__ void mma_bf16(float c[4], const unsigned a[4],
                                         unsigned b0, unsigned b1) {
    asm volatile(
        "mma.sync.aligned.m16n8k16.row.col.f32.bf16.bf16.f32 "
        "{%0,%1,%2,%3}, {%4,%5,%6,%7}, {%8,%9}, {%0,%1,%2,%3};"
        : "+f"(c[0]), "+f"(c[1]), "+f"(c[2]), "+f"(c[3])
        : "r"(a[0]), "r"(a[1]), "r"(a[2]), "r"(a[3]), "r"(b0), "r"(b1));
}

// ---------------- edge dtype detection + decode ----------------------------
__global__ void detect_kernel(const unsigned* __restrict__ w) {
    if (threadIdx.x == 0) {
        int is64 = 1;
        for (int i = 1; i < 64; i += 2)
            if (w[i] != 0u) { is64 = 0; break; }
        g_is64 = is64;
    }
}

__global__ void decode_kernel(const void* __restrict__ ei) {
    int e = blockIdx.x * blockDim.x + threadIdx.x;
    if (e >= ET) return;
    int s, d;
    if (e < E0) {
        if (g_is64) {
            const long long* p = (const long long*)ei;
            s = (int)p[e]; d = (int)p[E0 + e];
        } else {
            const int* p = (const int*)ei;
            s = p[e]; d = p[E0 + e];
        }
    } else {
        s = d = e - E0;
    }
    g_src[e] = s; g_dstv[e] = d;
}

__global__ void zero_deg_kernel() {
    int i = blockIdx.x * blockDim.x + threadIdx.x;
    if (i < NN) g_deg[i] = 0;
}

__global__ void count_kernel() {
    int e = blockIdx.x * blockDim.x + threadIdx.x;
    if (e < ET) atomicAdd(&g_deg[g_dstv[e]], 1);
}

// single-pass scan: 1024 threads x 20 nodes each
__global__ __launch_bounds__(1024) void scan_kernel() {
    __shared__ int wsum[32];
    int t = threadIdx.x, lane = t & 31, w = t >> 5;
    int base = t * 20;
    int loc[20];
    int s = 0;
    #pragma unroll
    for (int i = 0; i < 20; i++) {
        int idx = base + i;
        int v = (idx < NN) ? g_deg[idx] : 0;
        s += v; loc[i] = s;
    }
    int x = s;
    #pragma unroll
    for (int o = 1; o < 32; o <<= 1) {
        int y = __shfl_up_sync(0xffffffffu, x, o);
        if (lane >= o) x += y;
    }
    if (lane == 31) wsum[w] = x;
    __syncthreads();
    if (w == 0) {
        int y = wsum[lane];
        #pragma unroll
        for (int o = 1; o < 32; o <<= 1) {
            int z = __shfl_up_sync(0xffffffffu, y, o);
            if (lane >= o) y += z;
        }
        wsum[lane] = y;
    }
    __syncthreads();
    int texcl = (w > 0 ? wsum[w - 1] : 0) + x - s;
    if (t == 0) g_rowoff[0] = 0;
    #pragma unroll
    for (int i = 0; i < 20; i++) {
        int idx = base + i;
        if (idx < NN) {
            g_rowoff[idx + 1] = texcl + loc[i];
            g_cursor[idx]     = texcl + (i ? loc[i - 1] : 0);
        }
    }
}

__global__ void scatter_kernel() {
    int e = blockIdx.x * blockDim.x + threadIdx.x;
    if (e >= ET) return;
    int d = g_dstv[e];
    int pos = atomicAdd(&g_cursor[d], 1);
    g_csrc[pos] = g_src[e];
}

// ---------------- W2 transpose + bf16 hi/lo split --------------------------
__global__ __launch_bounds__(256) void transpose_kernel(const float* __restrict__ W) {
    __shared__ float tile[32][33];
    int bx = blockIdx.x * 32, by = blockIdx.y * 32;
    int tx = threadIdx.x, ty = threadIdx.y;
    #pragma unroll
    for (int i = 0; i < 32; i += 8)
        tile[ty + i][tx] = W[(size_t)(bx + ty + i) * 512 + by + tx];
    __syncthreads();
    #pragma unroll
    for (int i = 0; i < 32; i += 8) {
        float v = tile[tx][ty + i];
        __nv_bfloat16 h = __float2bfloat16(v);
        __nv_bfloat16 l = __float2bfloat16(v - __bfloat162float(h));
        size_t o = (size_t)(by + ty + i) * 512 + bx + tx;
        g_W2Th[o] = h;
        g_W2Tl[o] = l;
    }
}

// ---------------- SGEMM layer 1 (fp32 SIMT, K=50) ---------------------------
__global__ __launch_bounds__(256) void sgemm_kernel(
    const float* __restrict__ A, const float* __restrict__ B, int M, int K)
{
    float* __restrict__ C = g_hA;
    __shared__ float As[8][128];
    __shared__ float Bs[8][128];
    int tid = threadIdx.x;
    int rowBase = blockIdx.y * 128;
    int colBase = blockIdx.x * 128;
    int tr = tid >> 4, tc = tid & 15;

    float acc[8][8];
    #pragma unroll
    for (int i = 0; i < 8; i++)
        #pragma unroll
        for (int j = 0; j < 8; j++) acc[i][j] = 0.f;

    for (int k0 = 0; k0 < K; k0 += 8) {
        #pragma unroll
        for (int i = 0; i < 4; i++) {
            int idx = tid * 4 + i;
            int r = idx >> 3, kk = idx & 7;
            int gr = rowBase + r, gk = k0 + kk;
            As[kk][r] = (gr < M && gk < K) ? A[(size_t)gr * K + gk] : 0.f;
        }
        #pragma unroll
        for (int i = 0; i < 4; i++) {
            int idx = tid + i * 256;
            int kk = idx >> 7, c = idx & 127;
            int gk = k0 + kk;
            Bs[kk][c] = (gk < K) ? B[(size_t)gk * 512 + colBase + c] : 0.f;
        }
        __syncthreads();
        #pragma unroll
        for (int kk = 0; kk < 8; kk++) {
            float a[8], b[8];
            const float4* A4 = (const float4*)&As[kk][0];
            const float4* B4 = (const float4*)&Bs[kk][0];
            float4 a0 = A4[tr * 2], a1 = A4[tr * 2 + 1];
            float4 b0 = B4[tc * 2], b1 = B4[tc * 2 + 1];
            a[0]=a0.x; a[1]=a0.y; a[2]=a0.z; a[3]=a0.w;
            a[4]=a1.x; a[5]=a1.y; a[6]=a1.z; a[7]=a1.w;
            b[0]=b0.x; b[1]=b0.y; b[2]=b0.z; b[3]=b0.w;
            b[4]=b1.x; b[5]=b1.y; b[6]=b1.z; b[7]=b1.w;
            #pragma unroll
            for (int i = 0; i < 8; i++)
                #pragma unroll
                for (int j = 0; j < 8; j++)
                    acc[i][j] = fmaf(a[i], b[j], acc[i][j]);
        }
        __syncthreads();
    }
    #pragma unroll
    for (int i = 0; i < 8; i++) {
        int gr = rowBase + tr * 8 + i;
        if (gr < M) {
            #pragma unroll
            for (int j = 0; j < 8; j++)
                C[(size_t)gr * 512 + colBase + tc * 8 + j] = acc[i][j];
        }
    }
}

// ---------------- GEMM layer 2: mma.sync bf16 3-pass ------------------------
// C[128x128] per CTA. A = g_hB fp32 (split on the fly), B = g_W2Th/l.
// 8 warps: warp_m = (wid&3)*32, warp_n = (wid>>2)*64. Warp tile 32x64.
#define LDS_STRIDE 40   // bf16 elems per smem row (80 B, conflict-free ldmatrix)

__global__ __launch_bounds__(256) void mma_gemm2_kernel()
{
    __shared__ __nv_bfloat16 sAh[128][LDS_STRIDE];
    __shared__ __nv_bfloat16 sAl[128][LDS_STRIDE];
    __shared__ __nv_bfloat16 sBh[128][LDS_STRIDE];
    __shared__ __nv_bfloat16 sBl[128][LDS_STRIDE];

    int tid = threadIdx.x;
    int wid = tid >> 5, lane = tid & 31;
    int wm = (wid & 3) * 32;
    int wn = (wid >> 2) * 64;
    int rowBase = blockIdx.y * 128;
    int colBase = blockIdx.x * 128;

    const float4* __restrict__ A4 = (const float4*)g_hB;

    float c[2][8][4];
    #pragma unroll
    for (int t = 0; t < 2; t++)
        #pragma unroll
        for (int j = 0; j < 8; j++)
            #pragma unroll
            for (int q = 0; q < 4; q++) c[t][j][q] = 0.f;

    uint32_t aBaseH = smem_u32(&sAh[0][0]);
    uint32_t aBaseL = smem_u32(&sAl[0][0]);
    uint32_t bBaseH = smem_u32(&sBh[0][0]);
    uint32_t bBaseL = smem_u32(&sBl[0][0]);
    int lr = lane & 15, lc = (lane >> 4) * 16;   // ldmatrix per-lane row/col-bytes

    for (int it = 0; it < 16; it++) {
        // ---- load + split A chunk: 128 rows x 32 k ----
        #pragma unroll
        for (int i = 0; i < 4; i++) {
            int idx = tid + i * 256;
            int r = idx >> 3, q = idx & 7;
            int grow = rowBase + r;
            float4 v = make_float4(0.f, 0.f, 0.f, 0.f);
            if (grow < NN) v = A4[(size_t)grow * 128 + it * 8 + q];
            float rx, ry, rz, rw;
            unsigned h0 = pk_hi(v.x, v.y, rx, ry);
            unsigned h1 = pk_hi(v.z, v.w, rz, rw);
            unsigned l0 = pk(rx, ry);
            unsigned l1 = pk(rz, rw);
            *(uint2*)&sAh[r][q * 4] = make_uint2(h0, h1);
            *(uint2*)&sAl[r][q * 4] = make_uint2(l0, l1);
        }
        // ---- load B chunk: 128 rows x 32 k (bf16 pre-split) ----
        #pragma unroll
        for (int i = 0; i < 8; i++) {
            int idx = tid + i * 256;
            int r = idx >> 4, q = idx & 15;
            size_t go = (size_t)(colBase + r) * 512 + it * 32 + q * 2;
            *(unsigned*)&sBh[r][q * 2] = *(const unsigned*)&g_W2Th[go];
            *(unsigned*)&sBl[r][q * 2] = *(const unsigned*)&g_W2Tl[go];
        }
        __syncthreads();

        #pragma unroll
        for (int s = 0; s < 2; s++) {
            unsigned ah[2][4], al[2][4], bh[4][4], bl[4][4];
            #pragma unroll
            for (int t = 0; t < 2; t++) {
                uint32_t off = (uint32_t)(wm + t * 16 + lr) * (LDS_STRIDE * 2) + s * 32 + lc;
                ldm_x4(ah[t], aBaseH + off);
                ldm_x4(al[t], aBaseL + off);
            }
            #pragma unroll
            for (int p = 0; p < 4; p++) {
                uint32_t off = (uint32_t)(wn + p * 16 + lr) * (LDS_STRIDE * 2) + s * 32 + lc;
                ldm_x4(bh[p], bBaseH + off);
                ldm_x4(bl[p], bBaseL + off);
            }
            #pragma unroll
            for (int t = 0; t < 2; t++) {
                #pragma unroll
                for (int j = 0; j < 8; j++) {
                    int p = j >> 1;
                    unsigned bh0 = (j & 1) ? bh[p][1] : bh[p][0];
                    unsigned bh1 = (j & 1) ? bh[p][3] : bh[p][2];
                    unsigned bl0 = (j & 1) ? bl[p][1] : bl[p][0];
                    unsigned bl1 = (j & 1) ? bl[p][3] : bl[p][2];
                    mma_bf16(c[t][j], ah[t], bh0, bh1);
                    mma_bf16(c[t][j], ah[t], bl0, bl1);
                    mma_bf16(c[t][j], al[t], bh0, bh1);
                }
            }
        }
        __syncthreads();
    }

    // ---- epilogue ----
    #pragma unroll
    for (int t = 0; t < 2; t++) {
        int r0 = rowBase + wm + t * 16 + (lane >> 2);
        #pragma unroll
        for (int j = 0; j < 8; j++) {
            int col = colBase + wn + j * 8 + (lane & 3) * 2;
            if (r0 < NN)
                *(float2*)&g_hA[(size_t)r0 * 512 + col] = make_float2(c[t][j][0], c[t][j][1]);
            if (r0 + 8 < NN)
                *(float2*)&g_hA[(size_t)(r0 + 8) * 512 + col] = make_float2(c[t][j][2], c[t][j][3]);
        }
    }
}

// ---------------- per-node attention dots ----------------------------------
__global__ __launch_bounds__(128) void dots_kernel(
    const float* __restrict__ atts, const float* __restrict__ attd)
{
    int n = blockIdx.x;
    int w = threadIdx.x >> 5, lane = threadIdx.x & 31;
    const float* hr = g_hA + (size_t)n * 512 + w * 128;
    float s1 = 0.f, s2 = 0.f;
    #pragma unroll
    for (int i = 0; i < 4; i++) {
        float v = hr[lane + 32 * i];
        s1 += v * atts[w * 128 + lane + 32 * i];
        s2 += v * attd[w * 128 + lane + 32 * i];
    }
    s1 = warp_red_sum(s1);
    s2 = warp_red_sum(s2);
    if (!lane) { g_asrc[n * 4 + w] = s1; g_adst[n * 4 + w] = s2; }
}

// ---------------- per-node softmax + aggregate (layers 1,2) ----------------
__global__ __launch_bounds__(512) void agg_kernel(const float* __restrict__ bias)
{
    __shared__ float red[512];
    __shared__ float wch[512];     // 128 edges x 4 heads
    __shared__ int   sc[128];
    __shared__ float m4[4], inv4[4];
    __shared__ float4 sacc[512];

    int n = blockIdx.x, t = threadIdx.x;
    int start = g_rowoff[n];
    int deg   = g_rowoff[n + 1] - start;
    int head = t & 3, el = t >> 2;
    int eg = t >> 7, cq = t & 127, hh = cq >> 5;
    float ad = g_adst[n * 4 + head];

    // phase 1: per-head max of leaky logits
    float lmax = -1e30f;
    for (int c = 0; c < deg; c += 128) {
        int e = c + el;
        if (e < deg) {
            int s = g_csrc[start + e];
            lmax = fmaxf(lmax, leaky(g_asrc[s * 4 + head] + ad));
        }
    }
    red[t] = lmax;
    __syncthreads();
    for (int s = 256; s >= 4; s >>= 1) {
        if (t < s) red[t] = fmaxf(red[t], red[t + s]);
        __syncthreads();
    }
    if (t < 4) m4[t] = red[t];
    __syncthreads();
    float m = m4[head];

    // phase 2: weights + vectorized accumulate
    float lsum = 0.f;
    float4 acc = make_float4(0.f, 0.f, 0.f, 0.f);
    const float4* __restrict__ hA4 = (const float4*)g_hA;
    for (int c = 0; c < deg; c += 128) {
        int e = c + el;
        if (e < deg) {
            int s = g_csrc[start + e];
            if (head == 0) sc[el] = s;
            float w = __expf(leaky(g_asrc[s * 4 + head] + ad) - m);
            wch[el * 4 + head] = w;
            lsum += w;
        }
        __syncthreads();
        int cend = min(128, deg - c);
        for (int e2 = eg; e2 < cend; e2 += 4) {
            float w = wch[e2 * 4 + hh];
            float4 v = hA4[(size_t)sc[e2] * 128 + cq];
            acc.x = fmaf(w, v.x, acc.x);
            acc.y = fmaf(w, v.y, acc.y);
            acc.z = fmaf(w, v.z, acc.z);
            acc.w = fmaf(w, v.w, acc.w);
        }
        __syncthreads();
    }
    red[t] = lsum;
    __syncthreads();
    for (int s = 256; s >= 4; s >>= 1) {
        if (t < s) red[t] += red[t + s];
        __syncthreads();
    }
    if (t < 4) inv4[t] = 1.f / (red[t] + 1e-16f);
    sacc[t] = acc;
    __syncthreads();

    if (eg == 0) {
        float4 a0 = sacc[t], a1 = sacc[t + 128], a2 = sacc[t + 256], a3 = sacc[t + 384];
        float inv = inv4[hh];
        float4 b4 = ((const float4*)bias)[t];
        float4 o;
        o.x = (a0.x + a1.x + a2.x + a3.x) * inv + b4.x;
        o.y = (a0.y + a1.y + a2.y + a3.y) * inv + b4.y;
        o.z = (a0.z + a1.z + a2.z + a3.z) * inv + b4.z;
        o.w = (a0.w + a1.w + a2.w + a3.w) * inv + b4.w;
        o.x = o.x > 0.f ? o.x : (__expf(o.x) - 1.f);
        o.y = o.y > 0.f ? o.y : (__expf(o.y) - 1.f);
        o.z = o.z > 0.f ? o.z : (__expf(o.z) - 1.f);
        o.w = o.w > 0.f ? o.w : (__expf(o.w) - 1.f);
        *(float4*)&g_hB[(size_t)n * 512 + t * 4] = o;
    }
}

// ---------------- layer 3: GEMV + scalar attention -------------------------
__global__ __launch_bounds__(256) void gemv3_kernel(
    const float* __restrict__ W3, const float* __restrict__ as3p,
    const float* __restrict__ ad3p)
{
    int n = blockIdx.x * 8 + (threadIdx.x >> 5);
    if (n >= NN) return;
    int lane = threadIdx.x & 31;
    const float* hr = g_hB + (size_t)n * 512;
    float s = 0.f;
    #pragma unroll
    for (int i = 0; i < 16; i++) s = fmaf(hr[lane + 32 * i], W3[lane + 32 * i], s);
    s = warp_red_sum(s);
    if (!lane) { g_h3[n] = s; g_as3[n] = s * as3p[0]; g_ad3[n] = s * ad3p[0]; }
}

__global__ __launch_bounds__(256) void agg3_kernel(
    const float* __restrict__ b3, float* __restrict__ out)
{
    int n = blockIdx.x * 8 + (threadIdx.x >> 5);
    if (n >= NN) return;
    int lane = threadIdx.x & 31;
    int start = g_rowoff[n], deg = g_rowoff[n + 1] - start;
    float ad = g_ad3[n];
    float m = -1e30f;
    for (int e = lane; e < deg; e += 32) {
        int s = g_csrc[start + e];
        m = fmaxf(m, leaky(g_as3[s] + ad));
    }
    m = warp_red_max(m);
    float sum = 0.f, acc = 0.f;
    for (int e = lane; e < deg; e += 32) {
        int s = g_csrc[start + e];
        float w = __expf(leaky(g_as3[s] + ad) - m);
        sum += w;
        acc = fmaf(w, g_h3[s], acc);
    }
    sum = warp_red_sum(sum);
    acc = warp_red_sum(acc);
    if (!lane) out[n] = acc / (sum + 1e-16f) + b3[0];
}

// ---------------- launch ----------------------------------------------------
extern "C" void kernel_launch(void* const* d_in, const int* in_sizes, int n_in,
                              void* d_out, int out_size)
{
    const float* x   = (const float*)d_in[0];
    const void*  ei  = d_in[1];
    const float* W1  = (const float*)d_in[2];
    const float* as1 = (const float*)d_in[3];
    const float* ad1 = (const float*)d_in[4];
    const float* b1  = (const float*)d_in[5];
    const float* W2  = (const float*)d_in[6];
    const float* as2 = (const float*)d_in[7];
    const float* ad2 = (const float*)d_in[8];
    const float* b2  = (const float*)d_in[9];
    const float* W3  = (const float*)d_in[10];
    const float* as3 = (const float*)d_in[11];
    const float* ad3 = (const float*)d_in[12];
    const float* b3  = (const float*)d_in[13];
    float* out = (float*)d_out;

    // CSR build + weight transpose/split
    detect_kernel<<<1, 32>>>((const unsigned*)ei);
    decode_kernel<<<(ET + 255) / 256, 256>>>(ei);
    zero_deg_kernel<<<(NN + 255) / 256, 256>>>();
    count_kernel<<<(ET + 255) / 256, 256>>>();
    scan_kernel<<<1, 1024>>>();
    scatter_kernel<<<(ET + 255) / 256, 256>>>();
    transpose_kernel<<<dim3(16, 16), dim3(32, 8)>>>(W2);

    // layer 1 (fp32 SIMT GEMM: K=50)
    sgemm_kernel<<<dim3(4, (NN + 127) / 128), 256>>>(x, W1, NN, FIN);
    dots_kernel<<<NN, 128>>>(as1, ad1);
    agg_kernel<<<NN, 512>>>(b1);

    // layer 2 (bf16 3-pass tensor-core GEMM)
    mma_gemm2_kernel<<<dim3(4, (NN + 127) / 128), 256>>>();
    dots_kernel<<<NN, 128>>>(as2, ad2);
    agg_kernel<<<NN, 512>>>(b2);

    // layer 3
    gemv3_kernel<<<(NN + 7) / 8, 256>>>(W3, as3, ad3);
    agg3_kernel<<<(NN + 7) / 8, 256>>>(b3, out);
}

// round 4
// speedup vs baseline: 1.6064x; 1.0464x over previous
#include <cuda_runtime.h>
#include <cuda_bf16.h>
#include <cstdint>

#define NN     20000
#define FIN    50
#define HID    128
#define HEADS  4
#define FOUT   512            // HEADS*HID
#define E0     320000
#define ET     (E0 + NN)      // edges incl. self-loops = 340000
#define K1     64             // layer-1 K padded 50 -> 64

// ---------------- scratch (device globals; no allocation allowed) ----------
__device__ float g_hA[(size_t)NN * FOUT];            // GEMM output (fp32)
__device__ __nv_bfloat16 g_hBh[(size_t)NN * FOUT];   // agg1 output hi
__device__ __nv_bfloat16 g_hBl[(size_t)NN * FOUT];   // agg1 output lo
__device__ __nv_bfloat16 g_xh[(size_t)NN * K1];      // x split hi (padded)
__device__ __nv_bfloat16 g_xl[(size_t)NN * K1];
__device__ __nv_bfloat16 g_W1Th[(size_t)FOUT * K1];  // W1^T hi [n][k]
__device__ __nv_bfloat16 g_W1Tl[(size_t)FOUT * K1];
__device__ __nv_bfloat16 g_W2Th[(size_t)FOUT * FOUT]; // W2^T hi [n][k]
__device__ __nv_bfloat16 g_W2Tl[(size_t)FOUT * FOUT];
__device__ float g_asrc[NN * HEADS];
__device__ float g_adst[NN * HEADS];
__device__ float g_h3[NN], g_as3[NN], g_ad3[NN];
__device__ int   g_src[ET], g_dstv[ET], g_csrc[ET];
__device__ int   g_deg[NN], g_cursor[NN], g_rowoff[NN + 1];
__device__ int   g_is64;

// ---------------- helpers --------------------------------------------------
__device__ __forceinline__ float warp_red_sum(float v) {
    #pragma unroll
    for (int o = 16; o; o >>= 1) v += __shfl_xor_sync(0xffffffffu, v, o);
    return v;
}
__device__ __forceinline__ float warp_red_max(float v) {
    #pragma unroll
    for (int o = 16; o; o >>= 1) v = fmaxf(v, __shfl_xor_sync(0xffffffffu, v, o));
    return v;
}
__device__ __forceinline__ float leaky(float x) { return x > 0.f ? x : 0.2f * x; }

__device__ __forceinline__ uint32_t smem_u32(const void* p) {
    uint32_t a;
    asm("{ .reg .u64 t; cvta.to.shared.u64 t, %1; cvt.u32.u64 %0, t; }" : "=r"(a) : "l"(p));
    return a;
}

// pack two floats' bf16-hi parts into one uint, return residuals
__device__ __forceinline__ unsigned pk_hi(float a, float b, float& ra, float& rb) {
    __nv_bfloat16 ha = __float2bfloat16(a), hb = __float2bfloat16(b);
    ra = a - __bfloat162float(ha);
    rb = b - __bfloat162float(hb);
    return ((unsigned)__bfloat16_as_ushort(hb) << 16) | (unsigned)__bfloat16_as_ushort(ha);
}
__device__ __forceinline__ unsigned pk(float a, float b) {
    __nv_bfloat16 ha = __float2bfloat16(a), hb = __float2bfloat16(b);
    return ((unsigned)__bfloat16_as_ushort(hb) << 16) | (unsigned)__bfloat16_as_ushort(ha);
}

__device__ __forceinline__ void ldm_x4(unsigned r[4], uint32_t addr) {
    asm volatile("ldmatrix.sync.aligned.m8n8.x4.shared.b16 {%0,%1,%2,%3}, [%4];"
                 : "=r"(r[0]), "=r"(r[1]), "=r"(r[2]), "=r"(r[3]) : "r"(addr));
}
__device__ __forceinline__ void mma_bf16(float c[4], const unsigned a[4],
                                         unsigned b0, unsigned b1) {
    asm volatile(
        "mma.sync.aligned.m16n8k16.row.col.f32.bf16.bf16.f32 "
        "{%0,%1,%2,%3}, {%4,%5,%6,%7}, {%8,%9}, {%0,%1,%2,%3};"
        : "+f"(c[0]), "+f"(c[1]), "+f"(c[2]), "+f"(c[3])
        : "r"(a[0]), "r"(a[1]), "r"(a[2]), "r"(a[3]), "r"(b0), "r"(b1));
}

// ---------------- edge dtype detection + decode+count ----------------------
__global__ void detect_kernel(const unsigned* __restrict__ w) {
    if (threadIdx.x == 0) {
        int is64 = 1;
        for (int i = 1; i < 64; i += 2)
            if (w[i] != 0u) { is64 = 0; break; }
        g_is64 = is64;
    }
}

__global__ void zero0_kernel() {
    int i = blockIdx.x * blockDim.x + threadIdx.x;
    if (i < NN) g_deg[i] = 0;
    if (i < NN * HEADS) { g_asrc[i] = 0.f; g_adst[i] = 0.f; }
}

__global__ void zatt_kernel() {
    int i = blockIdx.x * blockDim.x + threadIdx.x;
    if (i < NN * HEADS) { g_asrc[i] = 0.f; g_adst[i] = 0.f; }
}

__global__ void decode_count_kernel(const void* __restrict__ ei) {
    int e = blockIdx.x * blockDim.x + threadIdx.x;
    if (e >= ET) return;
    int s, d;
    if (e < E0) {
        if (g_is64) {
            const long long* p = (const long long*)ei;
            s = (int)p[e]; d = (int)p[E0 + e];
        } else {
            const int* p = (const int*)ei;
            s = p[e]; d = p[E0 + e];
        }
    } else {
        s = d = e - E0;
    }
    g_src[e] = s; g_dstv[e] = d;
    atomicAdd(&g_deg[d], 1);
}

// single-pass scan: 1024 threads x 20 nodes each
__global__ __launch_bounds__(1024) void scan_kernel() {
    __shared__ int wsum[32];
    int t = threadIdx.x, lane = t & 31, w = t >> 5;
    int base = t * 20;
    int loc[20];
    int s = 0;
    #pragma unroll
    for (int i = 0; i < 20; i++) {
        int idx = base + i;
        int v = (idx < NN) ? g_deg[idx] : 0;
        s += v; loc[i] = s;
    }
    int x = s;
    #pragma unroll
    for (int o = 1; o < 32; o <<= 1) {
        int y = __shfl_up_sync(0xffffffffu, x, o);
        if (lane >= o) x += y;
    }
    if (lane == 31) wsum[w] = x;
    __syncthreads();
    if (w == 0) {
        int y = wsum[lane];
        #pragma unroll
        for (int o = 1; o < 32; o <<= 1) {
            int z = __shfl_up_sync(0xffffffffu, y, o);
            if (lane >= o) y += z;
        }
        wsum[lane] = y;
    }
    __syncthreads();
    int texcl = (w > 0 ? wsum[w - 1] : 0) + x - s;
    if (t == 0) g_rowoff[0] = 0;
    #pragma unroll
    for (int i = 0; i < 20; i++) {
        int idx = base + i;
        if (idx < NN) {
            g_rowoff[idx + 1] = texcl + loc[i];
            g_cursor[idx]     = texcl + (i ? loc[i - 1] : 0);
        }
    }
}

__global__ void scatter_kernel() {
    int e = blockIdx.x * blockDim.x + threadIdx.x;
    if (e >= ET) return;
    int d = g_dstv[e];
    int pos = atomicAdd(&g_cursor[d], 1);
    g_csrc[pos] = g_src[e];
}

// ---------------- weight prep ----------------------------------------------
__global__ __launch_bounds__(256) void transpose_kernel(const float* __restrict__ W) {
    __shared__ float tile[32][33];
    int bx = blockIdx.x * 32, by = blockIdx.y * 32;
    int tx = threadIdx.x, ty = threadIdx.y;
    #pragma unroll
    for (int i = 0; i < 32; i += 8)
        tile[ty + i][tx] = W[(size_t)(bx + ty + i) * 512 + by + tx];
    __syncthreads();
    #pragma unroll
    for (int i = 0; i < 32; i += 8) {
        float v = tile[tx][ty + i];
        __nv_bfloat16 h = __float2bfloat16(v);
        __nv_bfloat16 l = __float2bfloat16(v - __bfloat162float(h));
        size_t o = (size_t)(by + ty + i) * 512 + bx + tx;
        g_W2Th[o] = h;
        g_W2Tl[o] = l;
    }
}

__global__ void prep_x_kernel(const float* __restrict__ x) {
    int idx = blockIdx.x * blockDim.x + threadIdx.x;
    if (idx >= NN * K1) return;
    int n = idx >> 6, k = idx & 63;
    float v = (k < FIN) ? x[n * FIN + k] : 0.f;
    __nv_bfloat16 h = __float2bfloat16(v);
    g_xh[idx] = h;
    g_xl[idx] = __float2bfloat16(v - __bfloat162float(h));
}

__global__ void prep_w1_kernel(const float* __restrict__ W1) {
    int idx = blockIdx.x * blockDim.x + threadIdx.x;
    if (idx >= FOUT * K1) return;
    int n = idx >> 6, k = idx & 63;
    float v = (k < FIN) ? W1[(size_t)k * 512 + n] : 0.f;
    __nv_bfloat16 h = __float2bfloat16(v);
    g_W1Th[idx] = h;
    g_W1Tl[idx] = __float2bfloat16(v - __bfloat162float(h));
}

// ---------------- unified bf16 3-pass mma GEMM + fused attention dots ------
// C[128x128] per CTA; blockIdx.x = head (col block of 128). 8 warps 32x64.
// LAYER 1: A=g_xh/l (K=64), B=g_W1Th/l.  LAYER 2: A=g_hBh/l (K=512), B=g_W2Th/l.
// Epilogue: write g_hA fp32 + atomicAdd per-row dots with att vectors.
template<int LAYER>
__global__ __launch_bounds__(256) void mma_gemm_kernel(
    const float* __restrict__ atts, const float* __restrict__ attd)
{
    constexpr int K = (LAYER == 1) ? K1 : FOUT;
    constexpr int KITER = K / 32;

    __shared__ __nv_bfloat16 sAh[128][40];
    __shared__ __nv_bfloat16 sAl[128][40];
    __shared__ __nv_bfloat16 sBh[128][40];
    __shared__ __nv_bfloat16 sBl[128][40];
    __shared__ float satts[128], sattd[128];

    const __nv_bfloat16* __restrict__ Ah = (LAYER == 1) ? g_xh : g_hBh;
    const __nv_bfloat16* __restrict__ Al = (LAYER == 1) ? g_xl : g_hBl;
    const __nv_bfloat16* __restrict__ Bh = (LAYER == 1) ? g_W1Th : g_W2Th;
    const __nv_bfloat16* __restrict__ Bl = (LAYER == 1) ? g_W1Tl : g_W2Tl;

    int tid = threadIdx.x;
    int wid = tid >> 5, lane = tid & 31;
    int wm = (wid & 3) * 32;
    int wn = (wid >> 2) * 64;
    int head = blockIdx.x;
    int rowBase = blockIdx.y * 128;
    int colBase = head * 128;

    if (tid < 128) {
        satts[tid] = atts[head * 128 + tid];
        sattd[tid] = attd[head * 128 + tid];
    }

    float c[2][8][4];
    #pragma unroll
    for (int t = 0; t < 2; t++)
        #pragma unroll
        for (int j = 0; j < 8; j++)
            #pragma unroll
            for (int q = 0; q < 4; q++) c[t][j][q] = 0.f;

    uint32_t aBaseH = smem_u32(&sAh[0][0]);
    uint32_t aBaseL = smem_u32(&sAl[0][0]);
    uint32_t bBaseH = smem_u32(&sBh[0][0]);
    uint32_t bBaseL = smem_u32(&sBl[0][0]);
    int lr = lane & 15, lhalf = lane >> 4;

    for (int it = 0; it < KITER; it++) {
        // ---- A chunk [128 x 32] hi/lo, XOR-swizzled 16B units ----
        #pragma unroll
        for (int i = 0; i < 2; i++) {
            int idx = tid + i * 256;
            int r = idx >> 2, c8 = idx & 3;
            int grow = rowBase + r;
            uint4 vh = make_uint4(0, 0, 0, 0), vl = vh;
            if (grow < NN) {
                size_t go = (size_t)grow * K + it * 32 + c8 * 8;
                vh = *(const uint4*)(Ah + go);
                vl = *(const uint4*)(Al + go);
            }
            int sw = c8 ^ (r & 3);
            *(uint4*)((char*)&sAh[r][0] + sw * 16) = vh;
            *(uint4*)((char*)&sAl[r][0] + sw * 16) = vl;
        }
        // ---- B chunk [128 x 32] hi/lo ----
        #pragma unroll
        for (int i = 0; i < 2; i++) {
            int idx = tid + i * 256;
            int r = idx >> 2, c8 = idx & 3;
            size_t go = (size_t)(colBase + r) * K + it * 32 + c8 * 8;
            int sw = c8 ^ (r & 3);
            *(uint4*)((char*)&sBh[r][0] + sw * 16) = *(const uint4*)(Bh + go);
            *(uint4*)((char*)&sBl[r][0] + sw * 16) = *(const uint4*)(Bl + go);
        }
        __syncthreads();

        #pragma unroll
        for (int s = 0; s < 2; s++) {
            unsigned ah[2][4], al[2][4], bh[4][4], bl[4][4];
            #pragma unroll
            for (int t = 0; t < 2; t++) {
                int row = wm + t * 16 + lr;
                uint32_t unit = (uint32_t)((s * 2 + lhalf) ^ (row & 3));
                uint32_t off = (uint32_t)row * 80u + unit * 16u;
                ldm_x4(ah[t], aBaseH + off);
                ldm_x4(al[t], aBaseL + off);
            }
            #pragma unroll
            for (int p = 0; p < 4; p++) {
                int row = wn + p * 16 + lr;
                uint32_t unit = (uint32_t)((s * 2 + lhalf) ^ (row & 3));
                uint32_t off = (uint32_t)row * 80u + unit * 16u;
                ldm_x4(bh[p], bBaseH + off);
                ldm_x4(bl[p], bBaseL + off);
            }
            #pragma unroll
            for (int t = 0; t < 2; t++) {
                #pragma unroll
                for (int j = 0; j < 8; j++) {
                    int p = j >> 1;
                    unsigned bh0 = (j & 1) ? bh[p][1] : bh[p][0];
                    unsigned bh1 = (j & 1) ? bh[p][3] : bh[p][2];
                    unsigned bl0 = (j & 1) ? bl[p][1] : bl[p][0];
                    unsigned bl1 = (j & 1) ? bl[p][3] : bl[p][2];
                    mma_bf16(c[t][j], ah[t], bh0, bh1);
                    mma_bf16(c[t][j], ah[t], bl0, bl1);
                    mma_bf16(c[t][j], al[t], bh0, bh1);
                }
            }
        }
        __syncthreads();
    }

    // ---- epilogue: write C + fused per-row attention dots ----
    #pragma unroll
    for (int t = 0; t < 2; t++) {
        int r0 = rowBase + wm + t * 16 + (lane >> 2);
        #pragma unroll
        for (int j = 0; j < 8; j++) {
            int col = colBase + wn + j * 8 + (lane & 3) * 2;
            if (r0 < NN)
                *(float2*)&g_hA[(size_t)r0 * 512 + col] = make_float2(c[t][j][0], c[t][j][1]);
            if (r0 + 8 < NN)
                *(float2*)&g_hA[(size_t)(r0 + 8) * 512 + col] = make_float2(c[t][j][2], c[t][j][3]);
        }
        // dots: quad-local cols then shuffle-reduce over lane&3
        float s_a = 0.f, d_a = 0.f, s_b = 0.f, d_b = 0.f;
        #pragma unroll
        for (int j = 0; j < 8; j++) {
            int cl = wn + j * 8 + (lane & 3) * 2;
            float a0 = satts[cl], a1 = satts[cl + 1];
            float e0 = sattd[cl], e1 = sattd[cl + 1];
            s_a += c[t][j][0] * a0 + c[t][j][1] * a1;
            d_a += c[t][j][0] * e0 + c[t][j][1] * e1;
            s_b += c[t][j][2] * a0 + c[t][j][3] * a1;
            d_b += c[t][j][2] * e0 + c[t][j][3] * e1;
        }
        #pragma unroll
        for (int o = 1; o <= 2; o <<= 1) {
            s_a += __shfl_xor_sync(0xffffffffu, s_a, o);
            d_a += __shfl_xor_sync(0xffffffffu, d_a, o);
            s_b += __shfl_xor_sync(0xffffffffu, s_b, o);
            d_b += __shfl_xor_sync(0xffffffffu, d_b, o);
        }
        if ((lane & 3) == 0) {
            if (r0 < NN) {
                atomicAdd(&g_asrc[r0 * 4 + head], s_a);
                atomicAdd(&g_adst[r0 * 4 + head], d_a);
            }
            if (r0 + 8 < NN) {
                atomicAdd(&g_asrc[(r0 + 8) * 4 + head], s_b);
                atomicAdd(&g_adst[(r0 + 8) * 4 + head], d_b);
            }
        }
    }
}

// ---------------- per-node softmax + aggregate ------------------------------
// LAYER 1: output -> bf16 hi/lo (g_hBh/g_hBl) after ELU.
// LAYER 2: output -> fused GEMV with W3 => g_h3/g_as3/g_ad3 (no feature write).
template<int LAYER>
__global__ __launch_bounds__(512) void agg_kernel(
    const float* __restrict__ bias, const float* __restrict__ W3,
    const float* __restrict__ as3p, const float* __restrict__ ad3p)
{
    __shared__ float red[512];
    __shared__ float wch[512];     // 128 edges x 4 heads
    __shared__ int   sc[128];
    __shared__ float m4[4], inv4[4];
    __shared__ float4 sacc[512];
    __shared__ float wred[16];

    int n = blockIdx.x, t = threadIdx.x;
    int start = g_rowoff[n];
    int deg   = g_rowoff[n + 1] - start;
    int head = t & 3, el = t >> 2;
    int eg = t >> 7, cq = t & 127, hh = cq >> 5;
    float ad = g_adst[n * 4 + head];

    // phase 1: per-head max of leaky logits
    float lmax = -1e30f;
    for (int c = 0; c < deg; c += 128) {
        int e = c + el;
        if (e < deg) {
            int s = g_csrc[start + e];
            lmax = fmaxf(lmax, leaky(g_asrc[s * 4 + head] + ad));
        }
    }
    red[t] = lmax;
    __syncthreads();
    for (int s = 256; s >= 4; s >>= 1) {
        if (t < s) red[t] = fmaxf(red[t], red[t + s]);
        __syncthreads();
    }
    if (t < 4) m4[t] = red[t];
    __syncthreads();
    float m = m4[head];

    // phase 2: weights + vectorized accumulate
    float lsum = 0.f;
    float4 acc = make_float4(0.f, 0.f, 0.f, 0.f);
    const float4* __restrict__ hA4 = (const float4*)g_hA;
    for (int c = 0; c < deg; c += 128) {
        int e = c + el;
        if (e < deg) {
            int s = g_csrc[start + e];
            if (head == 0) sc[el] = s;
            float w = __expf(leaky(g_asrc[s * 4 + head] + ad) - m);
            wch[el * 4 + head] = w;
            lsum += w;
        }
        __syncthreads();
        int cend = min(128, deg - c);
        for (int e2 = eg; e2 < cend; e2 += 4) {
            float w = wch[e2 * 4 + hh];
            float4 v = hA4[(size_t)sc[e2] * 128 + cq];
            acc.x = fmaf(w, v.x, acc.x);
            acc.y = fmaf(w, v.y, acc.y);
            acc.z = fmaf(w, v.z, acc.z);
            acc.w = fmaf(w, v.w, acc.w);
        }
        __syncthreads();
    }
    red[t] = lsum;
    __syncthreads();
    for (int s = 256; s >= 4; s >>= 1) {
        if (t < s) red[t] += red[t + s];
        __syncthreads();
    }
    if (t < 4) inv4[t] = 1.f / (red[t] + 1e-16f);
    sacc[t] = acc;
    __syncthreads();

    float p = 0.f;
    if (eg == 0) {
        float4 a0 = sacc[t], a1 = sacc[t + 128], a2 = sacc[t + 256], a3 = sacc[t + 384];
        float inv = inv4[hh];
        float4 b4 = ((const float4*)bias)[t];
        float4 o;
        o.x = (a0.x + a1.x + a2.x + a3.x) * inv + b4.x;
        o.y = (a0.y + a1.y + a2.y + a3.y) * inv + b4.y;
        o.z = (a0.z + a1.z + a2.z + a3.z) * inv + b4.z;
        o.w = (a0.w + a1.w + a2.w + a3.w) * inv + b4.w;
        o.x = o.x > 0.f ? o.x : (__expf(o.x) - 1.f);
        o.y = o.y > 0.f ? o.y : (__expf(o.y) - 1.f);
        o.z = o.z > 0.f ? o.z : (__expf(o.z) - 1.f);
        o.w = o.w > 0.f ? o.w : (__expf(o.w) - 1.f);
        if (LAYER == 1) {
            float rx, ry, rz, rw;
            unsigned h0 = pk_hi(o.x, o.y, rx, ry);
            unsigned h1 = pk_hi(o.z, o.w, rz, rw);
            size_t go = (size_t)n * 512 + t * 4;
            *(uint2*)&g_hBh[go] = make_uint2(h0, h1);
            *(uint2*)&g_hBl[go] = make_uint2(pk(rx, ry), pk(rz, rw));
        } else {
            float4 w4 = ((const float4*)W3)[t];
            p = o.x * w4.x + o.y * w4.y + o.z * w4.z + o.w * w4.w;
        }
    }
    if (LAYER == 2) {
        p = warp_red_sum(p);
        if (!(t & 31)) wred[t >> 5] = p;
        __syncthreads();
        if (t == 0) {
            float h3 = 0.f;
            #pragma unroll
            for (int i = 0; i < 16; i++) h3 += wred[i];
            g_h3[n] = h3;
            g_as3[n] = h3 * as3p[0];
            g_ad3[n] = h3 * ad3p[0];
        }
    }
}

// ---------------- layer-3 aggregation ---------------------------------------
__global__ __launch_bounds__(256) void agg3_kernel(
    const float* __restrict__ b3, float* __restrict__ out)
{
    int n = blockIdx.x * 8 + (threadIdx.x >> 5);
    if (n >= NN) return;
    int lane = threadIdx.x & 31;
    int start = g_rowoff[n], deg = g_rowoff[n + 1] - start;
    float ad = g_ad3[n];
    float m = -1e30f;
    for (int e = lane; e < deg; e += 32) {
        int s = g_csrc[start + e];
        m = fmaxf(m, leaky(g_as3[s] + ad));
    }
    m = warp_red_max(m);
    float sum = 0.f, acc = 0.f;
    for (int e = lane; e < deg; e += 32) {
        int s = g_csrc[start + e];
        float w = __expf(leaky(g_as3[s] + ad) - m);
        sum += w;
        acc = fmaf(w, g_h3[s], acc);
    }
    sum = warp_red_sum(sum);
    acc = warp_red_sum(acc);
    if (!lane) out[n] = acc / (sum + 1e-16f) + b3[0];
}

// ---------------- launch ----------------------------------------------------
extern "C" void kernel_launch(void* const* d_in, const int* in_sizes, int n_in,
                              void* d_out, int out_size)
{
    const float* x   = (const float*)d_in[0];
    const void*  ei  = d_in[1];
    const float* W1  = (const float*)d_in[2];
    const float* as1 = (const float*)d_in[3];
    const float* ad1 = (const float*)d_in[4];
    const float* b1  = (const float*)d_in[5];
    const float* W2  = (const float*)d_in[6];
    const float* as2 = (const float*)d_in[7];
    const float* ad2 = (const float*)d_in[8];
    const float* b2  = (const float*)d_in[9];
    const float* W3  = (const float*)d_in[10];
    const float* as3 = (const float*)d_in[11];
    const float* ad3 = (const float*)d_in[12];
    const float* b3  = (const float*)d_in[13];
    float* out = (float*)d_out;

    dim3 gg(4, (NN + 127) / 128);

    // CSR build + prep
    detect_kernel<<<1, 32>>>((const unsigned*)ei);
    zero0_kernel<<<(NN * HEADS + 255) / 256, 256>>>();
    decode_count_kernel<<<(ET + 255) / 256, 256>>>(ei);
    scan_kernel<<<1, 1024>>>();
    scatter_kernel<<<(ET + 255) / 256, 256>>>();
    transpose_kernel<<<dim3(16, 16), dim3(32, 8)>>>(W2);
    prep_x_kernel<<<(NN * K1 + 255) / 256, 256>>>(x);
    prep_w1_kernel<<<(FOUT * K1 + 255) / 256, 256>>>(W1);

    // layer 1
    mma_gemm_kernel<1><<<gg, 256>>>(as1, ad1);
    agg_kernel<1><<<NN, 512>>>(b1, W3, as3, ad3);

    // layer 2
    zatt_kernel<<<(NN * HEADS + 255) / 256, 256>>>();
    mma_gemm_kernel<2><<<gg, 256>>>(as2, ad2);
    agg_kernel<2><<<NN, 512>>>(b2, W3, as3, ad3);

    // layer 3
    agg3_kernel<<<(NN + 7) / 8, 256>>>(b3, out);
}

// round 5
// speedup vs baseline: 2.3905x; 1.4882x over previous
#include <cuda_runtime.h>
#include <cuda_bf16.h>
#include <cstdint>

#define NN     20000
#define FIN    50
#define HID    128
#define HEADS  4
#define FOUT   512            // HEADS*HID
#define E0     320000
#define ET     (E0 + NN)      // edges incl. self-loops = 340000
#define K1     64             // layer-1 K padded 50 -> 64

// ---------------- scratch (device globals; no allocation allowed) ----------
__device__ float g_hA[(size_t)NN * FOUT];            // GEMM output (fp32)
__device__ __nv_bfloat16 g_hBh[(size_t)NN * FOUT];   // agg1 output hi
__device__ __nv_bfloat16 g_hBl[(size_t)NN * FOUT];   // agg1 output lo
__device__ __nv_bfloat16 g_xh[(size_t)NN * K1];      // x split hi (padded)
__device__ __nv_bfloat16 g_xl[(size_t)NN * K1];
__device__ __nv_bfloat16 g_W1Th[(size_t)FOUT * K1];  // W1^T hi [n][k]
__device__ __nv_bfloat16 g_W1Tl[(size_t)FOUT * K1];
__device__ __nv_bfloat16 g_W2Th[(size_t)FOUT * FOUT]; // W2^T hi [n][k]
__device__ __nv_bfloat16 g_W2Tl[(size_t)FOUT * FOUT];
__device__ float g_asrc[NN * HEADS];
__device__ float g_adst[NN * HEADS];
__device__ float g_h3[NN], g_as3[NN], g_ad3[NN];
__device__ int   g_src[ET], g_dstv[ET], g_csrc[ET];
__device__ int   g_deg[NN], g_cursor[NN], g_rowoff[NN + 1];
__device__ int   g_is64;

// ---------------- helpers --------------------------------------------------
__device__ __forceinline__ float warp_red_sum(float v) {
    #pragma unroll
    for (int o = 16; o; o >>= 1) v += __shfl_xor_sync(0xffffffffu, v, o);
    return v;
}
__device__ __forceinline__ float warp_red_max(float v) {
    #pragma unroll
    for (int o = 16; o; o >>= 1) v = fmaxf(v, __shfl_xor_sync(0xffffffffu, v, o));
    return v;
}
__device__ __forceinline__ float leaky(float x) { return x > 0.f ? x : 0.2f * x; }

__device__ __forceinline__ uint32_t smem_u32(const void* p) {
    uint32_t a;
    asm("{ .reg .u64 t; cvta.to.shared.u64 t, %1; cvt.u32.u64 %0, t; }" : "=r"(a) : "l"(p));
    return a;
}

// pack two floats' bf16-hi parts into one uint, return residuals
__device__ __forceinline__ unsigned pk_hi(float a, float b, float& ra, float& rb) {
    __nv_bfloat16 ha = __float2bfloat16(a), hb = __float2bfloat16(b);
    ra = a - __bfloat162float(ha);
    rb = b - __bfloat162float(hb);
    return ((unsigned)__bfloat16_as_ushort(hb) << 16) | (unsigned)__bfloat16_as_ushort(ha);
}
__device__ __forceinline__ unsigned pk(float a, float b) {
    __nv_bfloat16 ha = __float2bfloat16(a), hb = __float2bfloat16(b);
    return ((unsigned)__bfloat16_as_ushort(hb) << 16) | (unsigned)__bfloat16_as_ushort(ha);
}

__device__ __forceinline__ void ldm_x4(unsigned r[4], uint32_t addr) {
    asm volatile("ldmatrix.sync.aligned.m8n8.x4.shared.b16 {%0,%1,%2,%3}, [%4];"
                 : "=r"(r[0]), "=r"(r[1]), "=r"(r[2]), "=r"(r[3]) : "r"(addr));
}
__device__ __forceinline__ void mma_bf16(float c[4], const unsigned a[4],
                                         unsigned b0, unsigned b1) {
    asm volatile(
        "mma.sync.aligned.m16n8k16.row.col.f32.bf16.bf16.f32 "
        "{%0,%1,%2,%3}, {%4,%5,%6,%7}, {%8,%9}, {%0,%1,%2,%3};"
        : "+f"(c[0]), "+f"(c[1]), "+f"(c[2]), "+f"(c[3])
        : "r"(a[0]), "r"(a[1]), "r"(a[2]), "r"(a[3]), "r"(b0), "r"(b1));
}

// ---------------- edge dtype detection + decode+count ----------------------
__global__ void detect_kernel(const unsigned* __restrict__ w) {
    if (threadIdx.x == 0) {
        int is64 = 1;
        for (int i = 1; i < 64; i += 2)
            if (w[i] != 0u) { is64 = 0; break; }
        g_is64 = is64;
    }
}

__global__ void zero0_kernel() {
    int i = blockIdx.x * blockDim.x + threadIdx.x;
    if (i < NN) g_deg[i] = 0;
    if (i < NN * HEADS) { g_asrc[i] = 0.f; g_adst[i] = 0.f; }
}

__global__ void zatt_kernel() {
    int i = blockIdx.x * blockDim.x + threadIdx.x;
    if (i < NN * HEADS) { g_asrc[i] = 0.f; g_adst[i] = 0.f; }
}

__global__ void decode_count_kernel(const void* __restrict__ ei) {
    int e = blockIdx.x * blockDim.x + threadIdx.x;
    if (e >= ET) return;
    int s, d;
    if (e < E0) {
        if (g_is64) {
            const long long* p = (const long long*)ei;
            s = (int)p[e]; d = (int)p[E0 + e];
        } else {
            const int* p = (const int*)ei;
            s = p[e]; d = p[E0 + e];
        }
    } else {
        s = d = e - E0;
    }
    g_src[e] = s; g_dstv[e] = d;
    atomicAdd(&g_deg[d], 1);
}

// single-pass scan with coalesced smem staging (80 KB dynamic smem)
__global__ __launch_bounds__(1024) void scan_kernel() {
    extern __shared__ int sdeg[];
    __shared__ int wsum[32];
    int t = threadIdx.x, lane = t & 31, w = t >> 5;
    for (int i = t; i < NN; i += 1024) sdeg[i] = g_deg[i];
    __syncthreads();

    int base = t * 20;
    int loc[20];
    int s = 0;
    #pragma unroll
    for (int i = 0; i < 20; i++) {
        int idx = base + i;
        int v = (idx < NN) ? sdeg[idx] : 0;
        s += v; loc[i] = s;
    }
    int x = s;
    #pragma unroll
    for (int o = 1; o < 32; o <<= 1) {
        int y = __shfl_up_sync(0xffffffffu, x, o);
        if (lane >= o) x += y;
    }
    if (lane == 31) wsum[w] = x;
    __syncthreads();
    if (w == 0) {
        int y = wsum[lane];
        #pragma unroll
        for (int o = 1; o < 32; o <<= 1) {
            int z = __shfl_up_sync(0xffffffffu, y, o);
            if (lane >= o) y += z;
        }
        wsum[lane] = y;
    }
    __syncthreads();
    int texcl = (w > 0 ? wsum[w - 1] : 0) + x - s;
    if (t == 0) g_rowoff[0] = 0;
    #pragma unroll
    for (int i = 0; i < 20; i++) {
        int idx = base + i;
        if (idx < NN) {
            g_rowoff[idx + 1] = texcl + loc[i];
            g_cursor[idx]     = texcl + (i ? loc[i - 1] : 0);
        }
    }
}

__global__ void scatter_kernel() {
    int e = blockIdx.x * blockDim.x + threadIdx.x;
    if (e >= ET) return;
    int d = g_dstv[e];
    int pos = atomicAdd(&g_cursor[d], 1);
    g_csrc[pos] = g_src[e];
}

// ---------------- weight prep ----------------------------------------------
__global__ __launch_bounds__(256) void transpose_kernel(const float* __restrict__ W) {
    __shared__ float tile[32][33];
    int bx = blockIdx.x * 32, by = blockIdx.y * 32;
    int tx = threadIdx.x, ty = threadIdx.y;
    #pragma unroll
    for (int i = 0; i < 32; i += 8)
        tile[ty + i][tx] = W[(size_t)(bx + ty + i) * 512 + by + tx];
    __syncthreads();
    #pragma unroll
    for (int i = 0; i < 32; i += 8) {
        float v = tile[tx][ty + i];
        __nv_bfloat16 h = __float2bfloat16(v);
        __nv_bfloat16 l = __float2bfloat16(v - __bfloat162float(h));
        size_t o = (size_t)(by + ty + i) * 512 + bx + tx;
        g_W2Th[o] = h;
        g_W2Tl[o] = l;
    }
}

__global__ void prep_x_kernel(const float* __restrict__ x) {
    int idx = blockIdx.x * blockDim.x + threadIdx.x;
    if (idx >= NN * K1) return;
    int n = idx >> 6, k = idx & 63;
    float v = (k < FIN) ? x[n * FIN + k] : 0.f;
    __nv_bfloat16 h = __float2bfloat16(v);
    g_xh[idx] = h;
    g_xl[idx] = __float2bfloat16(v - __bfloat162float(h));
}

__global__ void prep_w1_kernel(const float* __restrict__ W1) {
    int idx = blockIdx.x * blockDim.x + threadIdx.x;
    if (idx >= FOUT * K1) return;
    int n = idx >> 6, k = idx & 63;
    float v = (k < FIN) ? W1[(size_t)k * 512 + n] : 0.f;
    __nv_bfloat16 h = __float2bfloat16(v);
    g_W1Th[idx] = h;
    g_W1Tl[idx] = __float2bfloat16(v - __bfloat162float(h));
}

// ---------------- unified bf16 3-pass mma GEMM + fused attention dots ------
template<int LAYER>
__global__ __launch_bounds__(256) void mma_gemm_kernel(
    const float* __restrict__ atts, const float* __restrict__ attd)
{
    constexpr int K = (LAYER == 1) ? K1 : FOUT;
    constexpr int KITER = K / 32;

    __shared__ __nv_bfloat16 sAh[128][40];
    __shared__ __nv_bfloat16 sAl[128][40];
    __shared__ __nv_bfloat16 sBh[128][40];
    __shared__ __nv_bfloat16 sBl[128][40];
    __shared__ float satts[128], sattd[128];

    const __nv_bfloat16* __restrict__ Ah = (LAYER == 1) ? g_xh : g_hBh;
    const __nv_bfloat16* __restrict__ Al = (LAYER == 1) ? g_xl : g_hBl;
    const __nv_bfloat16* __restrict__ Bh = (LAYER == 1) ? g_W1Th : g_W2Th;
    const __nv_bfloat16* __restrict__ Bl = (LAYER == 1) ? g_W1Tl : g_W2Tl;

    int tid = threadIdx.x;
    int wid = tid >> 5, lane = tid & 31;
    int wm = (wid & 3) * 32;
    int wn = (wid >> 2) * 64;
    int head = blockIdx.x;
    int rowBase = blockIdx.y * 128;
    int colBase = head * 128;

    if (tid < 128) {
        satts[tid] = atts[head * 128 + tid];
        sattd[tid] = attd[head * 128 + tid];
    }

    float c[2][8][4];
    #pragma unroll
    for (int t = 0; t < 2; t++)
        #pragma unroll
        for (int j = 0; j < 8; j++)
            #pragma unroll
            for (int q = 0; q < 4; q++) c[t][j][q] = 0.f;

    uint32_t aBaseH = smem_u32(&sAh[0][0]);
    uint32_t aBaseL = smem_u32(&sAl[0][0]);
    uint32_t bBaseH = smem_u32(&sBh[0][0]);
    uint32_t bBaseL = smem_u32(&sBl[0][0]);
    int lr = lane & 15, lhalf = lane >> 4;

    for (int it = 0; it < KITER; it++) {
        #pragma unroll
        for (int i = 0; i < 2; i++) {
            int idx = tid + i * 256;
            int r = idx >> 2, c8 = idx & 3;
            int grow = rowBase + r;
            uint4 vh = make_uint4(0, 0, 0, 0), vl = vh;
            if (grow < NN) {
                size_t go = (size_t)grow * K + it * 32 + c8 * 8;
                vh = *(const uint4*)(Ah + go);
                vl = *(const uint4*)(Al + go);
            }
            int sw = c8 ^ (r & 3);
            *(uint4*)((char*)&sAh[r][0] + sw * 16) = vh;
            *(uint4*)((char*)&sAl[r][0] + sw * 16) = vl;
        }
        #pragma unroll
        for (int i = 0; i < 2; i++) {
            int idx = tid + i * 256;
            int r = idx >> 2, c8 = idx & 3;
            size_t go = (size_t)(colBase + r) * K + it * 32 + c8 * 8;
            int sw = c8 ^ (r & 3);
            *(uint4*)((char*)&sBh[r][0] + sw * 16) = *(const uint4*)(Bh + go);
            *(uint4*)((char*)&sBl[r][0] + sw * 16) = *(const uint4*)(Bl + go);
        }
        __syncthreads();

        #pragma unroll
        for (int s = 0; s < 2; s++) {
            unsigned ah[2][4], al[2][4], bh[4][4], bl[4][4];
            #pragma unroll
            for (int t = 0; t < 2; t++) {
                int row = wm + t * 16 + lr;
                uint32_t unit = (uint32_t)((s * 2 + lhalf) ^ (row & 3));
                uint32_t off = (uint32_t)row * 80u + unit * 16u;
                ldm_x4(ah[t], aBaseH + off);
                ldm_x4(al[t], aBaseL + off);
            }
            #pragma unroll
            for (int p = 0; p < 4; p++) {
                int row = wn + p * 16 + lr;
                uint32_t unit = (uint32_t)((s * 2 + lhalf) ^ (row & 3));
                uint32_t off = (uint32_t)row * 80u + unit * 16u;
                ldm_x4(bh[p], bBaseH + off);
                ldm_x4(bl[p], bBaseL + off);
            }
            #pragma unroll
            for (int t = 0; t < 2; t++) {
                #pragma unroll
                for (int j = 0; j < 8; j++) {
                    int p = j >> 1;
                    unsigned bh0 = (j & 1) ? bh[p][1] : bh[p][0];
                    unsigned bh1 = (j & 1) ? bh[p][3] : bh[p][2];
                    unsigned bl0 = (j & 1) ? bl[p][1] : bl[p][0];
                    unsigned bl1 = (j & 1) ? bl[p][3] : bl[p][2];
                    mma_bf16(c[t][j], ah[t], bh0, bh1);
                    mma_bf16(c[t][j], ah[t], bl0, bl1);
                    mma_bf16(c[t][j], al[t], bh0, bh1);
                }
            }
        }
        __syncthreads();
    }

    #pragma unroll
    for (int t = 0; t < 2; t++) {
        int r0 = rowBase + wm + t * 16 + (lane >> 2);
        #pragma unroll
        for (int j = 0; j < 8; j++) {
            int col = colBase + wn + j * 8 + (lane & 3) * 2;
            if (r0 < NN)
                *(float2*)&g_hA[(size_t)r0 * 512 + col] = make_float2(c[t][j][0], c[t][j][1]);
            if (r0 + 8 < NN)
                *(float2*)&g_hA[(size_t)(r0 + 8) * 512 + col] = make_float2(c[t][j][2], c[t][j][3]);
        }
        float s_a = 0.f, d_a = 0.f, s_b = 0.f, d_b = 0.f;
        #pragma unroll
        for (int j = 0; j < 8; j++) {
            int cl = wn + j * 8 + (lane & 3) * 2;
            float a0 = satts[cl], a1 = satts[cl + 1];
            float e0 = sattd[cl], e1 = sattd[cl + 1];
            s_a += c[t][j][0] * a0 + c[t][j][1] * a1;
            d_a += c[t][j][0] * e0 + c[t][j][1] * e1;
            s_b += c[t][j][2] * a0 + c[t][j][3] * a1;
            d_b += c[t][j][2] * e0 + c[t][j][3] * e1;
        }
        #pragma unroll
        for (int o = 1; o <= 2; o <<= 1) {
            s_a += __shfl_xor_sync(0xffffffffu, s_a, o);
            d_a += __shfl_xor_sync(0xffffffffu, d_a, o);
            s_b += __shfl_xor_sync(0xffffffffu, s_b, o);
            d_b += __shfl_xor_sync(0xffffffffu, d_b, o);
        }
        if ((lane & 3) == 0) {
            if (r0 < NN) {
                atomicAdd(&g_asrc[r0 * 4 + head], s_a);
                atomicAdd(&g_adst[r0 * 4 + head], d_a);
            }
            if (r0 + 8 < NN) {
                atomicAdd(&g_asrc[(r0 + 8) * 4 + head], s_b);
                atomicAdd(&g_adst[(r0 + 8) * 4 + head], d_b);
            }
        }
    }
}

// ---------------- warp-per-node softmax + aggregate -------------------------
// 8 warps per block, one node per warp, no block barriers.
// lane layout for logits: e-slot = lane>>2 (8 edges/pass), head = lane&3.
// feature accumulate: float4 group it in 0..3 covers channels [it*128 + lane*4 ..+3],
// whose head is exactly it.
template<int LAYER>
__global__ __launch_bounds__(256) void wagg_kernel(
    const float* __restrict__ bias, const float* __restrict__ W3,
    const float* __restrict__ as3p, const float* __restrict__ ad3p)
{
    __shared__ float wbuf[8][32 * 4];   // per warp: 32 edges x 4 heads
    __shared__ int   sbuf[8][32];       // per warp: src ids of chunk

    int w = threadIdx.x >> 5, lane = threadIdx.x & 31;
    int n = blockIdx.x * 8 + w;
    if (n >= NN) return;
    int start = g_rowoff[n];
    int deg   = g_rowoff[n + 1] - start;
    int head  = lane & 3, eslot = lane >> 2;
    float ad = g_adst[n * 4 + head];

    // ---- pass 1: per-head max ----
    float mx = -1e30f;
    for (int c = 0; c < deg; c += 8) {
        int e = c + eslot;
        if (e < deg) {
            int s = g_csrc[start + e];
            mx = fmaxf(mx, leaky(g_asrc[s * 4 + head] + ad));
        }
    }
    #pragma unroll
    for (int o = 4; o < 32; o <<= 1)
        mx = fmaxf(mx, __shfl_xor_sync(0xffffffffu, mx, o));

    // ---- pass 2: weights + accumulate ----
    float ssum = 0.f;
    float4 acc[4];
    #pragma unroll
    for (int i = 0; i < 4; i++) acc[i] = make_float4(0.f, 0.f, 0.f, 0.f);
    const float4* __restrict__ hA4 = (const float4*)g_hA;

    for (int c = 0; c < deg; c += 32) {
        #pragma unroll
        for (int sp = 0; sp < 4; sp++) {
            int el = sp * 8 + eslot;
            int e = c + el;
            float wgt = 0.f;
            if (e < deg) {
                int s = g_csrc[start + e];
                if (head == 0) sbuf[w][el] = s;
                wgt = __expf(leaky(g_asrc[s * 4 + head] + ad) - mx);
            }
            wbuf[w][el * 4 + head] = wgt;
            ssum += wgt;
        }
        __syncwarp();
        int cend = min(32, deg - c);
        for (int e2 = 0; e2 < cend; e2++) {
            int s = sbuf[w][e2];
            const float4* hp = hA4 + (size_t)s * 128 + lane;
            #pragma unroll
            for (int i = 0; i < 4; i++) {
                float wgt = wbuf[w][e2 * 4 + i];
                float4 v = hp[i * 32];
                acc[i].x = fmaf(wgt, v.x, acc[i].x);
                acc[i].y = fmaf(wgt, v.y, acc[i].y);
                acc[i].z = fmaf(wgt, v.z, acc[i].z);
                acc[i].w = fmaf(wgt, v.w, acc[i].w);
            }
        }
        __syncwarp();
    }
    #pragma unroll
    for (int o = 4; o < 32; o <<= 1)
        ssum += __shfl_xor_sync(0xffffffffu, ssum, o);

    float inv[4];
    #pragma unroll
    for (int i = 0; i < 4; i++)
        inv[i] = 1.f / (__shfl_sync(0xffffffffu, ssum, i) + 1e-16f);

    // ---- epilogue ----
    float p = 0.f;
    #pragma unroll
    for (int i = 0; i < 4; i++) {
        float4 b4 = ((const float4*)bias)[i * 32 + lane];
        float4 o;
        o.x = acc[i].x * inv[i] + b4.x;
        o.y = acc[i].y * inv[i] + b4.y;
        o.z = acc[i].z * inv[i] + b4.z;
        o.w = acc[i].w * inv[i] + b4.w;
        o.x = o.x > 0.f ? o.x : (__expf(o.x) - 1.f);
        o.y = o.y > 0.f ? o.y : (__expf(o.y) - 1.f);
        o.z = o.z > 0.f ? o.z : (__expf(o.z) - 1.f);
        o.w = o.w > 0.f ? o.w : (__expf(o.w) - 1.f);
        if (LAYER == 1) {
            float rx, ry, rz, rw;
            unsigned h0 = pk_hi(o.x, o.y, rx, ry);
            unsigned h1 = pk_hi(o.z, o.w, rz, rw);
            size_t go = (size_t)n * 512 + i * 128 + lane * 4;
            *(uint2*)&g_hBh[go] = make_uint2(h0, h1);
            *(uint2*)&g_hBl[go] = make_uint2(pk(rx, ry), pk(rz, rw));
        } else {
            float4 w4 = ((const float4*)W3)[i * 32 + lane];
            p += o.x * w4.x + o.y * w4.y + o.z * w4.z + o.w * w4.w;
        }
    }
    if (LAYER == 2) {
        p = warp_red_sum(p);
        if (lane == 0) {
            g_h3[n] = p;
            g_as3[n] = p * as3p[0];
            g_ad3[n] = p * ad3p[0];
        }
    }
}

// ---------------- layer-3 aggregation ---------------------------------------
__global__ __launch_bounds__(256) void agg3_kernel(
    const float* __restrict__ b3, float* __restrict__ out)
{
    int n = blockIdx.x * 8 + (threadIdx.x >> 5);
    if (n >= NN) return;
    int lane = threadIdx.x & 31;
    int start = g_rowoff[n], deg = g_rowoff[n + 1] - start;
    float ad = g_ad3[n];
    float m = -1e30f;
    for (int e = lane; e < deg; e += 32) {
        int s = g_csrc[start + e];
        m = fmaxf(m, leaky(g_as3[s] + ad));
    }
    m = warp_red_max(m);
    float sum = 0.f, acc = 0.f;
    for (int e = lane; e < deg; e += 32) {
        int s = g_csrc[start + e];
        float w = __expf(leaky(g_as3[s] + ad) - m);
        sum += w;
        acc = fmaf(w, g_h3[s], acc);
    }
    sum = warp_red_sum(sum);
    acc = warp_red_sum(acc);
    if (!lane) out[n] = acc / (sum + 1e-16f) + b3[0];
}

// ---------------- launch ----------------------------------------------------
extern "C" void kernel_launch(void* const* d_in, const int* in_sizes, int n_in,
                              void* d_out, int out_size)
{
    const float* x   = (const float*)d_in[0];
    const void*  ei  = d_in[1];
    const float* W1  = (const float*)d_in[2];
    const float* as1 = (const float*)d_in[3];
    const float* ad1 = (const float*)d_in[4];
    const float* b1  = (const float*)d_in[5];
    const float* W2  = (const float*)d_in[6];
    const float* as2 = (const float*)d_in[7];
    const float* ad2 = (const float*)d_in[8];
    const float* b2  = (const float*)d_in[9];
    const float* W3  = (const float*)d_in[10];
    const float* as3 = (const float*)d_in[11];
    const float* ad3 = (const float*)d_in[12];
    const float* b3  = (const float*)d_in[13];
    float* out = (float*)d_out;

    cudaFuncSetAttribute(scan_kernel,
                         cudaFuncAttributeMaxDynamicSharedMemorySize, NN * 4);

    dim3 gg(4, (NN + 127) / 128);

    // CSR build + prep
    detect_kernel<<<1, 32>>>((const unsigned*)ei);
    zero0_kernel<<<(NN * HEADS + 255) / 256, 256>>>();
    decode_count_kernel<<<(ET + 255) / 256, 256>>>(ei);
    scan_kernel<<<1, 1024, NN * 4>>>();
    scatter_kernel<<<(ET + 255) / 256, 256>>>();
    transpose_kernel<<<dim3(16, 16), dim3(32, 8)>>>(W2);
    prep_x_kernel<<<(NN * K1 + 255) / 256, 256>>>(x);
    prep_w1_kernel<<<(FOUT * K1 + 255) / 256, 256>>>(W1);

    // layer 1
    mma_gemm_kernel<1><<<gg, 256>>>(as1, ad1);
    wagg_kernel<1><<<(NN + 7) / 8, 256>>>(b1, W3, as3, ad3);

    // layer 2
    zatt_kernel<<<(NN * HEADS + 255) / 256, 256>>>();
    mma_gemm_kernel<2><<<gg, 256>>>(as2, ad2);
    wagg_kernel<2><<<(NN + 7) / 8, 256>>>(b2, W3, as3, ad3);

    // layer 3
    agg3_kernel<<<(NN + 7) / 8, 256>>>(b3, out);
}

// round 6
// speedup vs baseline: 2.7678x; 1.1578x over previous
#include <cuda_runtime.h>
#include <cuda_bf16.h>
#include <cstdint>

#define NN     20000
#define FIN    50
#define HID    128
#define HEADS  4
#define FOUT   512            // HEADS*HID
#define E0     320000
#define ET     (E0 + NN)      // edges incl. self-loops = 340000
#define K1     64             // layer-1 K padded 50 -> 64
#define NB     20             // scan blocks (ceil(NN/1024))

// ---------------- scratch (device globals; no allocation allowed) ----------
__device__ float g_hA[(size_t)NN * FOUT];            // GEMM output (fp32)
__device__ __nv_bfloat16 g_hBh[(size_t)NN * FOUT];   // agg1 output hi
__device__ __nv_bfloat16 g_hBl[(size_t)NN * FOUT];   // agg1 output lo
__device__ __nv_bfloat16 g_xh[(size_t)NN * K1];      // x split hi (padded)
__device__ __nv_bfloat16 g_xl[(size_t)NN * K1];
__device__ __nv_bfloat16 g_W1Th[(size_t)FOUT * K1];  // W1^T hi [n][k]
__device__ __nv_bfloat16 g_W1Tl[(size_t)FOUT * K1];
__device__ __nv_bfloat16 g_W2Th[(size_t)FOUT * FOUT]; // W2^T hi [n][k]
__device__ __nv_bfloat16 g_W2Tl[(size_t)FOUT * FOUT];
__device__ float g_asrc[NN * HEADS],  g_adst[NN * HEADS];    // layer-1 dots
__device__ float g_asrc2[NN * HEADS], g_adst2[NN * HEADS];   // layer-2 dots
__device__ float g_h3[NN], g_as3[NN], g_ad3[NN];
__device__ int   g_src[ET], g_dstv[ET], g_csrc[ET];
__device__ int   g_deg[NN], g_cursor[NN], g_rowoff[NN + 1];
__device__ int   g_bsum[32];
__device__ int   g_is64;

// ---------------- helpers --------------------------------------------------
__device__ __forceinline__ float warp_red_sum(float v) {
    #pragma unroll
    for (int o = 16; o; o >>= 1) v += __shfl_xor_sync(0xffffffffu, v, o);
    return v;
}
__device__ __forceinline__ float warp_red_max(float v) {
    #pragma unroll
    for (int o = 16; o; o >>= 1) v = fmaxf(v, __shfl_xor_sync(0xffffffffu, v, o));
    return v;
}
__device__ __forceinline__ float leaky(float x) { return x > 0.f ? x : 0.2f * x; }

__device__ __forceinline__ uint32_t smem_u32(const void* p) {
    uint32_t a;
    asm("{ .reg .u64 t; cvta.to.shared.u64 t, %1; cvt.u32.u64 %0, t; }" : "=r"(a) : "l"(p));
    return a;
}

__device__ __forceinline__ unsigned pk_hi(float a, float b, float& ra, float& rb) {
    __nv_bfloat16 ha = __float2bfloat16(a), hb = __float2bfloat16(b);
    ra = a - __bfloat162float(ha);
    rb = b - __bfloat162float(hb);
    return ((unsigned)__bfloat16_as_ushort(hb) << 16) | (unsigned)__bfloat16_as_ushort(ha);
}
__device__ __forceinline__ unsigned pk(float a, float b) {
    __nv_bfloat16 ha = __float2bfloat16(a), hb = __float2bfloat16(b);
    return ((unsigned)__bfloat16_as_ushort(hb) << 16) | (unsigned)__bfloat16_as_ushort(ha);
}

__device__ __forceinline__ void ldm_x4(unsigned r[4], uint32_t addr) {
    asm volatile("ldmatrix.sync.aligned.m8n8.x4.shared.b16 {%0,%1,%2,%3}, [%4];"
                 : "=r"(r[0]), "=r"(r[1]), "=r"(r[2]), "=r"(r[3]) : "r"(addr));
}
__device__ __forceinline__ void mma_bf16(float c[4], const unsigned a[4],
                                         unsigned b0, unsigned b1) {
    asm volatile(
        "mma.sync.aligned.m16n8k16.row.col.f32.bf16.bf16.f32 "
        "{%0,%1,%2,%3}, {%4,%5,%6,%7}, {%8,%9}, {%0,%1,%2,%3};"
        : "+f"(c[0]), "+f"(c[1]), "+f"(c[2]), "+f"(c[3])
        : "r"(a[0]), "r"(a[1]), "r"(a[2]), "r"(a[3]), "r"(b0), "r"(b1));
}
__device__ __forceinline__ void cpa16(uint32_t dst, const void* src, bool p) {
    int sz = p ? 16 : 0;
    asm volatile("cp.async.cg.shared.global [%0], [%1], 16, %2;"
                 :: "r"(dst), "l"(src), "r"(sz));
}
__device__ __forceinline__ void cpa_commit() {
    asm volatile("cp.async.commit_group;");
}
template<int N> __device__ __forceinline__ void cpa_wait() {
    asm volatile("cp.async.wait_group %0;" :: "n"(N));
}

// ---------------- edge dtype detection + decode+count ----------------------
__global__ void detect_kernel(const unsigned* __restrict__ w) {
    if (threadIdx.x == 0) {
        int is64 = 1;
        for (int i = 1; i < 64; i += 2)
            if (w[i] != 0u) { is64 = 0; break; }
        g_is64 = is64;
    }
}

__global__ void zero0_kernel() {
    int i = blockIdx.x * blockDim.x + threadIdx.x;
    if (i < NN) g_deg[i] = 0;
    if (i < NN * HEADS) {
        g_asrc[i] = 0.f;  g_adst[i] = 0.f;
        g_asrc2[i] = 0.f; g_adst2[i] = 0.f;
    }
}

__global__ void decode_count_kernel(const void* __restrict__ ei) {
    int e = blockIdx.x * blockDim.x + threadIdx.x;
    if (e >= ET) return;
    int s, d;
    if (e < E0) {
        if (g_is64) {
            const long long* p = (const long long*)ei;
            s = (int)p[e]; d = (int)p[E0 + e];
        } else {
            const int* p = (const int*)ei;
            s = p[e]; d = p[E0 + e];
        }
    } else {
        s = d = e - E0;
    }
    g_src[e] = s; g_dstv[e] = d;
    atomicAdd(&g_deg[d], 1);
}

// ---------------- multi-block scan (3 tiny kernels) -------------------------
__global__ __launch_bounds__(1024) void scan1_kernel() {
    __shared__ int wsum[32];
    int b = blockIdx.x, t = threadIdx.x, lane = t & 31, w = t >> 5;
    int i = b * 1024 + t;
    int v = (i < NN) ? g_deg[i] : 0;
    int x = v;
    #pragma unroll
    for (int o = 1; o < 32; o <<= 1) {
        int y = __shfl_up_sync(0xffffffffu, x, o);
        if (lane >= o) x += y;
    }
    if (lane == 31) wsum[w] = x;
    __syncthreads();
    if (w == 0) {
        int y = wsum[lane];
        #pragma unroll
        for (int o = 1; o < 32; o <<= 1) {
            int z = __shfl_up_sync(0xffffffffu, y, o);
            if (lane >= o) y += z;
        }
        wsum[lane] = y;
    }
    __syncthreads();
    int incl = x + (w ? wsum[w - 1] : 0);
    if (i < NN) {
        g_rowoff[i + 1] = incl;
        g_cursor[i]     = incl - v;
    }
    if (t == 1023) g_bsum[b] = incl;
}

__global__ void scan2_kernel() {
    int lane = threadIdx.x;
    int v = (lane < NB) ? g_bsum[lane] : 0;
    int x = v;
    #pragma unroll
    for (int o = 1; o < 32; o <<= 1) {
        int y = __shfl_up_sync(0xffffffffu, x, o);
        if (lane >= o) x += y;
    }
    if (lane < NB) g_bsum[lane] = x - v;   // exclusive
}

__global__ __launch_bounds__(1024) void scan3_kernel() {
    int b = blockIdx.x, t = threadIdx.x;
    int i = b * 1024 + t;
    int off = g_bsum[b];
    if (i < NN) {
        g_rowoff[i + 1] += off;
        g_cursor[i]     += off;
    }
    if (b == 0 && t == 0) g_rowoff[0] = 0;
}

__global__ void scatter_kernel() {
    int e = blockIdx.x * blockDim.x + threadIdx.x;
    if (e >= ET) return;
    int d = g_dstv[e];
    int pos = atomicAdd(&g_cursor[d], 1);
    g_csrc[pos] = g_src[e];
}

// ---------------- combined weight/x prep ------------------------------------
// blocks [0,256): W2 transpose+split; [256,5256): x split; [5256,5384): W1 split
__global__ __launch_bounds__(256) void prep_kernel(
    const float* __restrict__ W1, const float* __restrict__ W2,
    const float* __restrict__ x)
{
    int b = blockIdx.x, t = threadIdx.x;
    if (b < 256) {
        __shared__ float tile[32][33];
        int bx = (b & 15) * 32, by = (b >> 4) * 32;
        int tx = t & 31, ty = t >> 5;
        #pragma unroll
        for (int i = 0; i < 32; i += 8)
            tile[ty + i][tx] = W2[(size_t)(bx + ty + i) * 512 + by + tx];
        __syncthreads();
        #pragma unroll
        for (int i = 0; i < 32; i += 8) {
            float v = tile[tx][ty + i];
            __nv_bfloat16 h = __float2bfloat16(v);
            __nv_bfloat16 l = __float2bfloat16(v - __bfloat162float(h));
            size_t o = (size_t)(by + ty + i) * 512 + bx + tx;
            g_W2Th[o] = h;
            g_W2Tl[o] = l;
        }
    } else if (b < 256 + (NN * K1) / 256) {
        int idx = (b - 256) * 256 + t;
        int n = idx >> 6, k = idx & 63;
        float v = (k < FIN) ? x[n * FIN + k] : 0.f;
        __nv_bfloat16 h = __float2bfloat16(v);
        g_xh[idx] = h;
        g_xl[idx] = __float2bfloat16(v - __bfloat162float(h));
    } else {
        int idx = (b - 256 - (NN * K1) / 256) * 256 + t;
        if (idx < FOUT * K1) {
            int n = idx >> 6, k = idx & 63;
            float v = (k < FIN) ? W1[(size_t)k * 512 + n] : 0.f;
            __nv_bfloat16 h = __float2bfloat16(v);
            g_W1Th[idx] = h;
            g_W1Tl[idx] = __float2bfloat16(v - __bfloat162float(h));
        }
    }
}

// ---------------- cp.async double-buffered bf16 3-pass mma GEMM -------------
// dynamic smem: 2 buffers x {AH,AL,BH,BL} of 10240 B each, then atts/attd.
#define TB   10240                 // one tile array
#define BUF  (4 * TB)              // one buffer = 40960
#define SM_ATT (2 * BUF)           // 81920
#define SM_TOTAL (SM_ATT + 1024)

template<int LAYER>
__global__ __launch_bounds__(256) void mma_gemm_kernel(
    const float* __restrict__ atts, const float* __restrict__ attd)
{
    constexpr int K = (LAYER == 1) ? K1 : FOUT;
    constexpr int KITER = K / 32;

    extern __shared__ char dsm[];
    float* satts = (float*)(dsm + SM_ATT);
    float* sattd = satts + 128;

    const __nv_bfloat16* __restrict__ Ah = (LAYER == 1) ? g_xh : g_hBh;
    const __nv_bfloat16* __restrict__ Al = (LAYER == 1) ? g_xl : g_hBl;
    const __nv_bfloat16* __restrict__ Bh = (LAYER == 1) ? g_W1Th : g_W2Th;
    const __nv_bfloat16* __restrict__ Bl = (LAYER == 1) ? g_W1Tl : g_W2Tl;

    int tid = threadIdx.x;
    int wid = tid >> 5, lane = tid & 31;
    int wm = (wid & 3) * 32;
    int wn = (wid >> 2) * 64;
    int head = blockIdx.x;
    int rowBase = blockIdx.y * 128;
    int colBase = head * 128;
    uint32_t smb = smem_u32(dsm);

    if (tid < 128) {
        satts[tid] = atts[head * 128 + tid];
        sattd[tid] = attd[head * 128 + tid];
    }

    float c[2][8][4];
    #pragma unroll
    for (int t = 0; t < 2; t++)
        #pragma unroll
        for (int j = 0; j < 8; j++)
            #pragma unroll
            for (int q = 0; q < 4; q++) c[t][j][q] = 0.f;

    // per-thread load geometry (2 rows per thread per array)
    int r0l = tid >> 2, c8 = tid & 3;

    auto load_tile = [&](int it, int buf) {
        uint32_t bb = smb + buf * BUF;
        #pragma unroll
        for (int i = 0; i < 2; i++) {
            int r = r0l + i * 64;
            int sw = c8 ^ (r & 3);
            uint32_t ro = (uint32_t)r * 80u + (uint32_t)sw * 16u;
            int grow = rowBase + r;
            bool p = grow < NN;
            int gcl = p ? grow : (NN - 1);
            size_t goA = (size_t)gcl * K + it * 32 + c8 * 8;
            cpa16(bb + ro,          Ah + goA, p);
            cpa16(bb + TB + ro,     Al + goA, p);
            size_t goB = (size_t)(colBase + r) * K + it * 32 + c8 * 8;
            cpa16(bb + 2 * TB + ro, Bh + goB, true);
            cpa16(bb + 3 * TB + ro, Bl + goB, true);
        }
    };

    load_tile(0, 0);
    cpa_commit();

    int lr = lane & 15, lhalf = lane >> 4;

    for (int it = 0; it < KITER; it++) {
        if (it + 1 < KITER) {
            load_tile(it + 1, (it + 1) & 1);
            cpa_commit();
            cpa_wait<1>();
        } else {
            cpa_wait<0>();
        }
        __syncthreads();

        uint32_t bb = smb + (it & 1) * BUF;
        uint32_t aBaseH = bb, aBaseL = bb + TB, bBaseH = bb + 2 * TB, bBaseL = bb + 3 * TB;

        #pragma unroll
        for (int s = 0; s < 2; s++) {
            unsigned ah[2][4], al[2][4], bh[4][4], bl[4][4];
            #pragma unroll
            for (int t = 0; t < 2; t++) {
                int row = wm + t * 16 + lr;
                uint32_t unit = (uint32_t)((s * 2 + lhalf) ^ (row & 3));
                uint32_t off = (uint32_t)row * 80u + unit * 16u;
                ldm_x4(ah[t], aBaseH + off);
                ldm_x4(al[t], aBaseL + off);
            }
            #pragma unroll
            for (int p = 0; p < 4; p++) {
                int row = wn + p * 16 + lr;
                uint32_t unit = (uint32_t)((s * 2 + lhalf) ^ (row & 3));
                uint32_t off = (uint32_t)row * 80u + unit * 16u;
                ldm_x4(bh[p], bBaseH + off);
                ldm_x4(bl[p], bBaseL + off);
            }
            #pragma unroll
            for (int t = 0; t < 2; t++) {
                #pragma unroll
                for (int j = 0; j < 8; j++) {
                    int p = j >> 1;
                    unsigned bh0 = (j & 1) ? bh[p][1] : bh[p][0];
                    unsigned bh1 = (j & 1) ? bh[p][3] : bh[p][2];
                    unsigned bl0 = (j & 1) ? bl[p][1] : bl[p][0];
                    unsigned bl1 = (j & 1) ? bl[p][3] : bl[p][2];
                    mma_bf16(c[t][j], ah[t], bh0, bh1);
                    mma_bf16(c[t][j], ah[t], bl0, bl1);
                    mma_bf16(c[t][j], al[t], bh0, bh1);
                }
            }
        }
        __syncthreads();
    }

    float* asrc_out = (LAYER == 1) ? g_asrc : g_asrc2;
    float* adst_out = (LAYER == 1) ? g_adst : g_adst2;

    #pragma unroll
    for (int t = 0; t < 2; t++) {
        int r0 = rowBase + wm + t * 16 + (lane >> 2);
        #pragma unroll
        for (int j = 0; j < 8; j++) {
            int col = colBase + wn + j * 8 + (lane & 3) * 2;
            if (r0 < NN)
                *(float2*)&g_hA[(size_t)r0 * 512 + col] = make_float2(c[t][j][0], c[t][j][1]);
            if (r0 + 8 < NN)
                *(float2*)&g_hA[(size_t)(r0 + 8) * 512 + col] = make_float2(c[t][j][2], c[t][j][3]);
        }
        float s_a = 0.f, d_a = 0.f, s_b = 0.f, d_b = 0.f;
        #pragma unroll
        for (int j = 0; j < 8; j++) {
            int cl = wn + j * 8 + (lane & 3) * 2;
            float a0 = satts[cl], a1 = satts[cl + 1];
            float e0 = sattd[cl], e1 = sattd[cl + 1];
            s_a += c[t][j][0] * a0 + c[t][j][1] * a1;
            d_a += c[t][j][0] * e0 + c[t][j][1] * e1;
            s_b += c[t][j][2] * a0 + c[t][j][3] * a1;
            d_b += c[t][j][2] * e0 + c[t][j][3] * e1;
        }
        #pragma unroll
        for (int o = 1; o <= 2; o <<= 1) {
            s_a += __shfl_xor_sync(0xffffffffu, s_a, o);
            d_a += __shfl_xor_sync(0xffffffffu, d_a, o);
            s_b += __shfl_xor_sync(0xffffffffu, s_b, o);
            d_b += __shfl_xor_sync(0xffffffffu, d_b, o);
        }
        if ((lane & 3) == 0) {
            if (r0 < NN) {
                atomicAdd(&asrc_out[r0 * 4 + head], s_a);
                atomicAdd(&adst_out[r0 * 4 + head], d_a);
            }
            if (r0 + 8 < NN) {
                atomicAdd(&asrc_out[(r0 + 8) * 4 + head], s_b);
                atomicAdd(&adst_out[(r0 + 8) * 4 + head], d_b);
            }
        }
    }
}

// ---------------- warp-per-node softmax + aggregate -------------------------
template<int LAYER>
__global__ __launch_bounds__(256) void wagg_kernel(
    const float* __restrict__ bias, const float* __restrict__ W3,
    const float* __restrict__ as3p, const float* __restrict__ ad3p)
{
    __shared__ float wbuf[8][32 * 4];
    __shared__ int   sbuf[8][32];

    const float* __restrict__ asrc_in = (LAYER == 1) ? g_asrc : g_asrc2;
    const float* __restrict__ adst_in = (LAYER == 1) ? g_adst : g_adst2;

    int w = threadIdx.x >> 5, lane = threadIdx.x & 31;
    int n = blockIdx.x * 8 + w;
    if (n >= NN) return;
    int start = g_rowoff[n];
    int deg   = g_rowoff[n + 1] - start;
    int head  = lane & 3, eslot = lane >> 2;
    float ad = adst_in[n * 4 + head];

    float mx = -1e30f;
    for (int c = 0; c < deg; c += 8) {
        int e = c + eslot;
        if (e < deg) {
            int s = g_csrc[start + e];
            mx = fmaxf(mx, leaky(asrc_in[s * 4 + head] + ad));
        }
    }
    #pragma unroll
    for (int o = 4; o < 32; o <<= 1)
        mx = fmaxf(mx, __shfl_xor_sync(0xffffffffu, mx, o));

    float ssum = 0.f;
    float4 acc[4];
    #pragma unroll
    for (int i = 0; i < 4; i++) acc[i] = make_float4(0.f, 0.f, 0.f, 0.f);
    const float4* __restrict__ hA4 = (const float4*)g_hA;

    for (int c = 0; c < deg; c += 32) {
        #pragma unroll
        for (int sp = 0; sp < 4; sp++) {
            int el = sp * 8 + eslot;
            int e = c + el;
            float wgt = 0.f;
            if (e < deg) {
                int s = g_csrc[start + e];
                if (head == 0) sbuf[w][el] = s;
                wgt = __expf(leaky(asrc_in[s * 4 + head] + ad) - mx);
            }
            wbuf[w][el * 4 + head] = wgt;
            ssum += wgt;
        }
        __syncwarp();
        int cend = min(32, deg - c);
        #pragma unroll 2
        for (int e2 = 0; e2 < cend; e2++) {
            int s = sbuf[w][e2];
            const float4* hp = hA4 + (size_t)s * 128 + lane;
            #pragma unroll
            for (int i = 0; i < 4; i++) {
                float wgt = wbuf[w][e2 * 4 + i];
                float4 v = hp[i * 32];
                acc[i].x = fmaf(wgt, v.x, acc[i].x);
                acc[i].y = fmaf(wgt, v.y, acc[i].y);
                acc[i].z = fmaf(wgt, v.z, acc[i].z);
                acc[i].w = fmaf(wgt, v.w, acc[i].w);
            }
        }
        __syncwarp();
    }
    #pragma unroll
    for (int o = 4; o < 32; o <<= 1)
        ssum += __shfl_xor_sync(0xffffffffu, ssum, o);

    float inv[4];
    #pragma unroll
    for (int i = 0; i < 4; i++)
        inv[i] = 1.f / (__shfl_sync(0xffffffffu, ssum, i) + 1e-16f);

    float p = 0.f;
    #pragma unroll
    for (int i = 0; i < 4; i++) {
        float4 b4 = ((const float4*)bias)[i * 32 + lane];
        float4 o;
        o.x = acc[i].x * inv[i] + b4.x;
        o.y = acc[i].y * inv[i] + b4.y;
        o.z = acc[i].z * inv[i] + b4.z;
        o.w = acc[i].w * inv[i] + b4.w;
        o.x = o.x > 0.f ? o.x : (__expf(o.x) - 1.f);
        o.y = o.y > 0.f ? o.y : (__expf(o.y) - 1.f);
        o.z = o.z > 0.f ? o.z : (__expf(o.z) - 1.f);
        o.w = o.w > 0.f ? o.w : (__expf(o.w) - 1.f);
        if (LAYER == 1) {
            float rx, ry, rz, rw;
            unsigned h0 = pk_hi(o.x, o.y, rx, ry);
            unsigned h1 = pk_hi(o.z, o.w, rz, rw);
            size_t go = (size_t)n * 512 + i * 128 + lane * 4;
            *(uint2*)&g_hBh[go] = make_uint2(h0, h1);
            *(uint2*)&g_hBl[go] = make_uint2(pk(rx, ry), pk(rz, rw));
        } else {
            float4 w4 = ((const float4*)W3)[i * 32 + lane];
            p += o.x * w4.x + o.y * w4.y + o.z * w4.z + o.w * w4.w;
        }
    }
    if (LAYER == 2) {
        p = warp_red_sum(p);
        if (lane == 0) {
            g_h3[n] = p;
            g_as3[n] = p * as3p[0];
            g_ad3[n] = p * ad3p[0];
        }
    }
}

// ---------------- layer-3 aggregation ---------------------------------------
__global__ __launch_bounds__(256) void agg3_kernel(
    const float* __restrict__ b3, float* __restrict__ out)
{
    int n = blockIdx.x * 8 + (threadIdx.x >> 5);
    if (n >= NN) return;
    int lane = threadIdx.x & 31;
    int start = g_rowoff[n], deg = g_rowoff[n + 1] - start;
    float ad = g_ad3[n];
    float m = -1e30f;
    for (int e = lane; e < deg; e += 32) {
        int s = g_csrc[start + e];
        m = fmaxf(m, leaky(g_as3[s] + ad));
    }
    m = warp_red_max(m);
    float sum = 0.f, acc = 0.f;
    for (int e = lane; e < deg; e += 32) {
        int s = g_csrc[start + e];
        float w = __expf(leaky(g_as3[s] + ad) - m);
        sum += w;
        acc = fmaf(w, g_h3[s], acc);
    }
    sum = warp_red_sum(sum);
    acc = warp_red_sum(acc);
    if (!lane) out[n] = acc / (sum + 1e-16f) + b3[0];
}

// ---------------- launch ----------------------------------------------------
extern "C" void kernel_launch(void* const* d_in, const int* in_sizes, int n_in,
                              void* d_out, int out_size)
{
    const float* x   = (const float*)d_in[0];
    const void*  ei  = d_in[1];
    const float* W1  = (const float*)d_in[2];
    const float* as1 = (const float*)d_in[3];
    const float* ad1 = (const float*)d_in[4];
    const float* b1  = (const float*)d_in[5];
    const float* W2  = (const float*)d_in[6];
    const float* as2 = (const float*)d_in[7];
    const float* ad2 = (const float*)d_in[8];
    const float* b2  = (const float*)d_in[9];
    const float* W3  = (const float*)d_in[10];
    const float* as3 = (const float*)d_in[11];
    const float* ad3 = (const float*)d_in[12];
    const float* b3  = (const float*)d_in[13];
    float* out = (float*)d_out;

    cudaFuncSetAttribute(mma_gemm_kernel<1>,
                         cudaFuncAttributeMaxDynamicSharedMemorySize, SM_TOTAL);
    cudaFuncSetAttribute(mma_gemm_kernel<2>,
                         cudaFuncAttributeMaxDynamicSharedMemorySize, SM_TOTAL);

    dim3 gg(4, (NN + 127) / 128);
    int prep_blocks = 256 + (NN * K1) / 256 + (FOUT * K1 + 255) / 256;

    // CSR build + prep
    detect_kernel<<<1, 32>>>((const unsigned*)ei);
    zero0_kernel<<<(NN * HEADS + 255) / 256, 256>>>();
    decode_count_kernel<<<(ET + 255) / 256, 256>>>(ei);
    scan1_kernel<<<NB, 1024>>>();
    scan2_kernel<<<1, 32>>>();
    scan3_kernel<<<NB, 1024>>>();
    scatter_kernel<<<(ET + 255) / 256, 256>>>();
    prep_kernel<<<prep_blocks, 256>>>(W1, W2, x);

    // layer 1
    mma_gemm_kernel<1><<<gg, 256, SM_TOTAL>>>(as1, ad1);
    wagg_kernel<1><<<(NN + 7) / 8, 256>>>(b1, W3, as3, ad3);

    // layer 2
    mma_gemm_kernel<2><<<gg, 256, SM_TOTAL>>>(as2, ad2);
    wagg_kernel<2><<<(NN + 7) / 8, 256>>>(b2, W3, as3, ad3);

    // layer 3
    agg3_kernel<<<(NN + 7) / 8, 256>>>(b3, out);
}

// round 7
// speedup vs baseline: 2.8686x; 1.0364x over previous
#include <cuda_runtime.h>
#include <cuda_bf16.h>
#include <cstdint>

#define NN     20000
#define FIN    50
#define HID    128
#define HEADS  4
#define FOUT   512            // HEADS*HID
#define E0     320000
#define ET     (E0 + NN)      // edges incl. self-loops = 340000
#define K1     64             // layer-1 K padded 50 -> 64
#define NB     20             // scan blocks (ceil(NN/1024))
#define RB     ((NN + 127) / 128)       // 157 row blocks
#define G1B    (4 * RB)                 // 628 GEMM1 blocks
#define DB     ((ET + 255) / 256)       // 1329 decode/scatter blocks

// ---------------- scratch (device globals; no allocation allowed) ----------
__device__ float g_hA[(size_t)NN * FOUT];            // GEMM output (fp32)
__device__ __nv_bfloat16 g_hBh[(size_t)NN * FOUT];   // agg1 output hi
__device__ __nv_bfloat16 g_hBl[(size_t)NN * FOUT];   // agg1 output lo
__device__ __nv_bfloat16 g_xh[(size_t)NN * K1];      // x split hi (padded)
__device__ __nv_bfloat16 g_xl[(size_t)NN * K1];
__device__ __nv_bfloat16 g_W1Th[(size_t)FOUT * K1];  // W1^T hi [n][k]
__device__ __nv_bfloat16 g_W1Tl[(size_t)FOUT * K1];
__device__ __nv_bfloat16 g_W2Th[(size_t)FOUT * FOUT]; // W2^T hi [n][k]
__device__ __nv_bfloat16 g_W2Tl[(size_t)FOUT * FOUT];
__device__ float g_asrc[NN * HEADS],  g_adst[NN * HEADS];    // layer-1 dots
__device__ float g_asrc2[NN * HEADS], g_adst2[NN * HEADS];   // layer-2 dots
__device__ float g_h3[NN], g_as3[NN], g_ad3[NN];
__device__ int   g_src[ET], g_dstv[ET], g_csrc[ET];
__device__ int   g_deg[NN], g_cursor[NN], g_rowoff[NN + 1];
__device__ int   g_bsum[32];
__device__ int   g_is64;

// ---------------- helpers --------------------------------------------------
__device__ __forceinline__ float warp_red_sum(float v) {
    #pragma unroll
    for (int o = 16; o; o >>= 1) v += __shfl_xor_sync(0xffffffffu, v, o);
    return v;
}
__device__ __forceinline__ float warp_red_max(float v) {
    #pragma unroll
    for (int o = 16; o; o >>= 1) v = fmaxf(v, __shfl_xor_sync(0xffffffffu, v, o));
    return v;
}
__device__ __forceinline__ float leaky(float x) { return x > 0.f ? x : 0.2f * x; }

__device__ __forceinline__ uint32_t smem_u32(const void* p) {
    uint32_t a;
    asm("{ .reg .u64 t; cvta.to.shared.u64 t, %1; cvt.u32.u64 %0, t; }" : "=r"(a) : "l"(p));
    return a;
}

__device__ __forceinline__ unsigned pk_hi(float a, float b, float& ra, float& rb) {
    __nv_bfloat16 ha = __float2bfloat16(a), hb = __float2bfloat16(b);
    ra = a - __bfloat162float(ha);
    rb = b - __bfloat162float(hb);
    return ((unsigned)__bfloat16_as_ushort(hb) << 16) | (unsigned)__bfloat16_as_ushort(ha);
}
__device__ __forceinline__ unsigned pk(float a, float b) {
    __nv_bfloat16 ha = __float2bfloat16(a), hb = __float2bfloat16(b);
    return ((unsigned)__bfloat16_as_ushort(hb) << 16) | (unsigned)__bfloat16_as_ushort(ha);
}

__device__ __forceinline__ void ldm_x4(unsigned r[4], uint32_t addr) {
    asm volatile("ldmatrix.sync.aligned.m8n8.x4.shared.b16 {%0,%1,%2,%3}, [%4];"
                 : "=r"(r[0]), "=r"(r[1]), "=r"(r[2]), "=r"(r[3]) : "r"(addr));
}
__device__ __forceinline__ void mma_bf16(float c[4], const unsigned a[4],
                                         unsigned b0, unsigned b1) {
    asm volatile(
        "mma.sync.aligned.m16n8k16.row.col.f32.bf16.bf16.f32 "
        "{%0,%1,%2,%3}, {%4,%5,%6,%7}, {%8,%9}, {%0,%1,%2,%3};"
        : "+f"(c[0]), "+f"(c[1]), "+f"(c[2]), "+f"(c[3])
        : "r"(a[0]), "r"(a[1]), "r"(a[2]), "r"(a[3]), "r"(b0), "r"(b1));
}
__device__ __forceinline__ void cpa16(uint32_t dst, const void* src, bool p) {
    int sz = p ? 16 : 0;
    asm volatile("cp.async.cg.shared.global [%0], [%1], 16, %2;"
                 :: "r"(dst), "l"(src), "r"(sz));
}
__device__ __forceinline__ void cpa_commit() {
    asm volatile("cp.async.commit_group;");
}
template<int N> __device__ __forceinline__ void cpa_wait() {
    asm volatile("cp.async.wait_group %0;" :: "n"(N));
}

// ---------------- init: detect dtype + zero accumulators --------------------
__global__ void init_kernel(const unsigned* __restrict__ w) {
    int i = blockIdx.x * blockDim.x + threadIdx.x;
    if (i == 0) {
        int is64 = 1;
        for (int q = 1; q < 64; q += 2)
            if (w[q] != 0u) { is64 = 0; break; }
        g_is64 = is64;
    }
    if (i < NN) g_deg[i] = 0;
    if (i < NN * HEADS) {
        g_asrc[i] = 0.f;  g_adst[i] = 0.f;
        g_asrc2[i] = 0.f; g_adst2[i] = 0.f;
    }
}

// ---------------- merged decode+count | W2 transpose | x split | W1 split ---
__global__ __launch_bounds__(256) void decode_prep_kernel(
    const void* __restrict__ ei, const float* __restrict__ W1,
    const float* __restrict__ W2, const float* __restrict__ x)
{
    int b = blockIdx.x, t = threadIdx.x;
    if (b < DB) {
        int e = b * 256 + t;
        if (e >= ET) return;
        int s, d;
        if (e < E0) {
            if (g_is64) {
                const long long* p = (const long long*)ei;
                s = (int)p[e]; d = (int)p[E0 + e];
            } else {
                const int* p = (const int*)ei;
                s = p[e]; d = p[E0 + e];
            }
        } else {
            s = d = e - E0;
        }
        g_src[e] = s; g_dstv[e] = d;
        atomicAdd(&g_deg[d], 1);
    } else if (b < DB + 256) {
        __shared__ float tile[32][33];
        int bb = b - DB;
        int bx = (bb & 15) * 32, by = (bb >> 4) * 32;
        int tx = t & 31, ty = t >> 5;
        #pragma unroll
        for (int i = 0; i < 32; i += 8)
            tile[ty + i][tx] = W2[(size_t)(bx + ty + i) * 512 + by + tx];
        __syncthreads();
        #pragma unroll
        for (int i = 0; i < 32; i += 8) {
            float v = tile[tx][ty + i];
            __nv_bfloat16 h = __float2bfloat16(v);
            __nv_bfloat16 l = __float2bfloat16(v - __bfloat162float(h));
            size_t o = (size_t)(by + ty + i) * 512 + bx + tx;
            g_W2Th[o] = h;
            g_W2Tl[o] = l;
        }
    } else if (b < DB + 256 + (NN * K1) / 256) {
        int idx = (b - DB - 256) * 256 + t;
        int n = idx >> 6, k = idx & 63;
        float v = (k < FIN) ? x[n * FIN + k] : 0.f;
        __nv_bfloat16 h = __float2bfloat16(v);
        g_xh[idx] = h;
        g_xl[idx] = __float2bfloat16(v - __bfloat162float(h));
    } else {
        int idx = (b - DB - 256 - (NN * K1) / 256) * 256 + t;
        if (idx < FOUT * K1) {
            int n = idx >> 6, k = idx & 63;
            float v = (k < FIN) ? W1[(size_t)k * 512 + n] : 0.f;
            __nv_bfloat16 h = __float2bfloat16(v);
            g_W1Th[idx] = h;
            g_W1Tl[idx] = __float2bfloat16(v - __bfloat162float(h));
        }
    }
}

// ---------------- multi-block scan (3 tiny kernels) -------------------------
__global__ __launch_bounds__(1024) void scan1_kernel() {
    __shared__ int wsum[32];
    int b = blockIdx.x, t = threadIdx.x, lane = t & 31, w = t >> 5;
    int i = b * 1024 + t;
    int v = (i < NN) ? g_deg[i] : 0;
    int x = v;
    #pragma unroll
    for (int o = 1; o < 32; o <<= 1) {
        int y = __shfl_up_sync(0xffffffffu, x, o);
        if (lane >= o) x += y;
    }
    if (lane == 31) wsum[w] = x;
    __syncthreads();
    if (w == 0) {
        int y = wsum[lane];
        #pragma unroll
        for (int o = 1; o < 32; o <<= 1) {
            int z = __shfl_up_sync(0xffffffffu, y, o);
            if (lane >= o) y += z;
        }
        wsum[lane] = y;
    }
    __syncthreads();
    int incl = x + (w ? wsum[w - 1] : 0);
    if (i < NN) {
        g_rowoff[i + 1] = incl;
        g_cursor[i]     = incl - v;
    }
    if (t == 1023) g_bsum[b] = incl;
}

__global__ void scan2_kernel() {
    int lane = threadIdx.x;
    int v = (lane < NB) ? g_bsum[lane] : 0;
    int x = v;
    #pragma unroll
    for (int o = 1; o < 32; o <<= 1) {
        int y = __shfl_up_sync(0xffffffffu, x, o);
        if (lane >= o) x += y;
    }
    if (lane < NB) g_bsum[lane] = x - v;   // exclusive
}

__global__ __launch_bounds__(1024) void scan3_kernel() {
    int b = blockIdx.x, t = threadIdx.x;
    int i = b * 1024 + t;
    int off = g_bsum[b];
    if (i < NN) {
        g_rowoff[i + 1] += off;
        g_cursor[i]     += off;
    }
    if (b == 0 && t == 0) g_rowoff[0] = 0;
}

// ---------------- GEMM body (shared by both layers) -------------------------
#define TB   10240                 // one tile array
#define BUF  (4 * TB)              // one buffer = 40960
#define SM_ATT (2 * BUF)           // 81920
#define SM_TOTAL (SM_ATT + 1024)

template<int LAYER>
__device__ __forceinline__ void gemm_body(
    int head, int rowb, char* dsm,
    const float* __restrict__ atts, const float* __restrict__ attd)
{
    constexpr int K = (LAYER == 1) ? K1 : FOUT;
    constexpr int KITER = K / 32;

    float* satts = (float*)(dsm + SM_ATT);
    float* sattd = satts + 128;

    const __nv_bfloat16* __restrict__ Ah = (LAYER == 1) ? g_xh : g_hBh;
    const __nv_bfloat16* __restrict__ Al = (LAYER == 1) ? g_xl : g_hBl;
    const __nv_bfloat16* __restrict__ Bh = (LAYER == 1) ? g_W1Th : g_W2Th;
    const __nv_bfloat16* __restrict__ Bl = (LAYER == 1) ? g_W1Tl : g_W2Tl;

    int tid = threadIdx.x;
    int wid = tid >> 5, lane = tid & 31;
    int wm = (wid & 3) * 32;
    int wn = (wid >> 2) * 64;
    int rowBase = rowb * 128;
    int colBase = head * 128;
    uint32_t smb = smem_u32(dsm);

    if (tid < 128) {
        satts[tid] = atts[head * 128 + tid];
        sattd[tid] = attd[head * 128 + tid];
    }

    float c[2][8][4];
    #pragma unroll
    for (int t = 0; t < 2; t++)
        #pragma unroll
        for (int j = 0; j < 8; j++)
            #pragma unroll
            for (int q = 0; q < 4; q++) c[t][j][q] = 0.f;

    int r0l = tid >> 2, c8 = tid & 3;

    auto load_tile = [&](int it, int buf) {
        uint32_t bb = smb + buf * BUF;
        #pragma unroll
        for (int i = 0; i < 2; i++) {
            int r = r0l + i * 64;
            int sw = c8 ^ (r & 3);
            uint32_t ro = (uint32_t)r * 80u + (uint32_t)sw * 16u;
            int grow = rowBase + r;
            bool p = grow < NN;
            int gcl = p ? grow : (NN - 1);
            size_t goA = (size_t)gcl * K + it * 32 + c8 * 8;
            cpa16(bb + ro,          Ah + goA, p);
            cpa16(bb + TB + ro,     Al + goA, p);
            size_t goB = (size_t)(colBase + r) * K + it * 32 + c8 * 8;
            cpa16(bb + 2 * TB + ro, Bh + goB, true);
            cpa16(bb + 3 * TB + ro, Bl + goB, true);
        }
    };

    load_tile(0, 0);
    cpa_commit();

    int lr = lane & 15, lhalf = lane >> 4;

    for (int it = 0; it < KITER; it++) {
        if (it + 1 < KITER) {
            load_tile(it + 1, (it + 1) & 1);
            cpa_commit();
            cpa_wait<1>();
        } else {
            cpa_wait<0>();
        }
        __syncthreads();

        uint32_t bb = smb + (it & 1) * BUF;
        uint32_t aBaseH = bb, aBaseL = bb + TB, bBaseH = bb + 2 * TB, bBaseL = bb + 3 * TB;

        #pragma unroll
        for (int s = 0; s < 2; s++) {
            unsigned ah[2][4], al[2][4], bh[4][4], bl[4][4];
            #pragma unroll
            for (int t = 0; t < 2; t++) {
                int row = wm + t * 16 + lr;
                uint32_t unit = (uint32_t)((s * 2 + lhalf) ^ (row & 3));
                uint32_t off = (uint32_t)row * 80u + unit * 16u;
                ldm_x4(ah[t], aBaseH + off);
                ldm_x4(al[t], aBaseL + off);
            }
            #pragma unroll
            for (int p = 0; p < 4; p++) {
                int row = wn + p * 16 + lr;
                uint32_t unit = (uint32_t)((s * 2 + lhalf) ^ (row & 3));
                uint32_t off = (uint32_t)row * 80u + unit * 16u;
                ldm_x4(bh[p], bBaseH + off);
                ldm_x4(bl[p], bBaseL + off);
            }
            #pragma unroll
            for (int t = 0; t < 2; t++) {
                #pragma unroll
                for (int j = 0; j < 8; j++) {
                    int p = j >> 1;
                    unsigned bh0 = (j & 1) ? bh[p][1] : bh[p][0];
                    unsigned bh1 = (j & 1) ? bh[p][3] : bh[p][2];
                    unsigned bl0 = (j & 1) ? bl[p][1] : bl[p][0];
                    unsigned bl1 = (j & 1) ? bl[p][3] : bl[p][2];
                    mma_bf16(c[t][j], ah[t], bh0, bh1);
                    mma_bf16(c[t][j], ah[t], bl0, bl1);
                    mma_bf16(c[t][j], al[t], bh0, bh1);
                }
            }
        }
        __syncthreads();
    }

    float* asrc_out = (LAYER == 1) ? g_asrc : g_asrc2;
    float* adst_out = (LAYER == 1) ? g_adst : g_adst2;

    #pragma unroll
    for (int t = 0; t < 2; t++) {
        int r0 = rowBase + wm + t * 16 + (lane >> 2);
        #pragma unroll
        for (int j = 0; j < 8; j++) {
            int col = colBase + wn + j * 8 + (lane & 3) * 2;
            if (r0 < NN)
                *(float2*)&g_hA[(size_t)r0 * 512 + col] = make_float2(c[t][j][0], c[t][j][1]);
            if (r0 + 8 < NN)
                *(float2*)&g_hA[(size_t)(r0 + 8) * 512 + col] = make_float2(c[t][j][2], c[t][j][3]);
        }
        float s_a = 0.f, d_a = 0.f, s_b = 0.f, d_b = 0.f;
        #pragma unroll
        for (int j = 0; j < 8; j++) {
            int cl = wn + j * 8 + (lane & 3) * 2;
            float a0 = satts[cl], a1 = satts[cl + 1];
            float e0 = sattd[cl], e1 = sattd[cl + 1];
            s_a += c[t][j][0] * a0 + c[t][j][1] * a1;
            d_a += c[t][j][0] * e0 + c[t][j][1] * e1;
            s_b += c[t][j][2] * a0 + c[t][j][3] * a1;
            d_b += c[t][j][2] * e0 + c[t][j][3] * e1;
        }
        #pragma unroll
        for (int o = 1; o <= 2; o <<= 1) {
            s_a += __shfl_xor_sync(0xffffffffu, s_a, o);
            d_a += __shfl_xor_sync(0xffffffffu, d_a, o);
            s_b += __shfl_xor_sync(0xffffffffu, s_b, o);
            d_b += __shfl_xor_sync(0xffffffffu, d_b, o);
        }
        if ((lane & 3) == 0) {
            if (r0 < NN) {
                atomicAdd(&asrc_out[r0 * 4 + head], s_a);
                atomicAdd(&adst_out[r0 * 4 + head], d_a);
            }
            if (r0 + 8 < NN) {
                atomicAdd(&adst_out[(r0 + 8) * 4 + head], d_b);
                atomicAdd(&asrc_out[(r0 + 8) * 4 + head], s_b);
            }
        }
    }
}

// ---------------- GEMM1 + scatter merged ------------------------------------
__global__ __launch_bounds__(256) void gemm1_scatter_kernel(
    const float* __restrict__ as1, const float* __restrict__ ad1)
{
    if (blockIdx.x < G1B) {
        extern __shared__ char dsm[];
        gemm_body<1>(blockIdx.x & 3, blockIdx.x >> 2, dsm, as1, ad1);
    } else {
        int e = (blockIdx.x - G1B) * 256 + threadIdx.x;
        if (e < ET) {
            int d = g_dstv[e];
            int pos = atomicAdd(&g_cursor[d], 1);
            g_csrc[pos] = g_src[e];
        }
    }
}

// ---------------- GEMM2 standalone ------------------------------------------
__global__ __launch_bounds__(256) void gemm2_kernel(
    const float* __restrict__ as2, const float* __restrict__ ad2)
{
    extern __shared__ char dsm[];
    gemm_body<2>(blockIdx.x & 3, blockIdx.x >> 2, dsm, as2, ad2);
}

// ---------------- warp-per-node softmax + aggregate -------------------------
template<int LAYER>
__global__ __launch_bounds__(256) void wagg_kernel(
    const float* __restrict__ bias, const float* __restrict__ W3,
    const float* __restrict__ as3p, const float* __restrict__ ad3p)
{
    __shared__ float wbuf[8][32 * 4];
    __shared__ int   sbuf[8][32];

    const float* __restrict__ asrc_in = (LAYER == 1) ? g_asrc : g_asrc2;
    const float* __restrict__ adst_in = (LAYER == 1) ? g_adst : g_adst2;

    int w = threadIdx.x >> 5, lane = threadIdx.x & 31;
    int n = blockIdx.x * 8 + w;
    if (n >= NN) return;
    int start = g_rowoff[n];
    int deg   = g_rowoff[n + 1] - start;
    int head  = lane & 3, eslot = lane >> 2;
    float ad = adst_in[n * 4 + head];

    float mx = -1e30f;
    for (int c = 0; c < deg; c += 8) {
        int e = c + eslot;
        if (e < deg) {
            int s = g_csrc[start + e];
            mx = fmaxf(mx, leaky(asrc_in[s * 4 + head] + ad));
        }
    }
    #pragma unroll
    for (int o = 4; o < 32; o <<= 1)
        mx = fmaxf(mx, __shfl_xor_sync(0xffffffffu, mx, o));

    float ssum = 0.f;
    float4 acc[4];
    #pragma unroll
    for (int i = 0; i < 4; i++) acc[i] = make_float4(0.f, 0.f, 0.f, 0.f);
    const float4* __restrict__ hA4 = (const float4*)g_hA;

    for (int c = 0; c < deg; c += 32) {
        #pragma unroll
        for (int sp = 0; sp < 4; sp++) {
            int el = sp * 8 + eslot;
            int e = c + el;
            float wgt = 0.f;
            if (e < deg) {
                int s = g_csrc[start + e];
                if (head == 0) sbuf[w][el] = s;
                wgt = __expf(leaky(asrc_in[s * 4 + head] + ad) - mx);
            }
            wbuf[w][el * 4 + head] = wgt;
            ssum += wgt;
        }
        __syncwarp();
        int cend = min(32, deg - c);
        #pragma unroll 4
        for (int e2 = 0; e2 < cend; e2++) {
            int s = sbuf[w][e2];
            const float4* hp = hA4 + (size_t)s * 128 + lane;
            #pragma unroll
            for (int i = 0; i < 4; i++) {
                float wgt = wbuf[w][e2 * 4 + i];
                float4 v = hp[i * 32];
                acc[i].x = fmaf(wgt, v.x, acc[i].x);
                acc[i].y = fmaf(wgt, v.y, acc[i].y);
                acc[i].z = fmaf(wgt, v.z, acc[i].z);
                acc[i].w = fmaf(wgt, v.w, acc[i].w);
            }
        }
        __syncwarp();
    }
    #pragma unroll
    for (int o = 4; o < 32; o <<= 1)
        ssum += __shfl_xor_sync(0xffffffffu, ssum, o);

    float inv[4];
    #pragma unroll
    for (int i = 0; i < 4; i++)
        inv[i] = 1.f / (__shfl_sync(0xffffffffu, ssum, i) + 1e-16f);

    float p = 0.f;
    #pragma unroll
    for (int i = 0; i < 4; i++) {
        float4 b4 = ((const float4*)bias)[i * 32 + lane];
        float4 o;
        o.x = acc[i].x * inv[i] + b4.x;
        o.y = acc[i].y * inv[i] + b4.y;
        o.z = acc[i].z * inv[i] + b4.z;
        o.w = acc[i].w * inv[i] + b4.w;
        o.x = o.x > 0.f ? o.x : (__expf(o.x) - 1.f);
        o.y = o.y > 0.f ? o.y : (__expf(o.y) - 1.f);
        o.z = o.z > 0.f ? o.z : (__expf(o.z) - 1.f);
        o.w = o.w > 0.f ? o.w : (__expf(o.w) - 1.f);
        if (LAYER == 1) {
            float rx, ry, rz, rw;
            unsigned h0 = pk_hi(o.x, o.y, rx, ry);
            unsigned h1 = pk_hi(o.z, o.w, rz, rw);
            size_t go = (size_t)n * 512 + i * 128 + lane * 4;
            *(uint2*)&g_hBh[go] = make_uint2(h0, h1);
            *(uint2*)&g_hBl[go] = make_uint2(pk(rx, ry), pk(rz, rw));
        } else {
            float4 w4 = ((const float4*)W3)[i * 32 + lane];
            p += o.x * w4.x + o.y * w4.y + o.z * w4.z + o.w * w4.w;
        }
    }
    if (LAYER == 2) {
        p = warp_red_sum(p);
        if (lane == 0) {
            g_h3[n] = p;
            g_as3[n] = p * as3p[0];
            g_ad3[n] = p * ad3p[0];
        }
    }
}

// ---------------- layer-3 aggregation ---------------------------------------
__global__ __launch_bounds__(256) void agg3_kernel(
    const float* __restrict__ b3, float* __restrict__ out)
{
    int n = blockIdx.x * 8 + (threadIdx.x >> 5);
    if (n >= NN) return;
    int lane = threadIdx.x & 31;
    int start = g_rowoff[n], deg = g_rowoff[n + 1] - start;
    float ad = g_ad3[n];
    float m = -1e30f;
    for (int e = lane; e < deg; e += 32) {
        int s = g_csrc[start + e];
        m = fmaxf(m, leaky(g_as3[s] + ad));
    }
    m = warp_red_max(m);
    float sum = 0.f, acc = 0.f;
    for (int e = lane; e < deg; e += 32) {
        int s = g_csrc[start + e];
        float w = __expf(leaky(g_as3[s] + ad) - m);
        sum += w;
        acc = fmaf(w, g_h3[s], acc);
    }
    sum = warp_red_sum(sum);
    acc = warp_red_sum(acc);
    if (!lane) out[n] = acc / (sum + 1e-16f) + b3[0];
}

// ---------------- launch ----------------------------------------------------
extern "C" void kernel_launch(void* const* d_in, const int* in_sizes, int n_in,
                              void* d_out, int out_size)
{
    const float* x   = (const float*)d_in[0];
    const void*  ei  = d_in[1];
    const float* W1  = (const float*)d_in[2];
    const float* as1 = (const float*)d_in[3];
    const float* ad1 = (const float*)d_in[4];
    const float* b1  = (const float*)d_in[5];
    const float* W2  = (const float*)d_in[6];
    const float* as2 = (const float*)d_in[7];
    const float* ad2 = (const float*)d_in[8];
    const float* b2  = (const float*)d_in[9];
    const float* W3  = (const float*)d_in[10];
    const float* as3 = (const float*)d_in[11];
    const float* ad3 = (const float*)d_in[12];
    const float* b3  = (const float*)d_in[13];
    float* out = (float*)d_out;

    cudaFuncSetAttribute(gemm1_scatter_kernel,
                         cudaFuncAttributeMaxDynamicSharedMemorySize, SM_TOTAL);
    cudaFuncSetAttribute(gemm2_kernel,
                         cudaFuncAttributeMaxDynamicSharedMemorySize, SM_TOTAL);

    int prep_blocks = DB + 256 + (NN * K1) / 256 + (FOUT * K1 + 255) / 256;

    // 0: init (dtype detect + zero)
    init_kernel<<<(NN * HEADS + 255) / 256, 256>>>((const unsigned*)ei);
    // 1: decode+count | weight/x prep
    decode_prep_kernel<<<prep_blocks, 256>>>(ei, W1, W2, x);
    // 2-4: degree scan
    scan1_kernel<<<NB, 1024>>>();
    scan2_kernel<<<1, 32>>>();
    scan3_kernel<<<NB, 1024>>>();
    // 5: GEMM1 (+dots) overlapped with CSR scatter
    gemm1_scatter_kernel<<<G1B + DB, 256, SM_TOTAL>>>(as1, ad1);
    // 6: layer-1 softmax-aggregate
    wagg_kernel<1><<<(NN + 7) / 8, 256>>>(b1, W3, as3, ad3);
    // 7: GEMM2 (+dots)
    gemm2_kernel<<<G1B, 256, SM_TOTAL>>>(as2, ad2);
    // 8: layer-2 softmax-aggregate + fused W3 GEMV
    wagg_kernel<2><<<(NN + 7) / 8, 256>>>(b2, W3, as3, ad3);
    // 9: layer-3 scalar attention
    agg3_kernel<<<(NN + 7) / 8, 256>>>(b3, out);
}

// round 8
// speedup vs baseline: 2.9037x; 1.0123x over previous
#include <cuda_runtime.h>
#include <cuda_bf16.h>
#include <cstdint>

#define NN     20000
#define FIN    50
#define HID    128
#define HEADS  4
#define FOUT   512            // HEADS*HID
#define E0     320000
#define ET     (E0 + NN)      // edges incl. self-loops = 340000
#define K1     64             // layer-1 K padded 50 -> 64
#define NB     20             // scan blocks (ceil(NN/1024))
#define RB     ((NN + 127) / 128)       // 157 row blocks
#define G1B    (4 * RB)                 // 628 GEMM blocks
#define DB     ((ET + 255) / 256)       // 1329 decode/scatter blocks

// ---------------- scratch (device globals; no allocation allowed) ----------
__device__ float g_hA[(size_t)NN * FOUT];            // GEMM output (fp32)
__device__ __nv_bfloat16 g_hBh[(size_t)NN * FOUT];   // agg1 output hi
__device__ __nv_bfloat16 g_hBl[(size_t)NN * FOUT];   // agg1 output lo
__device__ __nv_bfloat16 g_xh[(size_t)NN * K1];      // x split hi (padded)
__device__ __nv_bfloat16 g_xl[(size_t)NN * K1];
__device__ __nv_bfloat16 g_W1Th[(size_t)FOUT * K1];  // W1^T hi [n][k]
__device__ __nv_bfloat16 g_W1Tl[(size_t)FOUT * K1];
__device__ __nv_bfloat16 g_W2Th[(size_t)FOUT * FOUT]; // W2^T hi [n][k]
__device__ __nv_bfloat16 g_W2Tl[(size_t)FOUT * FOUT];
__device__ float g_asrc[NN * HEADS],  g_adst[NN * HEADS];    // layer-1 dots
__device__ float g_asrc2[NN * HEADS], g_adst2[NN * HEADS];   // layer-2 dots
__device__ float g_h3[NN], g_as3[NN], g_ad3[NN];
__device__ int   g_src[ET], g_dstv[ET], g_csrc[ET];
__device__ int   g_deg[NN], g_cursor[NN], g_rowoff[NN + 1];
__device__ int   g_bsum[32], g_boff[32];
__device__ int   g_ctr, g_flag;
__device__ int   g_is64;

// ---------------- helpers --------------------------------------------------
__device__ __forceinline__ float warp_red_sum(float v) {
    #pragma unroll
    for (int o = 16; o; o >>= 1) v += __shfl_xor_sync(0xffffffffu, v, o);
    return v;
}
__device__ __forceinline__ float warp_red_max(float v) {
    #pragma unroll
    for (int o = 16; o; o >>= 1) v = fmaxf(v, __shfl_xor_sync(0xffffffffu, v, o));
    return v;
}
__device__ __forceinline__ float leaky(float x) { return x > 0.f ? x : 0.2f * x; }

__device__ __forceinline__ uint32_t smem_u32(const void* p) {
    uint32_t a;
    asm("{ .reg .u64 t; cvta.to.shared.u64 t, %1; cvt.u32.u64 %0, t; }" : "=r"(a) : "l"(p));
    return a;
}

__device__ __forceinline__ unsigned pk_hi(float a, float b, float& ra, float& rb) {
    __nv_bfloat16 ha = __float2bfloat16(a), hb = __float2bfloat16(b);
    ra = a - __bfloat162float(ha);
    rb = b - __bfloat162float(hb);
    return ((unsigned)__bfloat16_as_ushort(hb) << 16) | (unsigned)__bfloat16_as_ushort(ha);
}
__device__ __forceinline__ unsigned pk(float a, float b) {
    __nv_bfloat16 ha = __float2bfloat16(a), hb = __float2bfloat16(b);
    return ((unsigned)__bfloat16_as_ushort(hb) << 16) | (unsigned)__bfloat16_as_ushort(ha);
}

__device__ __forceinline__ void ldm_x4(unsigned r[4], uint32_t addr) {
    asm volatile("ldmatrix.sync.aligned.m8n8.x4.shared.b16 {%0,%1,%2,%3}, [%4];"
                 : "=r"(r[0]), "=r"(r[1]), "=r"(r[2]), "=r"(r[3]) : "r"(addr));
}
__device__ __forceinline__ void mma_bf16(float c[4], const unsigned a[4],
                                         unsigned b0, unsigned b1) {
    asm volatile(
        "mma.sync.aligned.m16n8k16.row.col.f32.bf16.bf16.f32 "
        "{%0,%1,%2,%3}, {%4,%5,%6,%7}, {%8,%9}, {%0,%1,%2,%3};"
        : "+f"(c[0]), "+f"(c[1]), "+f"(c[2]), "+f"(c[3])
        : "r"(a[0]), "r"(a[1]), "r"(a[2]), "r"(a[3]), "r"(b0), "r"(b1));
}
__device__ __forceinline__ void cpa16(uint32_t dst, const void* src, bool p) {
    int sz = p ? 16 : 0;
    asm volatile("cp.async.cg.shared.global [%0], [%1], 16, %2;"
                 :: "r"(dst), "l"(src), "r"(sz));
}
__device__ __forceinline__ void cpa_commit() {
    asm volatile("cp.async.commit_group;");
}
template<int N> __device__ __forceinline__ void cpa_wait() {
    asm volatile("cp.async.wait_group %0;" :: "n"(N));
}

// ---------------- init: detect dtype + zero accumulators --------------------
__global__ void init_kernel(const unsigned* __restrict__ w) {
    int i = blockIdx.x * blockDim.x + threadIdx.x;
    if (i == 0) {
        int is64 = 1;
        for (int q = 1; q < 64; q += 2)
            if (w[q] != 0u) { is64 = 0; break; }
        g_is64 = is64;
        g_ctr = 0;
        g_flag = 0;
    }
    if (i < NN) g_deg[i] = 0;
    if (i < NN * HEADS) {
        g_asrc[i] = 0.f;  g_adst[i] = 0.f;
        g_asrc2[i] = 0.f; g_adst2[i] = 0.f;
    }
}

// ---------------- merged decode+count | W2 transpose | x split | W1 split ---
__global__ __launch_bounds__(256) void decode_prep_kernel(
    const void* __restrict__ ei, const float* __restrict__ W1,
    const float* __restrict__ W2, const float* __restrict__ x)
{
    int b = blockIdx.x, t = threadIdx.x;
    if (b < DB) {
        int e = b * 256 + t;
        if (e >= ET) return;
        int s, d;
        if (e < E0) {
            if (g_is64) {
                const long long* p = (const long long*)ei;
                s = (int)p[e]; d = (int)p[E0 + e];
            } else {
                const int* p = (const int*)ei;
                s = p[e]; d = p[E0 + e];
            }
        } else {
            s = d = e - E0;
        }
        g_src[e] = s; g_dstv[e] = d;
        atomicAdd(&g_deg[d], 1);
    } else if (b < DB + 256) {
        __shared__ float tile[32][33];
        int bb = b - DB;
        int bx = (bb & 15) * 32, by = (bb >> 4) * 32;
        int tx = t & 31, ty = t >> 5;
        #pragma unroll
        for (int i = 0; i < 32; i += 8)
            tile[ty + i][tx] = W2[(size_t)(bx + ty + i) * 512 + by + tx];
        __syncthreads();
        #pragma unroll
        for (int i = 0; i < 32; i += 8) {
            float v = tile[tx][ty + i];
            __nv_bfloat16 h = __float2bfloat16(v);
            __nv_bfloat16 l = __float2bfloat16(v - __bfloat162float(h));
            size_t o = (size_t)(by + ty + i) * 512 + bx + tx;
            g_W2Th[o] = h;
            g_W2Tl[o] = l;
        }
    } else if (b < DB + 256 + (NN * K1) / 256) {
        int idx = (b - DB - 256) * 256 + t;
        int n = idx >> 6, k = idx & 63;
        float v = (k < FIN) ? x[n * FIN + k] : 0.f;
        __nv_bfloat16 h = __float2bfloat16(v);
        g_xh[idx] = h;
        g_xl[idx] = __float2bfloat16(v - __bfloat162float(h));
    } else {
        int idx = (b - DB - 256 - (NN * K1) / 256) * 256 + t;
        if (idx < FOUT * K1) {
            int n = idx >> 6, k = idx & 63;
            float v = (k < FIN) ? W1[(size_t)k * 512 + n] : 0.f;
            __nv_bfloat16 h = __float2bfloat16(v);
            g_W1Th[idx] = h;
            g_W1Tl[idx] = __float2bfloat16(v - __bfloat162float(h));
        }
    }
}

// ---------------- fused multi-block scan (one kernel, device flag sync) -----
// 20 blocks, all guaranteed co-resident (nothing else running).
__global__ __launch_bounds__(1024) void scan_kernel() {
    __shared__ int wsum[32];
    int b = blockIdx.x, t = threadIdx.x, lane = t & 31, w = t >> 5;
    int i = b * 1024 + t;
    int v = (i < NN) ? g_deg[i] : 0;
    int x = v;
    #pragma unroll
    for (int o = 1; o < 32; o <<= 1) {
        int y = __shfl_up_sync(0xffffffffu, x, o);
        if (lane >= o) x += y;
    }
    if (lane == 31) wsum[w] = x;
    __syncthreads();
    if (w == 0) {
        int y = wsum[lane];
        #pragma unroll
        for (int o = 1; o < 32; o <<= 1) {
            int z = __shfl_up_sync(0xffffffffu, y, o);
            if (lane >= o) y += z;
        }
        wsum[lane] = y;
    }
    __syncthreads();
    int incl = x + (w ? wsum[w - 1] : 0);
    int excl_local = incl - v;
    if (t == 1023) g_bsum[b] = incl;
    __threadfence();
    __syncthreads();

    // grid sync: last block to arrive computes block-offset prefix
    if (t == 0) {
        int arrived = atomicAdd(&g_ctr, 1);
        if (arrived == NB - 1) {
            int acc = 0;
            #pragma unroll
            for (int q = 0; q < NB; q++) { g_boff[q] = acc; acc += g_bsum[q]; }
            __threadfence();
            atomicExch(&g_flag, 1);
        }
        while (atomicAdd(&g_flag, 0) == 0) {}
    }
    __syncthreads();

    int off = g_boff[b];
    if (i < NN) {
        g_rowoff[i + 1] = off + incl;
        g_cursor[i]     = off + excl_local;
    }
    if (b == 0 && t == 0) g_rowoff[0] = 0;
}

// ---------------- GEMM body (shared by both layers) -------------------------
#define TB   10240                 // one tile array
#define BUF  (4 * TB)              // one buffer = 40960
#define SM_ATT (2 * BUF)           // 81920
#define SM_TOTAL (SM_ATT + 1024)

template<int LAYER>
__device__ __forceinline__ void gemm_body(
    int head, int rowb, char* dsm,
    const float* __restrict__ atts, const float* __restrict__ attd)
{
    constexpr int K = (LAYER == 1) ? K1 : FOUT;
    constexpr int KITER = K / 32;

    float* satts = (float*)(dsm + SM_ATT);
    float* sattd = satts + 128;

    const __nv_bfloat16* __restrict__ Ah = (LAYER == 1) ? g_xh : g_hBh;
    const __nv_bfloat16* __restrict__ Al = (LAYER == 1) ? g_xl : g_hBl;
    const __nv_bfloat16* __restrict__ Bh = (LAYER == 1) ? g_W1Th : g_W2Th;
    const __nv_bfloat16* __restrict__ Bl = (LAYER == 1) ? g_W1Tl : g_W2Tl;

    int tid = threadIdx.x;
    int wid = tid >> 5, lane = tid & 31;
    int wm = (wid & 3) * 32;
    int wn = (wid >> 2) * 64;
    int rowBase = rowb * 128;
    int colBase = head * 128;
    uint32_t smb = smem_u32(dsm);

    if (tid < 128) {
        satts[tid] = atts[head * 128 + tid];
        sattd[tid] = attd[head * 128 + tid];
    }

    float c[2][8][4];
    #pragma unroll
    for (int t = 0; t < 2; t++)
        #pragma unroll
        for (int j = 0; j < 8; j++)
            #pragma unroll
            for (int q = 0; q < 4; q++) c[t][j][q] = 0.f;

    int r0l = tid >> 2, c8 = tid & 3;

    auto load_tile = [&](int it, int buf) {
        uint32_t bb = smb + buf * BUF;
        #pragma unroll
        for (int i = 0; i < 2; i++) {
            int r = r0l + i * 64;
            int sw = c8 ^ (r & 3);
            uint32_t ro = (uint32_t)r * 80u + (uint32_t)sw * 16u;
            int grow = rowBase + r;
            bool p = grow < NN;
            int gcl = p ? grow : (NN - 1);
            size_t goA = (size_t)gcl * K + it * 32 + c8 * 8;
            cpa16(bb + ro,          Ah + goA, p);
            cpa16(bb + TB + ro,     Al + goA, p);
            size_t goB = (size_t)(colBase + r) * K + it * 32 + c8 * 8;
            cpa16(bb + 2 * TB + ro, Bh + goB, true);
            cpa16(bb + 3 * TB + ro, Bl + goB, true);
        }
    };

    load_tile(0, 0);
    cpa_commit();

    int lr = lane & 15, lhalf = lane >> 4;

    for (int it = 0; it < KITER; it++) {
        if (it + 1 < KITER) {
            load_tile(it + 1, (it + 1) & 1);
            cpa_commit();
            cpa_wait<1>();
        } else {
            cpa_wait<0>();
        }
        __syncthreads();

        uint32_t bb = smb + (it & 1) * BUF;
        uint32_t aBaseH = bb, aBaseL = bb + TB, bBaseH = bb + 2 * TB, bBaseL = bb + 3 * TB;

        #pragma unroll
        for (int s = 0; s < 2; s++) {
            unsigned ah[2][4], al[2][4], bh[4][4], bl[4][4];
            #pragma unroll
            for (int t = 0; t < 2; t++) {
                int row = wm + t * 16 + lr;
                uint32_t unit = (uint32_t)((s * 2 + lhalf) ^ (row & 3));
                uint32_t off = (uint32_t)row * 80u + unit * 16u;
                ldm_x4(ah[t], aBaseH + off);
                ldm_x4(al[t], aBaseL + off);
            }
            #pragma unroll
            for (int p = 0; p < 4; p++) {
                int row = wn + p * 16 + lr;
                uint32_t unit = (uint32_t)((s * 2 + lhalf) ^ (row & 3));
                uint32_t off = (uint32_t)row * 80u + unit * 16u;
                ldm_x4(bh[p], bBaseH + off);
                ldm_x4(bl[p], bBaseL + off);
            }
            #pragma unroll
            for (int t = 0; t < 2; t++) {
                #pragma unroll
                for (int j = 0; j < 8; j++) {
                    int p = j >> 1;
                    unsigned bh0 = (j & 1) ? bh[p][1] : bh[p][0];
                    unsigned bh1 = (j & 1) ? bh[p][3] : bh[p][2];
                    unsigned bl0 = (j & 1) ? bl[p][1] : bl[p][0];
                    unsigned bl1 = (j & 1) ? bl[p][3] : bl[p][2];
                    mma_bf16(c[t][j], ah[t], bh0, bh1);
                    mma_bf16(c[t][j], ah[t], bl0, bl1);
                    mma_bf16(c[t][j], al[t], bh0, bh1);
                }
            }
        }
        __syncthreads();
    }

    float* asrc_out = (LAYER == 1) ? g_asrc : g_asrc2;
    float* adst_out = (LAYER == 1) ? g_adst : g_adst2;

    #pragma unroll
    for (int t = 0; t < 2; t++) {
        int r0 = rowBase + wm + t * 16 + (lane >> 2);
        #pragma unroll
        for (int j = 0; j < 8; j++) {
            int col = colBase + wn + j * 8 + (lane & 3) * 2;
            if (r0 < NN)
                *(float2*)&g_hA[(size_t)r0 * 512 + col] = make_float2(c[t][j][0], c[t][j][1]);
            if (r0 + 8 < NN)
                *(float2*)&g_hA[(size_t)(r0 + 8) * 512 + col] = make_float2(c[t][j][2], c[t][j][3]);
        }
        float s_a = 0.f, d_a = 0.f, s_b = 0.f, d_b = 0.f;
        #pragma unroll
        for (int j = 0; j < 8; j++) {
            int cl = wn + j * 8 + (lane & 3) * 2;
            float a0 = satts[cl], a1 = satts[cl + 1];
            float e0 = sattd[cl], e1 = sattd[cl + 1];
            s_a += c[t][j][0] * a0 + c[t][j][1] * a1;
            d_a += c[t][j][0] * e0 + c[t][j][1] * e1;
            s_b += c[t][j][2] * a0 + c[t][j][3] * a1;
            d_b += c[t][j][2] * e0 + c[t][j][3] * e1;
        }
        #pragma unroll
        for (int o = 1; o <= 2; o <<= 1) {
            s_a += __shfl_xor_sync(0xffffffffu, s_a, o);
            d_a += __shfl_xor_sync(0xffffffffu, d_a, o);
            s_b += __shfl_xor_sync(0xffffffffu, s_b, o);
            d_b += __shfl_xor_sync(0xffffffffu, d_b, o);
        }
        if ((lane & 3) == 0) {
            if (r0 < NN) {
                atomicAdd(&asrc_out[r0 * 4 + head], s_a);
                atomicAdd(&adst_out[r0 * 4 + head], d_a);
            }
            if (r0 + 8 < NN) {
                atomicAdd(&asrc_out[(r0 + 8) * 4 + head], s_b);
                atomicAdd(&adst_out[(r0 + 8) * 4 + head], d_b);
            }
        }
    }
}

// ---------------- GEMM1 + scatter merged ------------------------------------
__global__ __launch_bounds__(256) void gemm1_scatter_kernel(
    const float* __restrict__ as1, const float* __restrict__ ad1)
{
    if (blockIdx.x < G1B) {
        extern __shared__ char dsm[];
        gemm_body<1>(blockIdx.x & 3, blockIdx.x >> 2, dsm, as1, ad1);
    } else {
        int e = (blockIdx.x - G1B) * 256 + threadIdx.x;
        if (e < ET) {
            int d = g_dstv[e];
            int pos = atomicAdd(&g_cursor[d], 1);
            g_csrc[pos] = g_src[e];
        }
    }
}

// ---------------- GEMM2 standalone ------------------------------------------
__global__ __launch_bounds__(256) void gemm2_kernel(
    const float* __restrict__ as2, const float* __restrict__ ad2)
{
    extern __shared__ char dsm[];
    gemm_body<2>(blockIdx.x & 3, blockIdx.x >> 2, dsm, as2, ad2);
}

// ---------------- warp-per-node softmax + aggregate -------------------------
// Fast path (deg <= 64): single gather of logits cached in smem.
template<int LAYER>
__global__ __launch_bounds__(256) void wagg_kernel(
    const float* __restrict__ bias, const float* __restrict__ W3,
    const float* __restrict__ as3p, const float* __restrict__ ad3p)
{
    __shared__ float lbuf[8][64 * 4];   // per warp: 64 edges x 4 heads
    __shared__ int   sbuf[8][64];       // per warp: src ids

    const float* __restrict__ asrc_in = (LAYER == 1) ? g_asrc : g_asrc2;
    const float* __restrict__ adst_in = (LAYER == 1) ? g_adst : g_adst2;

    int w = threadIdx.x >> 5, lane = threadIdx.x & 31;
    int n = blockIdx.x * 8 + w;
    if (n >= NN) return;
    int start = g_rowoff[n];
    int deg   = g_rowoff[n + 1] - start;
    int head  = lane & 3, eslot = lane >> 2;
    float ad = adst_in[n * 4 + head];
    const float4* __restrict__ hA4 = (const float4*)g_hA;

    float ssum;
    int nacc;   // edges to accumulate from smem per pass (fast: deg, slow: 32)
    float4 acc[4];
    #pragma unroll
    for (int i = 0; i < 4; i++) acc[i] = make_float4(0.f, 0.f, 0.f, 0.f);

    if (deg <= 64) {
        // ---- single gather: logits into smem ----
        float mx = -1e30f;
        for (int e = eslot; e < deg; e += 8) {
            int s = g_csrc[start + e];
            if (head == 0) sbuf[w][e] = s;
            float lg = leaky(asrc_in[s * 4 + head] + ad);
            lbuf[w][e * 4 + head] = lg;
            mx = fmaxf(mx, lg);
        }
        #pragma unroll
        for (int o = 4; o < 32; o <<= 1)
            mx = fmaxf(mx, __shfl_xor_sync(0xffffffffu, mx, o));
        // ---- exp in place + sum ----
        float ls = 0.f;
        for (int e = eslot; e < deg; e += 8) {
            float wgt = __expf(lbuf[w][e * 4 + head] - mx);
            lbuf[w][e * 4 + head] = wgt;
            ls += wgt;
        }
        #pragma unroll
        for (int o = 4; o < 32; o <<= 1)
            ls += __shfl_xor_sync(0xffffffffu, ls, o);
        ssum = ls;
        __syncwarp();
        // ---- gather-accumulate ----
        #pragma unroll 4
        for (int e2 = 0; e2 < deg; e2++) {
            int s = sbuf[w][e2];
            const float4* hp = hA4 + (size_t)s * 128 + lane;
            #pragma unroll
            for (int i = 0; i < 4; i++) {
                float wgt = lbuf[w][e2 * 4 + i];
                float4 v = hp[i * 32];
                acc[i].x = fmaf(wgt, v.x, acc[i].x);
                acc[i].y = fmaf(wgt, v.y, acc[i].y);
                acc[i].z = fmaf(wgt, v.z, acc[i].z);
                acc[i].w = fmaf(wgt, v.w, acc[i].w);
            }
        }
    } else {
        // ---- fallback: 2-pass chunked (rare) ----
        float mx = -1e30f;
        for (int c = 0; c < deg; c += 8) {
            int e = c + eslot;
            if (e < deg) {
                int s = g_csrc[start + e];
                mx = fmaxf(mx, leaky(asrc_in[s * 4 + head] + ad));
            }
        }
        #pragma unroll
        for (int o = 4; o < 32; o <<= 1)
            mx = fmaxf(mx, __shfl_xor_sync(0xffffffffu, mx, o));

        float ls = 0.f;
        for (int c = 0; c < deg; c += 32) {
            #pragma unroll
            for (int sp = 0; sp < 4; sp++) {
                int el = sp * 8 + eslot;
                int e = c + el;
                float wgt = 0.f;
                if (e < deg) {
                    int s = g_csrc[start + e];
                    if (head == 0) sbuf[w][el] = s;
                    wgt = __expf(leaky(asrc_in[s * 4 + head] + ad) - mx);
                }
                lbuf[w][el * 4 + head] = wgt;
                ls += wgt;
            }
            __syncwarp();
            int cend = min(32, deg - c);
            #pragma unroll 4
            for (int e2 = 0; e2 < cend; e2++) {
                int s = sbuf[w][e2];
                const float4* hp = hA4 + (size_t)s * 128 + lane;
                #pragma unroll
                for (int i = 0; i < 4; i++) {
                    float wgt = lbuf[w][e2 * 4 + i];
                    float4 v = hp[i * 32];
                    acc[i].x = fmaf(wgt, v.x, acc[i].x);
                    acc[i].y = fmaf(wgt, v.y, acc[i].y);
                    acc[i].z = fmaf(wgt, v.z, acc[i].z);
                    acc[i].w = fmaf(wgt, v.w, acc[i].w);
                }
            }
            __syncwarp();
        }
        #pragma unroll
        for (int o = 4; o < 32; o <<= 1)
            ls += __shfl_xor_sync(0xffffffffu, ls, o);
        ssum = ls;
    }

    float inv[4];
    #pragma unroll
    for (int i = 0; i < 4; i++)
        inv[i] = 1.f / (__shfl_sync(0xffffffffu, ssum, i) + 1e-16f);

    float p = 0.f;
    #pragma unroll
    for (int i = 0; i < 4; i++) {
        float4 b4 = ((const float4*)bias)[i * 32 + lane];
        float4 o;
        o.x = acc[i].x * inv[i] + b4.x;
        o.y = acc[i].y * inv[i] + b4.y;
        o.z = acc[i].z * inv[i] + b4.z;
        o.w = acc[i].w * inv[i] + b4.w;
        o.x = o.x > 0.f ? o.x : (__expf(o.x) - 1.f);
        o.y = o.y > 0.f ? o.y : (__expf(o.y) - 1.f);
        o.z = o.z > 0.f ? o.z : (__expf(o.z) - 1.f);
        o.w = o.w > 0.f ? o.w : (__expf(o.w) - 1.f);
        if (LAYER == 1) {
            float rx, ry, rz, rw;
            unsigned h0 = pk_hi(o.x, o.y, rx, ry);
            unsigned h1 = pk_hi(o.z, o.w, rz, rw);
            size_t go = (size_t)n * 512 + i * 128 + lane * 4;
            *(uint2*)&g_hBh[go] = make_uint2(h0, h1);
            *(uint2*)&g_hBl[go] = make_uint2(pk(rx, ry), pk(rz, rw));
        } else {
            float4 w4 = ((const float4*)W3)[i * 32 + lane];
            p += o.x * w4.x + o.y * w4.y + o.z * w4.z + o.w * w4.w;
        }
    }
    if (LAYER == 2) {
        p = warp_red_sum(p);
        if (lane == 0) {
            g_h3[n] = p;
            g_as3[n] = p * as3p[0];
            g_ad3[n] = p * ad3p[0];
        }
    }
}

// ---------------- layer-3 aggregation ---------------------------------------
__global__ __launch_bounds__(256) void agg3_kernel(
    const float* __restrict__ b3, float* __restrict__ out)
{
    int n = blockIdx.x * 8 + (threadIdx.x >> 5);
    if (n >= NN) return;
    int lane = threadIdx.x & 31;
    int start = g_rowoff[n], deg = g_rowoff[n + 1] - start;
    float ad = g_ad3[n];
    float m = -1e30f;
    for (int e = lane; e < deg; e += 32) {
        int s = g_csrc[start + e];
        m = fmaxf(m, leaky(g_as3[s] + ad));
    }
    m = warp_red_max(m);
    float sum = 0.f, acc = 0.f;
    for (int e = lane; e < deg; e += 32) {
        int s = g_csrc[start + e];
        float w = __expf(leaky(g_as3[s] + ad) - m);
        sum += w;
        acc = fmaf(w, g_h3[s], acc);
    }
    sum = warp_red_sum(sum);
    acc = warp_red_sum(acc);
    if (!lane) out[n] = acc / (sum + 1e-16f) + b3[0];
}

// ---------------- launch ----------------------------------------------------
extern "C" void kernel_launch(void* const* d_in, const int* in_sizes, int n_in,
                              void* d_out, int out_size)
{
    const float* x   = (const float*)d_in[0];
    const void*  ei  = d_in[1];
    const float* W1  = (const float*)d_in[2];
    const float* as1 = (const float*)d_in[3];
    const float* ad1 = (const float*)d_in[4];
    const float* b1  = (const float*)d_in[5];
    const float* W2  = (const float*)d_in[6];
    const float* as2 = (const float*)d_in[7];
    const float* ad2 = (const float*)d_in[8];
    const float* b2  = (const float*)d_in[9];
    const float* W3  = (const float*)d_in[10];
    const float* as3 = (const float*)d_in[11];
    const float* ad3 = (const float*)d_in[12];
    const float* b3  = (const float*)d_in[13];
    float* out = (float*)d_out;

    cudaFuncSetAttribute(gemm1_scatter_kernel,
                         cudaFuncAttributeMaxDynamicSharedMemorySize, SM_TOTAL);
    cudaFuncSetAttribute(gemm2_kernel,
                         cudaFuncAttributeMaxDynamicSharedMemorySize, SM_TOTAL);

    int prep_blocks = DB + 256 + (NN * K1) / 256 + (FOUT * K1 + 255) / 256;

    // 0: init (dtype detect + zero + sync state)
    init_kernel<<<(NN * HEADS + 255) / 256, 256>>>((const unsigned*)ei);
    // 1: decode+count | weight/x prep
    decode_prep_kernel<<<prep_blocks, 256>>>(ei, W1, W2, x);
    // 2: fused degree scan
    scan_kernel<<<NB, 1024>>>();
    // 3: GEMM1 (+dots) overlapped with CSR scatter
    gemm1_scatter_kernel<<<G1B + DB, 256, SM_TOTAL>>>(as1, ad1);
    // 4: layer-1 softmax-aggregate
    wagg_kernel<1><<<(NN + 7) / 8, 256>>>(b1, W3, as3, ad3);
    // 5: GEMM2 (+dots)
    gemm2_kernel<<<G1B, 256, SM_TOTAL>>>(as2, ad2);
    // 6: layer-2 softmax-aggregate + fused W3 GEMV
    wagg_kernel<2><<<(NN + 7) / 8, 256>>>(b2, W3, as3, ad3);
    // 7: layer-3 scalar attention
    agg3_kernel<<<(NN + 7) / 8, 256>>>(b3, out);
}

// round 9
// speedup vs baseline: 3.2339x; 1.1137x over previous
#include <cuda_runtime.h>
#include <cuda_bf16.h>
#include <cuda_fp16.h>
#include <cstdint>

#define NN     20000
#define FIN    50
#define HID    128
#define HEADS  4
#define FOUT   512            // HEADS*HID
#define E0     320000
#define ET     (E0 + NN)      // edges incl. self-loops = 340000
#define K1     64             // layer-1 K padded 50 -> 64
#define NB     20             // scan blocks (ceil(NN/1024))
#define RB     ((NN + 127) / 128)       // 157 row blocks
#define G1B    (4 * RB)                 // 628 GEMM blocks
#define DB     ((ET + 255) / 256)       // 1329 decode/scatter blocks

// ---------------- scratch (device globals; no allocation allowed) ----------
__device__ __half g_hA[(size_t)NN * FOUT];           // GEMM output (fp16 messages)
__device__ __nv_bfloat16 g_hBh[(size_t)NN * FOUT];   // agg1 output hi
__device__ __nv_bfloat16 g_hBl[(size_t)NN * FOUT];   // agg1 output lo
__device__ __nv_bfloat16 g_xh[(size_t)NN * K1];      // x split hi (padded)
__device__ __nv_bfloat16 g_xl[(size_t)NN * K1];
__device__ __nv_bfloat16 g_W1Th[(size_t)FOUT * K1];  // W1^T hi [n][k]
__device__ __nv_bfloat16 g_W1Tl[(size_t)FOUT * K1];
__device__ __nv_bfloat16 g_W2Th[(size_t)FOUT * FOUT]; // W2^T hi [n][k]
__device__ __nv_bfloat16 g_W2Tl[(size_t)FOUT * FOUT];
__device__ float g_asrc[NN * HEADS],  g_adst[NN * HEADS];    // layer-1 dots
__device__ float g_asrc2[NN * HEADS], g_adst2[NN * HEADS];   // layer-2 dots
__device__ float g_h3[NN], g_as3[NN], g_ad3[NN];
__device__ int   g_src[ET], g_dstv[ET], g_csrc[ET];
__device__ int   g_deg[NN], g_cursor[NN], g_rowoff[NN + 1];
__device__ int   g_bsum[32], g_boff[32];
__device__ int   g_ctr, g_flag;
__device__ int   g_is64;

// ---------------- helpers --------------------------------------------------
__device__ __forceinline__ float warp_red_sum(float v) {
    #pragma unroll
    for (int o = 16; o; o >>= 1) v += __shfl_xor_sync(0xffffffffu, v, o);
    return v;
}
__device__ __forceinline__ float warp_red_max(float v) {
    #pragma unroll
    for (int o = 16; o; o >>= 1) v = fmaxf(v, __shfl_xor_sync(0xffffffffu, v, o));
    return v;
}
__device__ __forceinline__ float leaky(float x) { return x > 0.f ? x : 0.2f * x; }

__device__ __forceinline__ uint32_t smem_u32(const void* p) {
    uint32_t a;
    asm("{ .reg .u64 t; cvta.to.shared.u64 t, %1; cvt.u32.u64 %0, t; }" : "=r"(a) : "l"(p));
    return a;
}

__device__ __forceinline__ unsigned pk_hi(float a, float b, float& ra, float& rb) {
    __nv_bfloat16 ha = __float2bfloat16(a), hb = __float2bfloat16(b);
    ra = a - __bfloat162float(ha);
    rb = b - __bfloat162float(hb);
    return ((unsigned)__bfloat16_as_ushort(hb) << 16) | (unsigned)__bfloat16_as_ushort(ha);
}
__device__ __forceinline__ unsigned pk(float a, float b) {
    __nv_bfloat16 ha = __float2bfloat16(a), hb = __float2bfloat16(b);
    return ((unsigned)__bfloat16_as_ushort(hb) << 16) | (unsigned)__bfloat16_as_ushort(ha);
}

__device__ __forceinline__ void ldm_x4(unsigned r[4], uint32_t addr) {
    asm volatile("ldmatrix.sync.aligned.m8n8.x4.shared.b16 {%0,%1,%2,%3}, [%4];"
                 : "=r"(r[0]), "=r"(r[1]), "=r"(r[2]), "=r"(r[3]) : "r"(addr));
}
__device__ __forceinline__ void mma_bf16(float c[4], const unsigned a[4],
                                         unsigned b0, unsigned b1) {
    asm volatile(
        "mma.sync.aligned.m16n8k16.row.col.f32.bf16.bf16.f32 "
        "{%0,%1,%2,%3}, {%4,%5,%6,%7}, {%8,%9}, {%0,%1,%2,%3};"
        : "+f"(c[0]), "+f"(c[1]), "+f"(c[2]), "+f"(c[3])
        : "r"(a[0]), "r"(a[1]), "r"(a[2]), "r"(a[3]), "r"(b0), "r"(b1));
}
__device__ __forceinline__ void cpa16(uint32_t dst, const void* src, bool p) {
    int sz = p ? 16 : 0;
    asm volatile("cp.async.cg.shared.global [%0], [%1], 16, %2;"
                 :: "r"(dst), "l"(src), "r"(sz));
}
__device__ __forceinline__ void cpa_commit() {
    asm volatile("cp.async.commit_group;");
}
template<int N> __device__ __forceinline__ void cpa_wait() {
    asm volatile("cp.async.wait_group %0;" :: "n"(N));
}

// ---------------- init: detect dtype + zero accumulators --------------------
__global__ void init_kernel(const unsigned* __restrict__ w) {
    int i = blockIdx.x * blockDim.x + threadIdx.x;
    if (i == 0) {
        int is64 = 1;
        for (int q = 1; q < 64; q += 2)
            if (w[q] != 0u) { is64 = 0; break; }
        g_is64 = is64;
        g_ctr = 0;
        g_flag = 0;
    }
    if (i < NN) g_deg[i] = 0;
    if (i < NN * HEADS) {
        g_asrc[i] = 0.f;  g_adst[i] = 0.f;
        g_asrc2[i] = 0.f; g_adst2[i] = 0.f;
    }
}

// ---------------- merged decode+count | W2 transpose | x split | W1 split ---
__global__ __launch_bounds__(256) void decode_prep_kernel(
    const void* __restrict__ ei, const float* __restrict__ W1,
    const float* __restrict__ W2, const float* __restrict__ x)
{
    int b = blockIdx.x, t = threadIdx.x;
    if (b < DB) {
        int e = b * 256 + t;
        if (e >= ET) return;
        int s, d;
        if (e < E0) {
            if (g_is64) {
                const long long* p = (const long long*)ei;
                s = (int)p[e]; d = (int)p[E0 + e];
            } else {
                const int* p = (const int*)ei;
                s = p[e]; d = p[E0 + e];
            }
        } else {
            s = d = e - E0;
        }
        g_src[e] = s; g_dstv[e] = d;
        atomicAdd(&g_deg[d], 1);
    } else if (b < DB + 256) {
        __shared__ float tile[32][33];
        int bb = b - DB;
        int bx = (bb & 15) * 32, by = (bb >> 4) * 32;
        int tx = t & 31, ty = t >> 5;
        #pragma unroll
        for (int i = 0; i < 32; i += 8)
            tile[ty + i][tx] = W2[(size_t)(bx + ty + i) * 512 + by + tx];
        __syncthreads();
        #pragma unroll
        for (int i = 0; i < 32; i += 8) {
            float v = tile[tx][ty + i];
            __nv_bfloat16 h = __float2bfloat16(v);
            __nv_bfloat16 l = __float2bfloat16(v - __bfloat162float(h));
            size_t o = (size_t)(by + ty + i) * 512 + bx + tx;
            g_W2Th[o] = h;
            g_W2Tl[o] = l;
        }
    } else if (b < DB + 256 + (NN * K1) / 256) {
        int idx = (b - DB - 256) * 256 + t;
        int n = idx >> 6, k = idx & 63;
        float v = (k < FIN) ? x[n * FIN + k] : 0.f;
        __nv_bfloat16 h = __float2bfloat16(v);
        g_xh[idx] = h;
        g_xl[idx] = __float2bfloat16(v - __bfloat162float(h));
    } else {
        int idx = (b - DB - 256 - (NN * K1) / 256) * 256 + t;
        if (idx < FOUT * K1) {
            int n = idx >> 6, k = idx & 63;
            float v = (k < FIN) ? W1[(size_t)k * 512 + n] : 0.f;
            __nv_bfloat16 h = __float2bfloat16(v);
            g_W1Th[idx] = h;
            g_W1Tl[idx] = __float2bfloat16(v - __bfloat162float(h));
        }
    }
}

// ---------------- fused multi-block scan (one kernel, device flag sync) -----
__global__ __launch_bounds__(1024) void scan_kernel() {
    __shared__ int wsum[32];
    int b = blockIdx.x, t = threadIdx.x, lane = t & 31, w = t >> 5;
    int i = b * 1024 + t;
    int v = (i < NN) ? g_deg[i] : 0;
    int x = v;
    #pragma unroll
    for (int o = 1; o < 32; o <<= 1) {
        int y = __shfl_up_sync(0xffffffffu, x, o);
        if (lane >= o) x += y;
    }
    if (lane == 31) wsum[w] = x;
    __syncthreads();
    if (w == 0) {
        int y = wsum[lane];
        #pragma unroll
        for (int o = 1; o < 32; o <<= 1) {
            int z = __shfl_up_sync(0xffffffffu, y, o);
            if (lane >= o) y += z;
        }
        wsum[lane] = y;
    }
    __syncthreads();
    int incl = x + (w ? wsum[w - 1] : 0);
    int excl_local = incl - v;
    if (t == 1023) g_bsum[b] = incl;
    __threadfence();
    __syncthreads();

    if (t == 0) {
        int arrived = atomicAdd(&g_ctr, 1);
        if (arrived == NB - 1) {
            int acc = 0;
            #pragma unroll
            for (int q = 0; q < NB; q++) { g_boff[q] = acc; acc += g_bsum[q]; }
            __threadfence();
            atomicExch(&g_flag, 1);
        }
        while (atomicAdd(&g_flag, 0) == 0) {}
    }
    __syncthreads();

    int off = g_boff[b];
    if (i < NN) {
        g_rowoff[i + 1] = off + incl;
        g_cursor[i]     = off + excl_local;
    }
    if (b == 0 && t == 0) g_rowoff[0] = 0;
}

// ---------------- GEMM body (shared by both layers) -------------------------
#define TB   10240                 // one tile array
#define BUF  (4 * TB)              // one buffer = 40960
#define SM_ATT (2 * BUF)           // 81920
#define SM_TOTAL (SM_ATT + 1024)

template<int LAYER>
__device__ __forceinline__ void gemm_body(
    int head, int rowb, char* dsm,
    const float* __restrict__ atts, const float* __restrict__ attd)
{
    constexpr int K = (LAYER == 1) ? K1 : FOUT;
    constexpr int KITER = K / 32;

    float* satts = (float*)(dsm + SM_ATT);
    float* sattd = satts + 128;

    const __nv_bfloat16* __restrict__ Ah = (LAYER == 1) ? g_xh : g_hBh;
    const __nv_bfloat16* __restrict__ Al = (LAYER == 1) ? g_xl : g_hBl;
    const __nv_bfloat16* __restrict__ Bh = (LAYER == 1) ? g_W1Th : g_W2Th;
    const __nv_bfloat16* __restrict__ Bl = (LAYER == 1) ? g_W1Tl : g_W2Tl;

    int tid = threadIdx.x;
    int wid = tid >> 5, lane = tid & 31;
    int wm = (wid & 3) * 32;
    int wn = (wid >> 2) * 64;
    int rowBase = rowb * 128;
    int colBase = head * 128;
    uint32_t smb = smem_u32(dsm);

    if (tid < 128) {
        satts[tid] = atts[head * 128 + tid];
        sattd[tid] = attd[head * 128 + tid];
    }

    float c[2][8][4];
    #pragma unroll
    for (int t = 0; t < 2; t++)
        #pragma unroll
        for (int j = 0; j < 8; j++)
            #pragma unroll
            for (int q = 0; q < 4; q++) c[t][j][q] = 0.f;

    int r0l = tid >> 2, c8 = tid & 3;

    auto load_tile = [&](int it, int buf) {
        uint32_t bb = smb + buf * BUF;
        #pragma unroll
        for (int i = 0; i < 2; i++) {
            int r = r0l + i * 64;
            int sw = c8 ^ (r & 3);
            uint32_t ro = (uint32_t)r * 80u + (uint32_t)sw * 16u;
            int grow = rowBase + r;
            bool p = grow < NN;
            int gcl = p ? grow : (NN - 1);
            size_t goA = (size_t)gcl * K + it * 32 + c8 * 8;
            cpa16(bb + ro,          Ah + goA, p);
            cpa16(bb + TB + ro,     Al + goA, p);
            size_t goB = (size_t)(colBase + r) * K + it * 32 + c8 * 8;
            cpa16(bb + 2 * TB + ro, Bh + goB, true);
            cpa16(bb + 3 * TB + ro, Bl + goB, true);
        }
    };

    load_tile(0, 0);
    cpa_commit();

    int lr = lane & 15, lhalf = lane >> 4;

    for (int it = 0; it < KITER; it++) {
        if (it + 1 < KITER) {
            load_tile(it + 1, (it + 1) & 1);
            cpa_commit();
            cpa_wait<1>();
        } else {
            cpa_wait<0>();
        }
        __syncthreads();

        uint32_t bb = smb + (it & 1) * BUF;
        uint32_t aBaseH = bb, aBaseL = bb + TB, bBaseH = bb + 2 * TB, bBaseL = bb + 3 * TB;

        #pragma unroll
        for (int s = 0; s < 2; s++) {
            unsigned ah[2][4], al[2][4], bh[4][4], bl[4][4];
            #pragma unroll
            for (int t = 0; t < 2; t++) {
                int row = wm + t * 16 + lr;
                uint32_t unit = (uint32_t)((s * 2 + lhalf) ^ (row & 3));
                uint32_t off = (uint32_t)row * 80u + unit * 16u;
                ldm_x4(ah[t], aBaseH + off);
                ldm_x4(al[t], aBaseL + off);
            }
            #pragma unroll
            for (int p = 0; p < 4; p++) {
                int row = wn + p * 16 + lr;
                uint32_t unit = (uint32_t)((s * 2 + lhalf) ^ (row & 3));
                uint32_t off = (uint32_t)row * 80u + unit * 16u;
                ldm_x4(bh[p], bBaseH + off);
                ldm_x4(bl[p], bBaseL + off);
            }
            #pragma unroll
            for (int t = 0; t < 2; t++) {
                #pragma unroll
                for (int j = 0; j < 8; j++) {
                    int p = j >> 1;
                    unsigned bh0 = (j & 1) ? bh[p][1] : bh[p][0];
                    unsigned bh1 = (j & 1) ? bh[p][3] : bh[p][2];
                    unsigned bl0 = (j & 1) ? bl[p][1] : bl[p][0];
                    unsigned bl1 = (j & 1) ? bl[p][3] : bl[p][2];
                    mma_bf16(c[t][j], ah[t], bh0, bh1);
                    mma_bf16(c[t][j], ah[t], bl0, bl1);
                    mma_bf16(c[t][j], al[t], bh0, bh1);
                }
            }
        }
        __syncthreads();
    }

    float* asrc_out = (LAYER == 1) ? g_asrc : g_asrc2;
    float* adst_out = (LAYER == 1) ? g_adst : g_adst2;

    #pragma unroll
    for (int t = 0; t < 2; t++) {
        int r0 = rowBase + wm + t * 16 + (lane >> 2);
        #pragma unroll
        for (int j = 0; j < 8; j++) {
            int col = colBase + wn + j * 8 + (lane & 3) * 2;
            if (r0 < NN) {
                __half2 hv = __floats2half2_rn(c[t][j][0], c[t][j][1]);
                *(__half2*)&g_hA[(size_t)r0 * 512 + col] = hv;
            }
            if (r0 + 8 < NN) {
                __half2 hv = __floats2half2_rn(c[t][j][2], c[t][j][3]);
                *(__half2*)&g_hA[(size_t)(r0 + 8) * 512 + col] = hv;
            }
        }
        float s_a = 0.f, d_a = 0.f, s_b = 0.f, d_b = 0.f;
        #pragma unroll
        for (int j = 0; j < 8; j++) {
            int cl = wn + j * 8 + (lane & 3) * 2;
            float a0 = satts[cl], a1 = satts[cl + 1];
            float e0 = sattd[cl], e1 = sattd[cl + 1];
            s_a += c[t][j][0] * a0 + c[t][j][1] * a1;
            d_a += c[t][j][0] * e0 + c[t][j][1] * e1;
            s_b += c[t][j][2] * a0 + c[t][j][3] * a1;
            d_b += c[t][j][2] * e0 + c[t][j][3] * e1;
        }
        #pragma unroll
        for (int o = 1; o <= 2; o <<= 1) {
            s_a += __shfl_xor_sync(0xffffffffu, s_a, o);
            d_a += __shfl_xor_sync(0xffffffffu, d_a, o);
            s_b += __shfl_xor_sync(0xffffffffu, s_b, o);
            d_b += __shfl_xor_sync(0xffffffffu, d_b, o);
        }
        if ((lane & 3) == 0) {
            if (r0 < NN) {
                atomicAdd(&asrc_out[r0 * 4 + head], s_a);
                atomicAdd(&adst_out[r0 * 4 + head], d_a);
            }
            if (r0 + 8 < NN) {
                atomicAdd(&asrc_out[(r0 + 8) * 4 + head], s_b);
                atomicAdd(&adst_out[(r0 + 8) * 4 + head], d_b);
            }
        }
    }
}

// ---------------- GEMM1 + scatter merged ------------------------------------
__global__ __launch_bounds__(256) void gemm1_scatter_kernel(
    const float* __restrict__ as1, const float* __restrict__ ad1)
{
    if (blockIdx.x < G1B) {
        extern __shared__ char dsm[];
        gemm_body<1>(blockIdx.x & 3, blockIdx.x >> 2, dsm, as1, ad1);
    } else {
        int e = (blockIdx.x - G1B) * 256 + threadIdx.x;
        if (e < ET) {
            int d = g_dstv[e];
            int pos = atomicAdd(&g_cursor[d], 1);
            g_csrc[pos] = g_src[e];
        }
    }
}

// ---------------- GEMM2 standalone ------------------------------------------
__global__ __launch_bounds__(256) void gemm2_kernel(
    const float* __restrict__ as2, const float* __restrict__ ad2)
{
    extern __shared__ char dsm[];
    gemm_body<2>(blockIdx.x & 3, blockIdx.x >> 2, dsm, as2, ad2);
}

// ---------------- warp-per-node softmax + aggregate (fp16 gather) ----------
__device__ __forceinline__ void acc_edge(float4 acc[4], const float* wj,
                                         const uint2* __restrict__ hp) {
    #pragma unroll
    for (int i = 0; i < 4; i++) {
        float wgt = wj[i];
        uint2 u = hp[i * 32];
        float2 v01 = __half22float2(*(__half2*)&u.x);
        float2 v23 = __half22float2(*(__half2*)&u.y);
        acc[i].x = fmaf(wgt, v01.x, acc[i].x);
        acc[i].y = fmaf(wgt, v01.y, acc[i].y);
        acc[i].z = fmaf(wgt, v23.x, acc[i].z);
        acc[i].w = fmaf(wgt, v23.y, acc[i].w);
    }
}

template<int LAYER>
__global__ __launch_bounds__(256) void wagg_kernel(
    const float* __restrict__ bias, const float* __restrict__ W3,
    const float* __restrict__ as3p, const float* __restrict__ ad3p)
{
    __shared__ float lbuf[8][64 * 4];   // per warp: 64 edges x 4 heads
    __shared__ int   sbuf[8][64];       // per warp: src ids

    const float* __restrict__ asrc_in = (LAYER == 1) ? g_asrc : g_asrc2;
    const float* __restrict__ adst_in = (LAYER == 1) ? g_adst : g_adst2;

    int w = threadIdx.x >> 5, lane = threadIdx.x & 31;
    int n = blockIdx.x * 8 + w;
    if (n >= NN) return;
    int start = g_rowoff[n];
    int deg   = g_rowoff[n + 1] - start;
    int head  = lane & 3, eslot = lane >> 2;
    float ad = adst_in[n * 4 + head];

    float ssum;
    float4 acc[4];
    #pragma unroll
    for (int i = 0; i < 4; i++) acc[i] = make_float4(0.f, 0.f, 0.f, 0.f);

    if (deg <= 64) {
        float mx = -1e30f;
        for (int e = eslot; e < deg; e += 8) {
            int s = g_csrc[start + e];
            if (head == 0) sbuf[w][e] = s;
            float lg = leaky(asrc_in[s * 4 + head] + ad);
            lbuf[w][e * 4 + head] = lg;
            mx = fmaxf(mx, lg);
        }
        #pragma unroll
        for (int o = 4; o < 32; o <<= 1)
            mx = fmaxf(mx, __shfl_xor_sync(0xffffffffu, mx, o));
        float ls = 0.f;
        for (int e = eslot; e < deg; e += 8) {
            float wgt = __expf(lbuf[w][e * 4 + head] - mx);
            lbuf[w][e * 4 + head] = wgt;
            ls += wgt;
        }
        #pragma unroll
        for (int o = 4; o < 32; o <<= 1)
            ls += __shfl_xor_sync(0xffffffffu, ls, o);
        ssum = ls;
        __syncwarp();
        #pragma unroll 4
        for (int e2 = 0; e2 < deg; e2++) {
            const uint2* hp = (const uint2*)(g_hA + (size_t)sbuf[w][e2] * 512) + lane;
            acc_edge(acc, &lbuf[w][e2 * 4], hp);
        }
    } else {
        float mx = -1e30f;
        for (int c = 0; c < deg; c += 8) {
            int e = c + eslot;
            if (e < deg) {
                int s = g_csrc[start + e];
                mx = fmaxf(mx, leaky(asrc_in[s * 4 + head] + ad));
            }
        }
        #pragma unroll
        for (int o = 4; o < 32; o <<= 1)
            mx = fmaxf(mx, __shfl_xor_sync(0xffffffffu, mx, o));

        float ls = 0.f;
        for (int c = 0; c < deg; c += 32) {
            #pragma unroll
            for (int sp = 0; sp < 4; sp++) {
                int el = sp * 8 + eslot;
                int e = c + el;
                float wgt = 0.f;
                if (e < deg) {
                    int s = g_csrc[start + e];
                    if (head == 0) sbuf[w][el] = s;
                    wgt = __expf(leaky(asrc_in[s * 4 + head] + ad) - mx);
                }
                lbuf[w][el * 4 + head] = wgt;
                ls += wgt;
            }
            __syncwarp();
            int cend = min(32, deg - c);
            #pragma unroll 4
            for (int e2 = 0; e2 < cend; e2++) {
                const uint2* hp = (const uint2*)(g_hA + (size_t)sbuf[w][e2] * 512) + lane;
                acc_edge(acc, &lbuf[w][e2 * 4], hp);
            }
            __syncwarp();
        }
        #pragma unroll
        for (int o = 4; o < 32; o <<= 1)
            ls += __shfl_xor_sync(0xffffffffu, ls, o);
        ssum = ls;
    }

    float inv[4];
    #pragma unroll
    for (int i = 0; i < 4; i++)
        inv[i] = 1.f / (__shfl_sync(0xffffffffu, ssum, i) + 1e-16f);

    float p = 0.f;
    #pragma unroll
    for (int i = 0; i < 4; i++) {
        float4 b4 = ((const float4*)bias)[i * 32 + lane];
        float4 o;
        o.x = acc[i].x * inv[i] + b4.x;
        o.y = acc[i].y * inv[i] + b4.y;
        o.z = acc[i].z * inv[i] + b4.z;
        o.w = acc[i].w * inv[i] + b4.w;
        o.x = o.x > 0.f ? o.x : (__expf(o.x) - 1.f);
        o.y = o.y > 0.f ? o.y : (__expf(o.y) - 1.f);
        o.z = o.z > 0.f ? o.z : (__expf(o.z) - 1.f);
        o.w = o.w > 0.f ? o.w : (__expf(o.w) - 1.f);
        if (LAYER == 1) {
            float rx, ry, rz, rw;
            unsigned h0 = pk_hi(o.x, o.y, rx, ry);
            unsigned h1 = pk_hi(o.z, o.w, rz, rw);
            size_t go = (size_t)n * 512 + i * 128 + lane * 4;
            *(uint2*)&g_hBh[go] = make_uint2(h0, h1);
            *(uint2*)&g_hBl[go] = make_uint2(pk(rx, ry), pk(rz, rw));
        } else {
            float4 w4 = ((const float4*)W3)[i * 32 + lane];
            p += o.x * w4.x + o.y * w4.y + o.z * w4.z + o.w * w4.w;
        }
    }
    if (LAYER == 2) {
        p = warp_red_sum(p);
        if (lane == 0) {
            g_h3[n] = p;
            g_as3[n] = p * as3p[0];
            g_ad3[n] = p * ad3p[0];
        }
    }
}

// ---------------- layer-3 aggregation ---------------------------------------
__global__ __launch_bounds__(256) void agg3_kernel(
    const float* __restrict__ b3, float* __restrict__ out)
{
    int n = blockIdx.x * 8 + (threadIdx.x >> 5);
    if (n >= NN) return;
    int lane = threadIdx.x & 31;
    int start = g_rowoff[n], deg = g_rowoff[n + 1] - start;
    float ad = g_ad3[n];
    float m = -1e30f;
    for (int e = lane; e < deg; e += 32) {
        int s = g_csrc[start + e];
        m = fmaxf(m, leaky(g_as3[s] + ad));
    }
    m = warp_red_max(m);
    float sum = 0.f, acc = 0.f;
    for (int e = lane; e < deg; e += 32) {
        int s = g_csrc[start + e];
        float w = __expf(leaky(g_as3[s] + ad) - m);
        sum += w;
        acc = fmaf(w, g_h3[s], acc);
    }
    sum = warp_red_sum(sum);
    acc = warp_red_sum(acc);
    if (!lane) out[n] = acc / (sum + 1e-16f) + b3[0];
}

// ---------------- launch ----------------------------------------------------
extern "C" void kernel_launch(void* const* d_in, const int* in_sizes, int n_in,
                              void* d_out, int out_size)
{
    const float* x   = (const float*)d_in[0];
    const void*  ei  = d_in[1];
    const float* W1  = (const float*)d_in[2];
    const float* as1 = (const float*)d_in[3];
    const float* ad1 = (const float*)d_in[4];
    const float* b1  = (const float*)d_in[5];
    const float* W2  = (const float*)d_in[6];
    const float* as2 = (const float*)d_in[7];
    const float* ad2 = (const float*)d_in[8];
    const float* b2  = (const float*)d_in[9];
    const float* W3  = (const float*)d_in[10];
    const float* as3 = (const float*)d_in[11];
    const float* ad3 = (const float*)d_in[12];
    const float* b3  = (const float*)d_in[13];
    float* out = (float*)d_out;

    cudaFuncSetAttribute(gemm1_scatter_kernel,
                         cudaFuncAttributeMaxDynamicSharedMemorySize, SM_TOTAL);
    cudaFuncSetAttribute(gemm2_kernel,
                         cudaFuncAttributeMaxDynamicSharedMemorySize, SM_TOTAL);

    int prep_blocks = DB + 256 + (NN * K1) / 256 + (FOUT * K1 + 255) / 256;

    // 0: init (dtype detect + zero + sync state)
    init_kernel<<<(NN * HEADS + 255) / 256, 256>>>((const unsigned*)ei);
    // 1: decode+count | weight/x prep
    decode_prep_kernel<<<prep_blocks, 256>>>(ei, W1, W2, x);
    // 2: fused degree scan
    scan_kernel<<<NB, 1024>>>();
    // 3: GEMM1 (+dots) overlapped with CSR scatter
    gemm1_scatter_kernel<<<G1B + DB, 256, SM_TOTAL>>>(as1, ad1);
    // 4: layer-1 softmax-aggregate
    wagg_kernel<1><<<(NN + 7) / 8, 256>>>(b1, W3, as3, ad3);
    // 5: GEMM2 (+dots)
    gemm2_kernel<<<G1B, 256, SM_TOTAL>>>(as2, ad2);
    // 6: layer-2 softmax-aggregate + fused W3 GEMV
    wagg_kernel<2><<<(NN + 7) / 8, 256>>>(b2, W3, as3, ad3);
    // 7: layer-3 scalar attention
    agg3_kernel<<<(NN + 7) / 8, 256>>>(b3, out);
}

// round 10
// speedup vs baseline: 3.9914x; 1.2342x over previous
#include <cuda_runtime.h>
#include <cuda_fp16.h>
#include <cstdint>

#define NN     20000
#define FIN    50
#define HID    128
#define HEADS  4
#define FOUT   512            // HEADS*HID
#define E0     320000
#define ET     (E0 + NN)      // edges incl. self-loops = 340000
#define K1     64             // layer-1 K padded 50 -> 64
#define NB     20             // scan blocks (ceil(NN/1024))
#define RB     ((NN + 127) / 128)       // 157 row blocks
#define G1B    (4 * RB)                 // 628 GEMM blocks
#define DB     ((ET + 255) / 256)       // 1329 decode/scatter blocks

// ---------------- scratch (device globals; no allocation allowed) ----------
__device__ __half g_hA[(size_t)NN * FOUT];      // GEMM output (fp16 messages)
__device__ __half g_hBh[(size_t)NN * FOUT];     // agg1 output hi (fp16)
__device__ __half g_hBl[(size_t)NN * FOUT];     // agg1 output lo (fp16)
__device__ __half g_xh[(size_t)NN * K1];        // x split hi (padded)
__device__ __half g_xl[(size_t)NN * K1];
__device__ __half g_W1T[(size_t)FOUT * K1];     // W1^T fp16 [n][k]
__device__ __half g_W2T[(size_t)FOUT * FOUT];   // W2^T fp16 [n][k]
__device__ float g_asrc[NN * HEADS],  g_adst[NN * HEADS];    // layer-1 dots
__device__ float g_asrc2[NN * HEADS], g_adst2[NN * HEADS];   // layer-2 dots
__device__ float g_h3[NN], g_as3[NN], g_ad3[NN];
__device__ int   g_src[ET], g_dstv[ET], g_csrc[ET];
__device__ int   g_deg[NN], g_cursor[NN], g_rowoff[NN + 1];
__device__ int   g_bsum[32], g_boff[32];
__device__ int   g_ctr, g_flag;
__device__ int   g_is64;

// ---------------- helpers --------------------------------------------------
__device__ __forceinline__ float warp_red_sum(float v) {
    #pragma unroll
    for (int o = 16; o; o >>= 1) v += __shfl_xor_sync(0xffffffffu, v, o);
    return v;
}
__device__ __forceinline__ float warp_red_max(float v) {
    #pragma unroll
    for (int o = 16; o; o >>= 1) v = fmaxf(v, __shfl_xor_sync(0xffffffffu, v, o));
    return v;
}
__device__ __forceinline__ float leaky(float x) { return x > 0.f ? x : 0.2f * x; }

__device__ __forceinline__ uint32_t smem_u32(const void* p) {
    uint32_t a;
    asm("{ .reg .u64 t; cvta.to.shared.u64 t, %1; cvt.u32.u64 %0, t; }" : "=r"(a) : "l"(p));
    return a;
}

// pack two floats' fp16-hi parts into one uint, return residuals
__device__ __forceinline__ unsigned pkh_hi(float a, float b, float& ra, float& rb) {
    __half ha = __float2half_rn(a), hb = __float2half_rn(b);
    ra = a - __half2float(ha);
    rb = b - __half2float(hb);
    return ((unsigned)__half_as_ushort(hb) << 16) | (unsigned)__half_as_ushort(ha);
}
__device__ __forceinline__ unsigned pkh(float a, float b) {
    __half ha = __float2half_rn(a), hb = __float2half_rn(b);
    return ((unsigned)__half_as_ushort(hb) << 16) | (unsigned)__half_as_ushort(ha);
}

__device__ __forceinline__ void ldm_x4(unsigned r[4], uint32_t addr) {
    asm volatile("ldmatrix.sync.aligned.m8n8.x4.shared.b16 {%0,%1,%2,%3}, [%4];"
                 : "=r"(r[0]), "=r"(r[1]), "=r"(r[2]), "=r"(r[3]) : "r"(addr));
}
__device__ __forceinline__ void mma_f16(float c[4], const unsigned a[4],
                                        unsigned b0, unsigned b1) {
    asm volatile(
        "mma.sync.aligned.m16n8k16.row.col.f32.f16.f16.f32 "
        "{%0,%1,%2,%3}, {%4,%5,%6,%7}, {%8,%9}, {%0,%1,%2,%3};"
        : "+f"(c[0]), "+f"(c[1]), "+f"(c[2]), "+f"(c[3])
        : "r"(a[0]), "r"(a[1]), "r"(a[2]), "r"(a[3]), "r"(b0), "r"(b1));
}
__device__ __forceinline__ void cpa16(uint32_t dst, const void* src, bool p) {
    int sz = p ? 16 : 0;
    asm volatile("cp.async.cg.shared.global [%0], [%1], 16, %2;"
                 :: "r"(dst), "l"(src), "r"(sz));
}
__device__ __forceinline__ void cpa_commit() {
    asm volatile("cp.async.commit_group;");
}
template<int N> __device__ __forceinline__ void cpa_wait() {
    asm volatile("cp.async.wait_group %0;" :: "n"(N));
}

// ---------------- init: detect dtype + zero accumulators --------------------
__global__ void init_kernel(const unsigned* __restrict__ w) {
    int i = blockIdx.x * blockDim.x + threadIdx.x;
    if (i == 0) {
        int is64 = 1;
        for (int q = 1; q < 64; q += 2)
            if (w[q] != 0u) { is64 = 0; break; }
        g_is64 = is64;
        g_ctr = 0;
        g_flag = 0;
    }
    if (i < NN) g_deg[i] = 0;
    if (i < NN * HEADS) {
        g_asrc[i] = 0.f;  g_adst[i] = 0.f;
        g_asrc2[i] = 0.f; g_adst2[i] = 0.f;
    }
}

// ---------------- merged decode+count | W2 transpose | x split | W1 ---------
__global__ __launch_bounds__(256) void decode_prep_kernel(
    const void* __restrict__ ei, const float* __restrict__ W1,
    const float* __restrict__ W2, const float* __restrict__ x)
{
    int b = blockIdx.x, t = threadIdx.x;
    if (b < DB) {
        int e = b * 256 + t;
        if (e >= ET) return;
        int s, d;
        if (e < E0) {
            if (g_is64) {
                const long long* p = (const long long*)ei;
                s = (int)p[e]; d = (int)p[E0 + e];
            } else {
                const int* p = (const int*)ei;
                s = p[e]; d = p[E0 + e];
            }
        } else {
            s = d = e - E0;
        }
        g_src[e] = s; g_dstv[e] = d;
        atomicAdd(&g_deg[d], 1);
    } else if (b < DB + 256) {
        __shared__ float tile[32][33];
        int bb = b - DB;
        int bx = (bb & 15) * 32, by = (bb >> 4) * 32;
        int tx = t & 31, ty = t >> 5;
        #pragma unroll
        for (int i = 0; i < 32; i += 8)
            tile[ty + i][tx] = W2[(size_t)(bx + ty + i) * 512 + by + tx];
        __syncthreads();
        #pragma unroll
        for (int i = 0; i < 32; i += 8) {
            float v = tile[tx][ty + i];
            g_W2T[(size_t)(by + ty + i) * 512 + bx + tx] = __float2half_rn(v);
        }
    } else if (b < DB + 256 + (NN * K1) / 256) {
        int idx = (b - DB - 256) * 256 + t;
        int n = idx >> 6, k = idx & 63;
        float v = (k < FIN) ? x[n * FIN + k] : 0.f;
        __half h = __float2half_rn(v);
        g_xh[idx] = h;
        g_xl[idx] = __float2half_rn(v - __half2float(h));
    } else {
        int idx = (b - DB - 256 - (NN * K1) / 256) * 256 + t;
        if (idx < FOUT * K1) {
            int n = idx >> 6, k = idx & 63;
            float v = (k < FIN) ? W1[(size_t)k * 512 + n] : 0.f;
            g_W1T[idx] = __float2half_rn(v);
        }
    }
}

// ---------------- fused multi-block scan (one kernel, device flag sync) -----
__global__ __launch_bounds__(1024) void scan_kernel() {
    __shared__ int wsum[32];
    int b = blockIdx.x, t = threadIdx.x, lane = t & 31, w = t >> 5;
    int i = b * 1024 + t;
    int v = (i < NN) ? g_deg[i] : 0;
    int x = v;
    #pragma unroll
    for (int o = 1; o < 32; o <<= 1) {
        int y = __shfl_up_sync(0xffffffffu, x, o);
        if (lane >= o) x += y;
    }
    if (lane == 31) wsum[w] = x;
    __syncthreads();
    if (w == 0) {
        int y = wsum[lane];
        #pragma unroll
        for (int o = 1; o < 32; o <<= 1) {
            int z = __shfl_up_sync(0xffffffffu, y, o);
            if (lane >= o) y += z;
        }
        wsum[lane] = y;
    }
    __syncthreads();
    int incl = x + (w ? wsum[w - 1] : 0);
    int excl_local = incl - v;
    if (t == 1023) g_bsum[b] = incl;
    __threadfence();
    __syncthreads();

    if (t == 0) {
        int arrived = atomicAdd(&g_ctr, 1);
        if (arrived == NB - 1) {
            int acc = 0;
            #pragma unroll
            for (int q = 0; q < NB; q++) { g_boff[q] = acc; acc += g_bsum[q]; }
            __threadfence();
            atomicExch(&g_flag, 1);
        }
        while (atomicAdd(&g_flag, 0) == 0) {}
    }
    __syncthreads();

    int off = g_boff[b];
    if (i < NN) {
        g_rowoff[i + 1] = off + incl;
        g_cursor[i]     = off + excl_local;
    }
    if (b == 0 && t == 0) g_rowoff[0] = 0;
}

// ---------------- GEMM body: fp16 2-pass (A hi/lo, B single) ----------------
#define TB   10240                 // one tile array (128 rows x 80 B)
#define BUF  (3 * TB)              // one buffer = {AH, AL, B} = 30720
#define SM_ATT (2 * BUF)           // 61440
#define SM_TOTAL (SM_ATT + 1024)

template<int LAYER>
__device__ __forceinline__ void gemm_body(
    int head, int rowb, char* dsm,
    const float* __restrict__ atts, const float* __restrict__ attd)
{
    constexpr int K = (LAYER == 1) ? K1 : FOUT;
    constexpr int KITER = K / 32;

    float* satts = (float*)(dsm + SM_ATT);
    float* sattd = satts + 128;

    const __half* __restrict__ Ah = (LAYER == 1) ? g_xh : g_hBh;
    const __half* __restrict__ Al = (LAYER == 1) ? g_xl : g_hBl;
    const __half* __restrict__ B  = (LAYER == 1) ? g_W1T : g_W2T;

    int tid = threadIdx.x;
    int wid = tid >> 5, lane = tid & 31;
    int wm = (wid & 3) * 32;
    int wn = (wid >> 2) * 64;
    int rowBase = rowb * 128;
    int colBase = head * 128;
    uint32_t smb = smem_u32(dsm);

    if (tid < 128) {
        satts[tid] = atts[head * 128 + tid];
        sattd[tid] = attd[head * 128 + tid];
    }

    float c[2][8][4];
    #pragma unroll
    for (int t = 0; t < 2; t++)
        #pragma unroll
        for (int j = 0; j < 8; j++)
            #pragma unroll
            for (int q = 0; q < 4; q++) c[t][j][q] = 0.f;

    int r0l = tid >> 2, c8 = tid & 3;

    auto load_tile = [&](int it, int buf) {
        uint32_t bb = smb + buf * BUF;
        #pragma unroll
        for (int i = 0; i < 2; i++) {
            int r = r0l + i * 64;
            int sw = c8 ^ (r & 3);
            uint32_t ro = (uint32_t)r * 80u + (uint32_t)sw * 16u;
            int grow = rowBase + r;
            bool p = grow < NN;
            int gcl = p ? grow : (NN - 1);
            size_t goA = (size_t)gcl * K + it * 32 + c8 * 8;
            cpa16(bb + ro,          Ah + goA, p);
            cpa16(bb + TB + ro,     Al + goA, p);
            size_t goB = (size_t)(colBase + r) * K + it * 32 + c8 * 8;
            cpa16(bb + 2 * TB + ro, B + goB, true);
        }
    };

    load_tile(0, 0);
    cpa_commit();

    int lr = lane & 15, lhalf = lane >> 4;

    for (int it = 0; it < KITER; it++) {
        if (it + 1 < KITER) {
            load_tile(it + 1, (it + 1) & 1);
            cpa_commit();
            cpa_wait<1>();
        } else {
            cpa_wait<0>();
        }
        __syncthreads();

        uint32_t bb = smb + (it & 1) * BUF;
        uint32_t aBaseH = bb, aBaseL = bb + TB, bBase = bb + 2 * TB;

        #pragma unroll
        for (int s = 0; s < 2; s++) {
            unsigned ah[2][4], al[2][4], bf[4][4];
            #pragma unroll
            for (int t = 0; t < 2; t++) {
                int row = wm + t * 16 + lr;
                uint32_t unit = (uint32_t)((s * 2 + lhalf) ^ (row & 3));
                uint32_t off = (uint32_t)row * 80u + unit * 16u;
                ldm_x4(ah[t], aBaseH + off);
                ldm_x4(al[t], aBaseL + off);
            }
            #pragma unroll
            for (int p = 0; p < 4; p++) {
                int row = wn + p * 16 + lr;
                uint32_t unit = (uint32_t)((s * 2 + lhalf) ^ (row & 3));
                uint32_t off = (uint32_t)row * 80u + unit * 16u;
                ldm_x4(bf[p], bBase + off);
            }
            #pragma unroll
            for (int t = 0; t < 2; t++) {
                #pragma unroll
                for (int j = 0; j < 8; j++) {
                    int p = j >> 1;
                    unsigned b0 = (j & 1) ? bf[p][1] : bf[p][0];
                    unsigned b1 = (j & 1) ? bf[p][3] : bf[p][2];
                    mma_f16(c[t][j], ah[t], b0, b1);
                    mma_f16(c[t][j], al[t], b0, b1);
                }
            }
        }
        __syncthreads();
    }

    float* asrc_out = (LAYER == 1) ? g_asrc : g_asrc2;
    float* adst_out = (LAYER == 1) ? g_adst : g_adst2;

    #pragma unroll
    for (int t = 0; t < 2; t++) {
        int r0 = rowBase + wm + t * 16 + (lane >> 2);
        #pragma unroll
        for (int j = 0; j < 8; j++) {
            int col = colBase + wn + j * 8 + (lane & 3) * 2;
            if (r0 < NN) {
                __half2 hv = __floats2half2_rn(c[t][j][0], c[t][j][1]);
                *(__half2*)&g_hA[(size_t)r0 * 512 + col] = hv;
            }
            if (r0 + 8 < NN) {
                __half2 hv = __floats2half2_rn(c[t][j][2], c[t][j][3]);
                *(__half2*)&g_hA[(size_t)(r0 + 8) * 512 + col] = hv;
            }
        }
        float s_a = 0.f, d_a = 0.f, s_b = 0.f, d_b = 0.f;
        #pragma unroll
        for (int j = 0; j < 8; j++) {
            int cl = wn + j * 8 + (lane & 3) * 2;
            float a0 = satts[cl], a1 = satts[cl + 1];
            float e0 = sattd[cl], e1 = sattd[cl + 1];
            s_a += c[t][j][0] * a0 + c[t][j][1] * a1;
            d_a += c[t][j][0] * e0 + c[t][j][1] * e1;
            s_b += c[t][j][2] * a0 + c[t][j][3] * a1;
            d_b += c[t][j][2] * e0 + c[t][j][3] * e1;
        }
        #pragma unroll
        for (int o = 1; o <= 2; o <<= 1) {
            s_a += __shfl_xor_sync(0xffffffffu, s_a, o);
            d_a += __shfl_xor_sync(0xffffffffu, d_a, o);
            s_b += __shfl_xor_sync(0xffffffffu, s_b, o);
            d_b += __shfl_xor_sync(0xffffffffu, d_b, o);
        }
        if ((lane & 3) == 0) {
            if (r0 < NN) {
                atomicAdd(&asrc_out[r0 * 4 + head], s_a);
                atomicAdd(&adst_out[r0 * 4 + head], d_a);
            }
            if (r0 + 8 < NN) {
                atomicAdd(&asrc_out[(r0 + 8) * 4 + head], s_b);
                atomicAdd(&adst_out[(r0 + 8) * 4 + head], d_b);
            }
        }
    }
}

// ---------------- GEMM1 + scatter merged ------------------------------------
__global__ __launch_bounds__(256) void gemm1_scatter_kernel(
    const float* __restrict__ as1, const float* __restrict__ ad1)
{
    if (blockIdx.x < G1B) {
        extern __shared__ char dsm[];
        gemm_body<1>(blockIdx.x & 3, blockIdx.x >> 2, dsm, as1, ad1);
    } else {
        int e = (blockIdx.x - G1B) * 256 + threadIdx.x;
        if (e < ET) {
            int d = g_dstv[e];
            int pos = atomicAdd(&g_cursor[d], 1);
            g_csrc[pos] = g_src[e];
        }
    }
}

// ---------------- GEMM2 standalone ------------------------------------------
__global__ __launch_bounds__(256) void gemm2_kernel(
    const float* __restrict__ as2, const float* __restrict__ ad2)
{
    extern __shared__ char dsm[];
    gemm_body<2>(blockIdx.x & 3, blockIdx.x >> 2, dsm, as2, ad2);
}

// ---------------- warp-per-node softmax + aggregate (fp16 gather) ----------
__device__ __forceinline__ void acc_edge(float4 acc[4], const float* wj,
                                         const uint2* __restrict__ hp) {
    #pragma unroll
    for (int i = 0; i < 4; i++) {
        float wgt = wj[i];
        uint2 u = hp[i * 32];
        float2 v01 = __half22float2(*(__half2*)&u.x);
        float2 v23 = __half22float2(*(__half2*)&u.y);
        acc[i].x = fmaf(wgt, v01.x, acc[i].x);
        acc[i].y = fmaf(wgt, v01.y, acc[i].y);
        acc[i].z = fmaf(wgt, v23.x, acc[i].z);
        acc[i].w = fmaf(wgt, v23.y, acc[i].w);
    }
}

template<int LAYER>
__global__ __launch_bounds__(256) void wagg_kernel(
    const float* __restrict__ bias, const float* __restrict__ W3,
    const float* __restrict__ as3p, const float* __restrict__ ad3p)
{
    __shared__ float lbuf[8][64 * 4];   // per warp: 64 edges x 4 heads
    __shared__ int   sbuf[8][64];       // per warp: src ids

    const float* __restrict__ asrc_in = (LAYER == 1) ? g_asrc : g_asrc2;
    const float* __restrict__ adst_in = (LAYER == 1) ? g_adst : g_adst2;

    int w = threadIdx.x >> 5, lane = threadIdx.x & 31;
    int n = blockIdx.x * 8 + w;
    if (n >= NN) return;
    int start = g_rowoff[n];
    int deg   = g_rowoff[n + 1] - start;
    int head  = lane & 3, eslot = lane >> 2;
    float ad = adst_in[n * 4 + head];

    float ssum;
    float4 acc[4];
    #pragma unroll
    for (int i = 0; i < 4; i++) acc[i] = make_float4(0.f, 0.f, 0.f, 0.f);

    if (deg <= 64) {
        float mx = -1e30f;
        for (int e = eslot; e < deg; e += 8) {
            int s = g_csrc[start + e];
            if (head == 0) sbuf[w][e] = s;
            float lg = leaky(asrc_in[s * 4 + head] + ad);
            lbuf[w][e * 4 + head] = lg;
            mx = fmaxf(mx, lg);
        }
        #pragma unroll
        for (int o = 4; o < 32; o <<= 1)
            mx = fmaxf(mx, __shfl_xor_sync(0xffffffffu, mx, o));
        float ls = 0.f;
        for (int e = eslot; e < deg; e += 8) {
            float wgt = __expf(lbuf[w][e * 4 + head] - mx);
            lbuf[w][e * 4 + head] = wgt;
            ls += wgt;
        }
        #pragma unroll
        for (int o = 4; o < 32; o <<= 1)
            ls += __shfl_xor_sync(0xffffffffu, ls, o);
        ssum = ls;
        __syncwarp();
        #pragma unroll 4
        for (int e2 = 0; e2 < deg; e2++) {
            const uint2* hp = (const uint2*)(g_hA + (size_t)sbuf[w][e2] * 512) + lane;
            acc_edge(acc, &lbuf[w][e2 * 4], hp);
        }
    } else {
        float mx = -1e30f;
        for (int c = 0; c < deg; c += 8) {
            int e = c + eslot;
            if (e < deg) {
                int s = g_csrc[start + e];
                mx = fmaxf(mx, leaky(asrc_in[s * 4 + head] + ad));
            }
        }
        #pragma unroll
        for (int o = 4; o < 32; o <<= 1)
            mx = fmaxf(mx, __shfl_xor_sync(0xffffffffu, mx, o));

        float ls = 0.f;
        for (int c = 0; c < deg; c += 32) {
            #pragma unroll
            for (int sp = 0; sp < 4; sp++) {
                int el = sp * 8 + eslot;
                int e = c + el;
                float wgt = 0.f;
                if (e < deg) {
                    int s = g_csrc[start + e];
                    if (head == 0) sbuf[w][el] = s;
                    wgt = __expf(leaky(asrc_in[s * 4 + head] + ad) - mx);
                }
                lbuf[w][el * 4 + head] = wgt;
                ls += wgt;
            }
            __syncwarp();
            int cend = min(32, deg - c);
            #pragma unroll 4
            for (int e2 = 0; e2 < cend; e2++) {
                const uint2* hp = (const uint2*)(g_hA + (size_t)sbuf[w][e2] * 512) + lane;
                acc_edge(acc, &lbuf[w][e2 * 4], hp);
            }
            __syncwarp();
        }
        #pragma unroll
        for (int o = 4; o < 32; o <<= 1)
            ls += __shfl_xor_sync(0xffffffffu, ls, o);
        ssum = ls;
    }

    float inv[4];
    #pragma unroll
    for (int i = 0; i < 4; i++)
        inv[i] = 1.f / (__shfl_sync(0xffffffffu, ssum, i) + 1e-16f);

    float p = 0.f;
    #pragma unroll
    for (int i = 0; i < 4; i++) {
        float4 b4 = ((const float4*)bias)[i * 32 + lane];
        float4 o;
        o.x = acc[i].x * inv[i] + b4.x;
        o.y = acc[i].y * inv[i] + b4.y;
        o.z = acc[i].z * inv[i] + b4.z;
        o.w = acc[i].w * inv[i] + b4.w;
        o.x = o.x > 0.f ? o.x : (__expf(o.x) - 1.f);
        o.y = o.y > 0.f ? o.y : (__expf(o.y) - 1.f);
        o.z = o.z > 0.f ? o.z : (__expf(o.z) - 1.f);
        o.w = o.w > 0.f ? o.w : (__expf(o.w) - 1.f);
        if (LAYER == 1) {
            float rx, ry, rz, rw;
            unsigned h0 = pkh_hi(o.x, o.y, rx, ry);
            unsigned h1 = pkh_hi(o.z, o.w, rz, rw);
            size_t go = (size_t)n * 512 + i * 128 + lane * 4;
            *(uint2*)&g_hBh[go] = make_uint2(h0, h1);
            *(uint2*)&g_hBl[go] = make_uint2(pkh(rx, ry), pkh(rz, rw));
        } else {
            float4 w4 = ((const float4*)W3)[i * 32 + lane];
            p += o.x * w4.x + o.y * w4.y + o.z * w4.z + o.w * w4.w;
        }
    }
    if (LAYER == 2) {
        p = warp_red_sum(p);
        if (lane == 0) {
            g_h3[n] = p;
            g_as3[n] = p * as3p[0];
            g_ad3[n] = p * ad3p[0];
        }
    }
}

// ---------------- layer-3 aggregation ---------------------------------------
__global__ __launch_bounds__(256) void agg3_kernel(
    const float* __restrict__ b3, float* __restrict__ out)
{
    int n = blockIdx.x * 8 + (threadIdx.x >> 5);
    if (n >= NN) return;
    int lane = threadIdx.x & 31;
    int start = g_rowoff[n], deg = g_rowoff[n + 1] - start;
    float ad = g_ad3[n];
    float m = -1e30f;
    for (int e = lane; e < deg; e += 32) {
        int s = g_csrc[start + e];
        m = fmaxf(m, leaky(g_as3[s] + ad));
    }
    m = warp_red_max(m);
    float sum = 0.f, acc = 0.f;
    for (int e = lane; e < deg; e += 32) {
        int s = g_csrc[start + e];
        float w = __expf(leaky(g_as3[s] + ad) - m);
        sum += w;
        acc = fmaf(w, g_h3[s], acc);
    }
    sum = warp_red_sum(sum);
    acc = warp_red_sum(acc);
    if (!lane) out[n] = acc / (sum + 1e-16f) + b3[0];
}

// ---------------- launch ----------------------------------------------------
extern "C" void kernel_launch(void* const* d_in, const int* in_sizes, int n_in,
                              void* d_out, int out_size)
{
    const float* x   = (const float*)d_in[0];
    const void*  ei  = d_in[1];
    const float* W1  = (const float*)d_in[2];
    const float* as1 = (const float*)d_in[3];
    const float* ad1 = (const float*)d_in[4];
    const float* b1  = (const float*)d_in[5];
    const float* W2  = (const float*)d_in[6];
    const float* as2 = (const float*)d_in[7];
    const float* ad2 = (const float*)d_in[8];
    const float* b2  = (const float*)d_in[9];
    const float* W3  = (const float*)d_in[10];
    const float* as3 = (const float*)d_in[11];
    const float* ad3 = (const float*)d_in[12];
    const float* b3  = (const float*)d_in[13];
    float* out = (float*)d_out;

    cudaFuncSetAttribute(gemm1_scatter_kernel,
                         cudaFuncAttributeMaxDynamicSharedMemorySize, SM_TOTAL);
    cudaFuncSetAttribute(gemm2_kernel,
                         cudaFuncAttributeMaxDynamicSharedMemorySize, SM_TOTAL);

    int prep_blocks = DB + 256 + (NN * K1) / 256 + (FOUT * K1 + 255) / 256;

    // 0: init (dtype detect + zero + sync state)
    init_kernel<<<(NN * HEADS + 255) / 256, 256>>>((const unsigned*)ei);
    // 1: decode+count | weight/x prep
    decode_prep_kernel<<<prep_blocks, 256>>>(ei, W1, W2, x);
    // 2: fused degree scan
    scan_kernel<<<NB, 1024>>>();
    // 3: GEMM1 (+dots) overlapped with CSR scatter
    gemm1_scatter_kernel<<<G1B + DB, 256, SM_TOTAL>>>(as1, ad1);
    // 4: layer-1 softmax-aggregate
    wagg_kernel<1><<<(NN + 7) / 8, 256>>>(b1, W3, as3, ad3);
    // 5: GEMM2 (+dots)
    gemm2_kernel<<<G1B, 256, SM_TOTAL>>>(as2, ad2);
    // 6: layer-2 softmax-aggregate + fused W3 GEMV
    wagg_kernel<2><<<(NN + 7) / 8, 256>>>(b2, W3, as3, ad3);
    // 7: layer-3 scalar attention
    agg3_kernel<<<(NN + 7) / 8, 256>>>(b3, out);
}

// round 11
// speedup vs baseline: 4.7321x; 1.1856x over previous
#include <cuda_runtime.h>
#include <cuda_fp16.h>
#include <cstdint>

#define NN     20000
#define FIN    50
#define HID    128
#define HEADS  4
#define FOUT   512            // HEADS*HID
#define E0     320000
#define ET     (E0 + NN)      // edges incl. self-loops = 340000
#define K1     64             // layer-1 K padded 50 -> 64
#define NB     20             // scan blocks (ceil(NN/1024))
#define RB     ((NN + 127) / 128)       // 157 row blocks
#define G1B    (4 * RB)                 // 628 GEMM blocks
#define DB     ((ET + 255) / 256)       // 1329 decode/scatter blocks

// ---------------- scratch (device globals; no allocation allowed) ----------
__device__ __half g_hA[(size_t)NN * FOUT];      // GEMM output (fp16 messages)
__device__ __half g_hB[(size_t)NN * FOUT];      // agg1 output (fp16)
__device__ __half g_x[(size_t)NN * K1];         // x fp16 (padded)
__device__ __half g_W1T[(size_t)FOUT * K1];     // W1^T fp16 [n][k]
__device__ __half g_W2T[(size_t)FOUT * FOUT];   // W2^T fp16 [n][k]
__device__ float g_asrc[NN * HEADS],  g_adst[NN * HEADS];    // layer-1 dots
__device__ float g_asrc2[NN * HEADS], g_adst2[NN * HEADS];   // layer-2 dots
__device__ float g_h3[NN], g_as3[NN], g_ad3[NN];
__device__ int   g_src[ET], g_dstv[ET], g_csrc[ET];
__device__ int   g_deg[NN], g_cursor[NN], g_rowoff[NN + 1];
__device__ int   g_bsum[32], g_boff[32];
__device__ int   g_ctr, g_flag;
__device__ int   g_is64;

// ---------------- helpers --------------------------------------------------
__device__ __forceinline__ float warp_red_sum(float v) {
    #pragma unroll
    for (int o = 16; o; o >>= 1) v += __shfl_xor_sync(0xffffffffu, v, o);
    return v;
}
__device__ __forceinline__ float warp_red_max(float v) {
    #pragma unroll
    for (int o = 16; o; o >>= 1) v = fmaxf(v, __shfl_xor_sync(0xffffffffu, v, o));
    return v;
}
__device__ __forceinline__ float leaky(float x) { return x > 0.f ? x : 0.2f * x; }

__device__ __forceinline__ uint32_t smem_u32(const void* p) {
    uint32_t a;
    asm("{ .reg .u64 t; cvta.to.shared.u64 t, %1; cvt.u32.u64 %0, t; }" : "=r"(a) : "l"(p));
    return a;
}

__device__ __forceinline__ void ldm_x4(unsigned r[4], uint32_t addr) {
    asm volatile("ldmatrix.sync.aligned.m8n8.x4.shared.b16 {%0,%1,%2,%3}, [%4];"
                 : "=r"(r[0]), "=r"(r[1]), "=r"(r[2]), "=r"(r[3]) : "r"(addr));
}
__device__ __forceinline__ void mma_f16(float c[4], const unsigned a[4],
                                        unsigned b0, unsigned b1) {
    asm volatile(
        "mma.sync.aligned.m16n8k16.row.col.f32.f16.f16.f32 "
        "{%0,%1,%2,%3}, {%4,%5,%6,%7}, {%8,%9}, {%0,%1,%2,%3};"
        : "+f"(c[0]), "+f"(c[1]), "+f"(c[2]), "+f"(c[3])
        : "r"(a[0]), "r"(a[1]), "r"(a[2]), "r"(a[3]), "r"(b0), "r"(b1));
}
__device__ __forceinline__ void cpa16(uint32_t dst, const void* src, bool p) {
    int sz = p ? 16 : 0;
    asm volatile("cp.async.cg.shared.global [%0], [%1], 16, %2;"
                 :: "r"(dst), "l"(src), "r"(sz));
}
__device__ __forceinline__ void cpa_commit() {
    asm volatile("cp.async.commit_group;");
}
template<int N> __device__ __forceinline__ void cpa_wait() {
    asm volatile("cp.async.wait_group %0;" :: "n"(N));
}

// ---------------- init: detect dtype + zero accumulators --------------------
__global__ void init_kernel(const unsigned* __restrict__ w) {
    int i = blockIdx.x * blockDim.x + threadIdx.x;
    if (i == 0) {
        int is64 = 1;
        for (int q = 1; q < 64; q += 2)
            if (w[q] != 0u) { is64 = 0; break; }
        g_is64 = is64;
        g_ctr = 0;
        g_flag = 0;
    }
    if (i < NN) g_deg[i] = 0;
    if (i < NN * HEADS) {
        g_asrc[i] = 0.f;  g_adst[i] = 0.f;
        g_asrc2[i] = 0.f; g_adst2[i] = 0.f;
    }
}

// ---------------- merged decode+count | W2 transpose | x fp16 | W1 ----------
__global__ __launch_bounds__(256) void decode_prep_kernel(
    const void* __restrict__ ei, const float* __restrict__ W1,
    const float* __restrict__ W2, const float* __restrict__ x)
{
    int b = blockIdx.x, t = threadIdx.x;
    if (b < DB) {
        int e = b * 256 + t;
        if (e >= ET) return;
        int s, d;
        if (e < E0) {
            if (g_is64) {
                const long long* p = (const long long*)ei;
                s = (int)p[e]; d = (int)p[E0 + e];
            } else {
                const int* p = (const int*)ei;
                s = p[e]; d = p[E0 + e];
            }
        } else {
            s = d = e - E0;
        }
        g_src[e] = s; g_dstv[e] = d;
        atomicAdd(&g_deg[d], 1);
    } else if (b < DB + 256) {
        __shared__ float tile[32][33];
        int bb = b - DB;
        int bx = (bb & 15) * 32, by = (bb >> 4) * 32;
        int tx = t & 31, ty = t >> 5;
        #pragma unroll
        for (int i = 0; i < 32; i += 8)
            tile[ty + i][tx] = W2[(size_t)(bx + ty + i) * 512 + by + tx];
        __syncthreads();
        #pragma unroll
        for (int i = 0; i < 32; i += 8) {
            float v = tile[tx][ty + i];
            g_W2T[(size_t)(by + ty + i) * 512 + bx + tx] = __float2half_rn(v);
        }
    } else if (b < DB + 256 + (NN * K1) / 256) {
        int idx = (b - DB - 256) * 256 + t;
        int n = idx >> 6, k = idx & 63;
        float v = (k < FIN) ? x[n * FIN + k] : 0.f;
        g_x[idx] = __float2half_rn(v);
    } else {
        int idx = (b - DB - 256 - (NN * K1) / 256) * 256 + t;
        if (idx < FOUT * K1) {
            int n = idx >> 6, k = idx & 63;
            float v = (k < FIN) ? W1[(size_t)k * 512 + n] : 0.f;
            g_W1T[idx] = __float2half_rn(v);
        }
    }
}

// ---------------- fused multi-block scan (one kernel, device flag sync) -----
__global__ __launch_bounds__(1024) void scan_kernel() {
    __shared__ int wsum[32];
    int b = blockIdx.x, t = threadIdx.x, lane = t & 31, w = t >> 5;
    int i = b * 1024 + t;
    int v = (i < NN) ? g_deg[i] : 0;
    int x = v;
    #pragma unroll
    for (int o = 1; o < 32; o <<= 1) {
        int y = __shfl_up_sync(0xffffffffu, x, o);
        if (lane >= o) x += y;
    }
    if (lane == 31) wsum[w] = x;
    __syncthreads();
    if (w == 0) {
        int y = wsum[lane];
        #pragma unroll
        for (int o = 1; o < 32; o <<= 1) {
            int z = __shfl_up_sync(0xffffffffu, y, o);
            if (lane >= o) y += z;
        }
        wsum[lane] = y;
    }
    __syncthreads();
    int incl = x + (w ? wsum[w - 1] : 0);
    int excl_local = incl - v;
    if (t == 1023) g_bsum[b] = incl;
    __threadfence();
    __syncthreads();

    if (t == 0) {
        int arrived = atomicAdd(&g_ctr, 1);
        if (arrived == NB - 1) {
            int acc = 0;
            #pragma unroll
            for (int q = 0; q < NB; q++) { g_boff[q] = acc; acc += g_bsum[q]; }
            __threadfence();
            atomicExch(&g_flag, 1);
        }
        while (atomicAdd(&g_flag, 0) == 0) {}
    }
    __syncthreads();

    int off = g_boff[b];
    if (i < NN) {
        g_rowoff[i + 1] = off + incl;
        g_cursor[i]     = off + excl_local;
    }
    if (b == 0 && t == 0) g_rowoff[0] = 0;
}

// ---------------- GEMM body: pure fp16 single-pass --------------------------
#define TB   10240                 // one tile array (128 rows x 80 B)
#define BUF  (2 * TB)              // one buffer = {A, B} = 20480
#define SM_ATT (2 * BUF)           // 40960
#define SM_TOTAL (SM_ATT + 1024)

template<int LAYER>
__device__ __forceinline__ void gemm_body(
    int head, int rowb, char* dsm,
    const float* __restrict__ atts, const float* __restrict__ attd)
{
    constexpr int K = (LAYER == 1) ? K1 : FOUT;
    constexpr int KITER = K / 32;

    float* satts = (float*)(dsm + SM_ATT);
    float* sattd = satts + 128;

    const __half* __restrict__ A = (LAYER == 1) ? g_x : g_hB;
    const __half* __restrict__ B = (LAYER == 1) ? g_W1T : g_W2T;

    int tid = threadIdx.x;
    int wid = tid >> 5, lane = tid & 31;
    int wm = (wid & 3) * 32;
    int wn = (wid >> 2) * 64;
    int rowBase = rowb * 128;
    int colBase = head * 128;
    uint32_t smb = smem_u32(dsm);

    if (tid < 128) {
        satts[tid] = atts[head * 128 + tid];
        sattd[tid] = attd[head * 128 + tid];
    }

    float c[2][8][4];
    #pragma unroll
    for (int t = 0; t < 2; t++)
        #pragma unroll
        for (int j = 0; j < 8; j++)
            #pragma unroll
            for (int q = 0; q < 4; q++) c[t][j][q] = 0.f;

    int r0l = tid >> 2, c8 = tid & 3;

    auto load_tile = [&](int it, int buf) {
        uint32_t bb = smb + buf * BUF;
        #pragma unroll
        for (int i = 0; i < 2; i++) {
            int r = r0l + i * 64;
            int sw = c8 ^ (r & 3);
            uint32_t ro = (uint32_t)r * 80u + (uint32_t)sw * 16u;
            int grow = rowBase + r;
            bool p = grow < NN;
            int gcl = p ? grow : (NN - 1);
            size_t goA = (size_t)gcl * K + it * 32 + c8 * 8;
            cpa16(bb + ro, A + goA, p);
            size_t goB = (size_t)(colBase + r) * K + it * 32 + c8 * 8;
            cpa16(bb + TB + ro, B + goB, true);
        }
    };

    load_tile(0, 0);
    cpa_commit();

    int lr = lane & 15, lhalf = lane >> 4;

    for (int it = 0; it < KITER; it++) {
        if (it + 1 < KITER) {
            load_tile(it + 1, (it + 1) & 1);
            cpa_commit();
            cpa_wait<1>();
        } else {
            cpa_wait<0>();
        }
        __syncthreads();

        uint32_t bb = smb + (it & 1) * BUF;
        uint32_t aBase = bb, bBase = bb + TB;

        #pragma unroll
        for (int s = 0; s < 2; s++) {
            unsigned af[2][4], bf[4][4];
            #pragma unroll
            for (int t = 0; t < 2; t++) {
                int row = wm + t * 16 + lr;
                uint32_t unit = (uint32_t)((s * 2 + lhalf) ^ (row & 3));
                uint32_t off = (uint32_t)row * 80u + unit * 16u;
                ldm_x4(af[t], aBase + off);
            }
            #pragma unroll
            for (int p = 0; p < 4; p++) {
                int row = wn + p * 16 + lr;
                uint32_t unit = (uint32_t)((s * 2 + lhalf) ^ (row & 3));
                uint32_t off = (uint32_t)row * 80u + unit * 16u;
                ldm_x4(bf[p], bBase + off);
            }
            #pragma unroll
            for (int t = 0; t < 2; t++) {
                #pragma unroll
                for (int j = 0; j < 8; j++) {
                    int p = j >> 1;
                    unsigned b0 = (j & 1) ? bf[p][1] : bf[p][0];
                    unsigned b1 = (j & 1) ? bf[p][3] : bf[p][2];
                    mma_f16(c[t][j], af[t], b0, b1);
                }
            }
        }
        __syncthreads();
    }

    float* asrc_out = (LAYER == 1) ? g_asrc : g_asrc2;
    float* adst_out = (LAYER == 1) ? g_adst : g_adst2;

    #pragma unroll
    for (int t = 0; t < 2; t++) {
        int r0 = rowBase + wm + t * 16 + (lane >> 2);
        #pragma unroll
        for (int j = 0; j < 8; j++) {
            int col = colBase + wn + j * 8 + (lane & 3) * 2;
            if (r0 < NN) {
                __half2 hv = __floats2half2_rn(c[t][j][0], c[t][j][1]);
                *(__half2*)&g_hA[(size_t)r0 * 512 + col] = hv;
            }
            if (r0 + 8 < NN) {
                __half2 hv = __floats2half2_rn(c[t][j][2], c[t][j][3]);
                *(__half2*)&g_hA[(size_t)(r0 + 8) * 512 + col] = hv;
            }
        }
        float s_a = 0.f, d_a = 0.f, s_b = 0.f, d_b = 0.f;
        #pragma unroll
        for (int j = 0; j < 8; j++) {
            int cl = wn + j * 8 + (lane & 3) * 2;
            float a0 = satts[cl], a1 = satts[cl + 1];
            float e0 = sattd[cl], e1 = sattd[cl + 1];
            s_a += c[t][j][0] * a0 + c[t][j][1] * a1;
            d_a += c[t][j][0] * e0 + c[t][j][1] * e1;
            s_b += c[t][j][2] * a0 + c[t][j][3] * a1;
            d_b += c[t][j][2] * e0 + c[t][j][3] * e1;
        }
        #pragma unroll
        for (int o = 1; o <= 2; o <<= 1) {
            s_a += __shfl_xor_sync(0xffffffffu, s_a, o);
            d_a += __shfl_xor_sync(0xffffffffu, d_a, o);
            s_b += __shfl_xor_sync(0xffffffffu, s_b, o);
            d_b += __shfl_xor_sync(0xffffffffu, d_b, o);
        }
        if ((lane & 3) == 0) {
            if (r0 < NN) {
                atomicAdd(&asrc_out[r0 * 4 + head], s_a);
                atomicAdd(&adst_out[r0 * 4 + head], d_a);
            }
            if (r0 + 8 < NN) {
                atomicAdd(&asrc_out[(r0 + 8) * 4 + head], s_b);
                atomicAdd(&adst_out[(r0 + 8) * 4 + head], d_b);
            }
        }
    }
}

// ---------------- GEMM1 + scatter merged ------------------------------------
__global__ __launch_bounds__(256) void gemm1_scatter_kernel(
    const float* __restrict__ as1, const float* __restrict__ ad1)
{
    if (blockIdx.x < G1B) {
        extern __shared__ char dsm[];
        gemm_body<1>(blockIdx.x & 3, blockIdx.x >> 2, dsm, as1, ad1);
    } else {
        int e = (blockIdx.x - G1B) * 256 + threadIdx.x;
        if (e < ET) {
            int d = g_dstv[e];
            int pos = atomicAdd(&g_cursor[d], 1);
            g_csrc[pos] = g_src[e];
        }
    }
}

// ---------------- GEMM2 standalone ------------------------------------------
__global__ __launch_bounds__(256) void gemm2_kernel(
    const float* __restrict__ as2, const float* __restrict__ ad2)
{
    extern __shared__ char dsm[];
    gemm_body<2>(blockIdx.x & 3, blockIdx.x >> 2, dsm, as2, ad2);
}

// ---------------- warp-per-node softmax + aggregate (fp16 gather) ----------
__device__ __forceinline__ void acc_edge(float4 acc[4], const float* wj,
                                         const uint2* __restrict__ hp) {
    #pragma unroll
    for (int i = 0; i < 4; i++) {
        float wgt = wj[i];
        uint2 u = hp[i * 32];
        float2 v01 = __half22float2(*(__half2*)&u.x);
        float2 v23 = __half22float2(*(__half2*)&u.y);
        acc[i].x = fmaf(wgt, v01.x, acc[i].x);
        acc[i].y = fmaf(wgt, v01.y, acc[i].y);
        acc[i].z = fmaf(wgt, v23.x, acc[i].z);
        acc[i].w = fmaf(wgt, v23.y, acc[i].w);
    }
}

template<int LAYER>
__global__ __launch_bounds__(256) void wagg_kernel(
    const float* __restrict__ bias, const float* __restrict__ W3,
    const float* __restrict__ as3p, const float* __restrict__ ad3p)
{
    __shared__ float lbuf[8][64 * 4];   // per warp: 64 edges x 4 heads
    __shared__ int   sbuf[8][64];       // per warp: src ids

    const float* __restrict__ asrc_in = (LAYER == 1) ? g_asrc : g_asrc2;
    const float* __restrict__ adst_in = (LAYER == 1) ? g_adst : g_adst2;

    int w = threadIdx.x >> 5, lane = threadIdx.x & 31;
    int n = blockIdx.x * 8 + w;
    if (n >= NN) return;
    int start = g_rowoff[n];
    int deg   = g_rowoff[n + 1] - start;
    int head  = lane & 3, eslot = lane >> 2;
    float ad = adst_in[n * 4 + head];

    float ssum;
    float4 acc[4];
    #pragma unroll
    for (int i = 0; i < 4; i++) acc[i] = make_float4(0.f, 0.f, 0.f, 0.f);

    if (deg <= 64) {
        float mx = -1e30f;
        for (int e = eslot; e < deg; e += 8) {
            int s = g_csrc[start + e];
            if (head == 0) sbuf[w][e] = s;
            float lg = leaky(asrc_in[s * 4 + head] + ad);
            lbuf[w][e * 4 + head] = lg;
            mx = fmaxf(mx, lg);
        }
        #pragma unroll
        for (int o = 4; o < 32; o <<= 1)
            mx = fmaxf(mx, __shfl_xor_sync(0xffffffffu, mx, o));
        float ls = 0.f;
        for (int e = eslot; e < deg; e += 8) {
            float wgt = __expf(lbuf[w][e * 4 + head] - mx);
            lbuf[w][e * 4 + head] = wgt;
            ls += wgt;
        }
        #pragma unroll
        for (int o = 4; o < 32; o <<= 1)
            ls += __shfl_xor_sync(0xffffffffu, ls, o);
        ssum = ls;
        __syncwarp();
        #pragma unroll 4
        for (int e2 = 0; e2 < deg; e2++) {
            const uint2* hp = (const uint2*)(g_hA + (size_t)sbuf[w][e2] * 512) + lane;
            acc_edge(acc, &lbuf[w][e2 * 4], hp);
        }
    } else {
        float mx = -1e30f;
        for (int c = 0; c < deg; c += 8) {
            int e = c + eslot;
            if (e < deg) {
                int s = g_csrc[start + e];
                mx = fmaxf(mx, leaky(asrc_in[s * 4 + head] + ad));
            }
        }
        #pragma unroll
        for (int o = 4; o < 32; o <<= 1)
            mx = fmaxf(mx, __shfl_xor_sync(0xffffffffu, mx, o));

        float ls = 0.f;
        for (int c = 0; c < deg; c += 32) {
            #pragma unroll
            for (int sp = 0; sp < 4; sp++) {
                int el = sp * 8 + eslot;
                int e = c + el;
                float wgt = 0.f;
                if (e < deg) {
                    int s = g_csrc[start + e];
                    if (head == 0) sbuf[w][el] = s;
                    wgt = __expf(leaky(asrc_in[s * 4 + head] + ad) - mx);
                }
                lbuf[w][el * 4 + head] = wgt;
                ls += wgt;
            }
            __syncwarp();
            int cend = min(32, deg - c);
            #pragma unroll 4
            for (int e2 = 0; e2 < cend; e2++) {
                const uint2* hp = (const uint2*)(g_hA + (size_t)sbuf[w][e2] * 512) + lane;
                acc_edge(acc, &lbuf[w][e2 * 4], hp);
            }
            __syncwarp();
        }
        #pragma unroll
        for (int o = 4; o < 32; o <<= 1)
            ls += __shfl_xor_sync(0xffffffffu, ls, o);
        ssum = ls;
    }

    float inv[4];
    #pragma unroll
    for (int i = 0; i < 4; i++)
        inv[i] = 1.f / (__shfl_sync(0xffffffffu, ssum, i) + 1e-16f);

    float p = 0.f;
    #pragma unroll
    for (int i = 0; i < 4; i++) {
        float4 b4 = ((const float4*)bias)[i * 32 + lane];
        float4 o;
        o.x = acc[i].x * inv[i] + b4.x;
        o.y = acc[i].y * inv[i] + b4.y;
        o.z = acc[i].z * inv[i] + b4.z;
        o.w = acc[i].w * inv[i] + b4.w;
        o.x = o.x > 0.f ? o.x : (__expf(o.x) - 1.f);
        o.y = o.y > 0.f ? o.y : (__expf(o.y) - 1.f);
        o.z = o.z > 0.f ? o.z : (__expf(o.z) - 1.f);
        o.w = o.w > 0.f ? o.w : (__expf(o.w) - 1.f);
        if (LAYER == 1) {
            __half2 h0 = __floats2half2_rn(o.x, o.y);
            __half2 h1 = __floats2half2_rn(o.z, o.w);
            size_t go = (size_t)n * 512 + i * 128 + lane * 4;
            *(uint2*)&g_hB[go] = make_uint2(*(unsigned*)&h0, *(unsigned*)&h1);
        } else {
            float4 w4 = ((const float4*)W3)[i * 32 + lane];
            p += o.x * w4.x + o.y * w4.y + o.z * w4.z + o.w * w4.w;
        }
    }
    if (LAYER == 2) {
        p = warp_red_sum(p);
        if (lane == 0) {
            g_h3[n] = p;
            g_as3[n] = p * as3p[0];
            g_ad3[n] = p * ad3p[0];
        }
    }
}

// ---------------- layer-3 aggregation ---------------------------------------
__global__ __launch_bounds__(256) void agg3_kernel(
    const float* __restrict__ b3, float* __restrict__ out)
{
    int n = blockIdx.x * 8 + (threadIdx.x >> 5);
    if (n >= NN) return;
    int lane = threadIdx.x & 31;
    int start = g_rowoff[n], deg = g_rowoff[n + 1] - start;
    float ad = g_ad3[n];
    float m = -1e30f;
    for (int e = lane; e < deg; e += 32) {
        int s = g_csrc[start + e];
        m = fmaxf(m, leaky(g_as3[s] + ad));
    }
    m = warp_red_max(m);
    float sum = 0.f, acc = 0.f;
    for (int e = lane; e < deg; e += 32) {
        int s = g_csrc[start + e];
        float w = __expf(leaky(g_as3[s] + ad) - m);
        sum += w;
        acc = fmaf(w, g_h3[s], acc);
    }
    sum = warp_red_sum(sum);
    acc = warp_red_sum(acc);
    if (!lane) out[n] = acc / (sum + 1e-16f) + b3[0];
}

// ---------------- launch ----------------------------------------------------
extern "C" void kernel_launch(void* const* d_in, const int* in_sizes, int n_in,
                              void* d_out, int out_size)
{
    const float* x   = (const float*)d_in[0];
    const void*  ei  = d_in[1];
    const float* W1  = (const float*)d_in[2];
    const float* as1 = (const float*)d_in[3];
    const float* ad1 = (const float*)d_in[4];
    const float* b1  = (const float*)d_in[5];
    const float* W2  = (const float*)d_in[6];
    const float* as2 = (const float*)d_in[7];
    const float* ad2 = (const float*)d_in[8];
    const float* b2  = (const float*)d_in[9];
    const float* W3  = (const float*)d_in[10];
    const float* as3 = (const float*)d_in[11];
    const float* ad3 = (const float*)d_in[12];
    const float* b3  = (const float*)d_in[13];
    float* out = (float*)d_out;

    cudaFuncSetAttribute(gemm1_scatter_kernel,
                         cudaFuncAttributeMaxDynamicSharedMemorySize, SM_TOTAL);
    cudaFuncSetAttribute(gemm2_kernel,
                         cudaFuncAttributeMaxDynamicSharedMemorySize, SM_TOTAL);

    int prep_blocks = DB + 256 + (NN * K1) / 256 + (FOUT * K1 + 255) / 256;

    // 0: init (dtype detect + zero + sync state)
    init_kernel<<<(NN * HEADS + 255) / 256, 256>>>((const unsigned*)ei);
    // 1: decode+count | weight/x prep
    decode_prep_kernel<<<prep_blocks, 256>>>(ei, W1, W2, x);
    // 2: fused degree scan
    scan_kernel<<<NB, 1024>>>();
    // 3: GEMM1 (+dots) overlapped with CSR scatter
    gemm1_scatter_kernel<<<G1B + DB, 256, SM_TOTAL>>>(as1, ad1);
    // 4: layer-1 softmax-aggregate
    wagg_kernel<1><<<(NN + 7) / 8, 256>>>(b1, W3, as3, ad3);
    // 5: GEMM2 (+dots)
    gemm2_kernel<<<G1B, 256, SM_TOTAL>>>(as2, ad2);
    // 6: layer-2 softmax-aggregate + fused W3 GEMV
    wagg_kernel<2><<<(NN + 7) / 8, 256>>>(b2, W3, as3, ad3);
    // 7: layer-3 scalar attention
    agg3_kernel<<<(NN + 7) / 8, 256>>>(b3, out);
}